// round 7
// baseline (speedup 1.0000x reference)
#include <cuda_runtime.h>
#include <cuda_bf16.h>
#include <cstdint>

#define SQ 2048
#define SK 2048
#define NB 8
#define DIM 1024
#define INNER 128
#define NH 4
#define HD 32

// Scratch (allocation-free)
__device__ float g_qkv[3u * NB * INNER * SK];   // [sel][n][e][s]
__device__ float g_x[(size_t)NB * SQ * INNER];  // [n][p][e]

// ============================ warp-MMA helpers =============================
__device__ __forceinline__ uint32_t smem_u32(const void* p) {
    return (uint32_t)__cvta_generic_to_shared(p);
}
__device__ __forceinline__ void ldsm_x4(uint32_t& r0, uint32_t& r1,
                                        uint32_t& r2, uint32_t& r3, uint32_t addr) {
    asm volatile("ldmatrix.sync.aligned.m8n8.x4.shared.b16 {%0,%1,%2,%3}, [%4];"
                 : "=r"(r0), "=r"(r1), "=r"(r2), "=r"(r3) : "r"(addr));
}
__device__ __forceinline__ void mma_bf16(float* d, const uint32_t* a,
                                         uint32_t b0, uint32_t b1) {
    asm volatile(
        "mma.sync.aligned.m16n8k16.row.col.f32.bf16.bf16.f32 "
        "{%0,%1,%2,%3}, {%4,%5,%6,%7}, {%8,%9}, {%0,%1,%2,%3};"
        : "+f"(d[0]), "+f"(d[1]), "+f"(d[2]), "+f"(d[3])
        : "r"(a[0]), "r"(a[1]), "r"(a[2]), "r"(a[3]), "r"(b0), "r"(b1));
}
__device__ __forceinline__ float ex2f(float x) {
    float y;
    asm("ex2.approx.f32 %0, %1;" : "=f"(y) : "f"(x));
    return y;
}

__device__ __forceinline__ void split2(float x, float y, uint32_t& hi, uint32_t& lo) {
    __nv_bfloat16 hx = __float2bfloat16(x);
    __nv_bfloat16 hy = __float2bfloat16(y);
    __nv_bfloat16 lx = __float2bfloat16(x - __bfloat162float(hx));
    __nv_bfloat16 ly = __float2bfloat16(y - __bfloat162float(hy));
    hi = (uint32_t)__bfloat16_as_ushort(hx) | ((uint32_t)__bfloat16_as_ushort(hy) << 16);
    lo = (uint32_t)__bfloat16_as_ushort(lx) | ((uint32_t)__bfloat16_as_ushort(ly) << 16);
}

// ===================== GEMM template (double-buffered) =====================
#define ROWB   80
#define TILE   (128 * ROWB)
#define SM_AH  0
#define SM_AL  TILE
#define SM_BH  (2 * TILE)
#define SM_BL  (3 * TILE)
#define GEMM_BUF (4 * TILE)           // 40960 per buffer
#define GEMM_SMEM (2 * GEMM_BUF)      // 81920

__device__ __forceinline__ void cvt_store(const float4* va, const float4* vb,
                                          char* buf, int rbase, int seg) {
#pragma unroll
    for (int p = 0; p < 4; p++) {
        int off = (rbase + 32 * p) * ROWB + seg * 8;
        uint2 h, l;
        split2(va[p].x, va[p].y, h.x, l.x);
        split2(va[p].z, va[p].w, h.y, l.y);
        *(uint2*)(buf + SM_AH + off) = h;
        *(uint2*)(buf + SM_AL + off) = l;
        split2(vb[p].x, vb[p].y, h.x, l.x);
        split2(vb[p].z, vb[p].w, h.y, l.y);
        *(uint2*)(buf + SM_BH + off) = h;
        *(uint2*)(buf + SM_BL + off) = l;
    }
}

template <int KCHUNKS>
__device__ __forceinline__ void mma_gemm(const float* __restrict__ A, size_t lda,
                                         const float* __restrict__ B, size_t ldb,
                                         float acc[4][4][4], char* sm) {
    const int tid  = threadIdx.x;
    const int lane = tid & 31;
    const int wid  = tid >> 5;
    const int wm   = (wid >> 2) * 64;
    const int wn   = (wid & 3) * 32;
    const int seg  = tid & 7;
    const int rbase = tid >> 3;

    float4 va[4], vb[4];
#pragma unroll
    for (int p = 0; p < 4; p++) {
        va[p] = *(const float4*)(A + (size_t)(rbase + 32 * p) * lda + seg * 4);
        vb[p] = *(const float4*)(B + (size_t)(rbase + 32 * p) * ldb + seg * 4);
    }
    cvt_store(va, vb, sm, rbase, seg);
    __syncthreads();

    for (int c = 0; c < KCHUNKS; c++) {
        char* cur = sm + (c & 1) * GEMM_BUF;
        char* nxt = sm + ((c + 1) & 1) * GEMM_BUF;
        const uint32_t smb = smem_u32(cur);

        if (c + 1 < KCHUNKS) {
            int co = (c + 1) * 32;
#pragma unroll
            for (int p = 0; p < 4; p++) {
                va[p] = *(const float4*)(A + (size_t)(rbase + 32 * p) * lda + co + seg * 4);
                vb[p] = *(const float4*)(B + (size_t)(rbase + 32 * p) * ldb + co + seg * 4);
            }
        }

#pragma unroll
        for (int ks = 0; ks < 2; ks++) {
            const int kb = ks * 32;
            uint32_t ah[4][4], al[4][4];
#pragma unroll
            for (int im = 0; im < 4; im++) {
                uint32_t ra = smb + (wm + im * 16 + (lane & 15)) * ROWB + (lane >> 4) * 16 + kb;
                ldsm_x4(ah[im][0], ah[im][1], ah[im][2], ah[im][3], ra + SM_AH);
                ldsm_x4(al[im][0], al[im][1], al[im][2], al[im][3], ra + SM_AL);
            }
            uint32_t bh[2][4], bl[2][4];
#pragma unroll
            for (int i2 = 0; i2 < 2; i2++) {
                uint32_t rb = smb + (wn + i2 * 16 + (lane & 15)) * ROWB + (lane >> 4) * 16 + kb;
                ldsm_x4(bh[i2][0], bh[i2][1], bh[i2][2], bh[i2][3], rb + SM_BH);
                ldsm_x4(bl[i2][0], bl[i2][1], bl[i2][2], bl[i2][3], rb + SM_BL);
            }
#pragma unroll
            for (int im = 0; im < 4; im++) {
#pragma unroll
                for (int in = 0; in < 4; in++) {
                    int i2 = in >> 1, sub = in & 1;
                    mma_bf16(acc[im][in], ah[im], bh[i2][sub], bh[i2][sub + 2]);
                    mma_bf16(acc[im][in], ah[im], bl[i2][sub], bl[i2][sub + 2]);
                    mma_bf16(acc[im][in], al[im], bh[i2][sub], bh[i2][sub + 2]);
                }
            }
        }

        if (c + 1 < KCHUNKS) cvt_store(va, vb, nxt, rbase, seg);
        __syncthreads();
    }
}

__global__ __launch_bounds__(256, 1)
void proj_mma(const float* __restrict__ query, const float* __restrict__ key_feat,
              const float* __restrict__ Wq, const float* __restrict__ Wk,
              const float* __restrict__ Wv) {
    extern __shared__ __align__(16) char smdyn[];
    const int s0  = blockIdx.x * 128;
    const int n   = blockIdx.y;
    const int sel = blockIdx.z;
    const float* __restrict__ X = (sel == 0) ? query : key_feat;
    const float* __restrict__ W = (sel == 0) ? Wq : (sel == 1 ? Wk : Wv);

    float acc[4][4][4];
#pragma unroll
    for (int i = 0; i < 4; i++)
#pragma unroll
        for (int j = 0; j < 4; j++)
#pragma unroll
            for (int t = 0; t < 4; t++) acc[i][j][t] = 0.f;

    mma_gemm<32>(W, DIM, X + (size_t)s0 * (NB * DIM) + (size_t)n * DIM, (size_t)NB * DIM,
                 acc, smdyn);

    const int lane = threadIdx.x & 31, wid = threadIdx.x >> 5;
    const int wm = (wid >> 2) * 64, wn = (wid & 3) * 32;
    float* __restrict__ outp = g_qkv + ((size_t)sel * NB + n) * ((size_t)INNER * SK);
#pragma unroll
    for (int im = 0; im < 4; im++) {
#pragma unroll
        for (int in = 0; in < 4; in++) {
            int e = wm + im * 16 + (lane >> 2);
            int s = s0 + wn + in * 8 + (lane & 3) * 2;
            *(float2*)&outp[(size_t)e * SK + s]       = make_float2(acc[im][in][0], acc[im][in][1]);
            *(float2*)&outp[(size_t)(e + 8) * SK + s] = make_float2(acc[im][in][2], acc[im][in][3]);
        }
    }
}

__global__ __launch_bounds__(256, 1)
void up_mma(const float* __restrict__ Wup, float* __restrict__ out) {
    extern __shared__ __align__(16) char smdyn[];
    const int d0 = blockIdx.x * 128;
    const int r0 = blockIdx.y * 128;

    float acc[4][4][4];
#pragma unroll
    for (int i = 0; i < 4; i++)
#pragma unroll
        for (int j = 0; j < 4; j++)
#pragma unroll
            for (int t = 0; t < 4; t++) acc[i][j][t] = 0.f;

    mma_gemm<4>(g_x + (size_t)r0 * INNER, INNER, Wup + (size_t)d0 * INNER, INNER, acc, smdyn);

    const int lane = threadIdx.x & 31, wid = threadIdx.x >> 5;
    const int wm = (wid >> 2) * 64, wn = (wid & 3) * 32;
#pragma unroll
    for (int im = 0; im < 4; im++) {
#pragma unroll
        for (int in = 0; in < 4; in++) {
            int d = d0 + wn + in * 8 + (lane & 3) * 2;
#pragma unroll
            for (int half = 0; half < 2; half++) {
                int r = r0 + wm + im * 16 + (lane >> 2) + half * 8;
                int nn = r >> 11, pp = r & 2047;
                *(float2*)&out[((size_t)pp * NB + nn) * DIM + d] =
                    make_float2(acc[im][in][half * 2], acc[im][in][half * 2 + 1]);
            }
        }
    }
}

// ===================== Flash attention on HMMA (double-buffered KV) ========
#define QP 136   // uint32 pitch for Q staging  [16 cpairs][128 queries]
#define KP 72    // uint32 pitch for K staging  [16 cpairs][64 keys]
#define VP 36    // uint32 pitch for V staging  [32 ch][32 keypairs]
#define KV_WORDS (4 * 1152)                    // ksh,ksl,vsh,vsl per buffer
#define ATTN_SMEM ((2 * 16 * QP + 2 * KV_WORDS) * 4)  // 54272 bytes

__global__ __launch_bounds__(128, 2)
void attn_mma() {
    const int p0 = blockIdx.x * 128;
    const int h  = blockIdx.y;
    const int n  = blockIdx.z;

    const float* __restrict__ q = g_qkv + ((size_t)0 * NB + n) * ((size_t)INNER * SK) + (size_t)(h * HD) * SK;
    const float* __restrict__ k = g_qkv + ((size_t)1 * NB + n) * ((size_t)INNER * SK) + (size_t)(h * HD) * SK;
    const float* __restrict__ v = g_qkv + ((size_t)2 * NB + n) * ((size_t)INNER * SK) + (size_t)(h * HD) * SK;

    extern __shared__ __align__(16) uint32_t dsm[];
    uint32_t* qsh   = dsm;
    uint32_t* qsl   = qsh + 16 * QP;
    uint32_t* kvbuf = qsl + 16 * QP;

    const int tid  = threadIdx.x;
    const int lane = tid & 31;
    const int w    = tid >> 5;

    // ---- stage Q (once) ----
#pragma unroll
    for (int t4 = 0; t4 < 4; t4++) {
        int task = tid + t4 * 128;
        int cp = task >> 5, qg = task & 31;
        int qq = qg * 4;
        float4 f0 = *(const float4*)&q[(size_t)(2 * cp) * SK + p0 + qq];
        float4 f1 = *(const float4*)&q[(size_t)(2 * cp + 1) * SK + p0 + qq];
        uint4 hh, ll;
        split2(f0.x, f1.x, hh.x, ll.x);
        split2(f0.y, f1.y, hh.y, ll.y);
        split2(f0.z, f1.z, hh.z, ll.z);
        split2(f0.w, f1.w, hh.w, ll.w);
        *(uint4*)&qsh[cp * QP + qq] = hh;
        *(uint4*)&qsl[cp * QP + qq] = ll;
    }

    // ---- stage KV chunk 0 into buf 0 ----
    {
        uint32_t* b = kvbuf;
#pragma unroll
        for (int t2 = 0; t2 < 2; t2++) {
            int task = tid + t2 * 128;
            int cp = task >> 4, kk = (task & 15) * 4;
            float4 f0 = *(const float4*)&k[(size_t)(2 * cp) * SK + kk];
            float4 f1 = *(const float4*)&k[(size_t)(2 * cp + 1) * SK + kk];
            uint4 hh, ll;
            split2(f0.x, f1.x, hh.x, ll.x);
            split2(f0.y, f1.y, hh.y, ll.y);
            split2(f0.z, f1.z, hh.z, ll.z);
            split2(f0.w, f1.w, hh.w, ll.w);
            *(uint4*)&b[cp * KP + kk] = hh;
            *(uint4*)&b[1152 + cp * KP + kk] = ll;
        }
#pragma unroll
        for (int t4 = 0; t4 < 4; t4++) {
            int task = tid + t4 * 128;
            int c = task >> 4, kk = (task & 15) * 4;
            float4 f = *(const float4*)&v[(size_t)c * SK + kk];
            uint2 hh, ll;
            split2(f.x, f.y, hh.x, ll.x);
            split2(f.z, f.w, hh.y, ll.y);
            *(uint2*)&b[2304 + c * VP + (kk >> 1)] = hh;
            *(uint2*)&b[3456 + c * VP + (kk >> 1)] = ll;
        }
    }
    __syncthreads();

    // ---- Q fragments in registers ----
    uint32_t qfh[2][2][4], qfl[2][2][4];
#pragma unroll
    for (int im = 0; im < 2; im++) {
#pragma unroll
        for (int ks = 0; ks < 2; ks++) {
            int row = w * 32 + im * 16 + (lane >> 2);
            int cp  = (lane & 3) + ks * 8;
            qfh[im][ks][0] = qsh[cp * QP + row];
            qfh[im][ks][1] = qsh[cp * QP + row + 8];
            qfh[im][ks][2] = qsh[(cp + 4) * QP + row];
            qfh[im][ks][3] = qsh[(cp + 4) * QP + row + 8];
            qfl[im][ks][0] = qsl[cp * QP + row];
            qfl[im][ks][1] = qsl[cp * QP + row + 8];
            qfl[im][ks][2] = qsl[(cp + 4) * QP + row];
            qfl[im][ks][3] = qsl[(cp + 4) * QP + row + 8];
        }
    }

    float oacc[2][4][4];
#pragma unroll
    for (int im = 0; im < 2; im++)
#pragma unroll
        for (int nt = 0; nt < 4; nt++)
#pragma unroll
            for (int t = 0; t < 4; t++) oacc[im][nt][t] = 0.f;
    float rowm[2][2] = {{-1e30f, -1e30f}, {-1e30f, -1e30f}};
    float rowl[2][2] = {{0.f, 0.f}, {0.f, 0.f}};

    const float SC2 = 0.17677669529663687f * 1.4426950408889634f;

    const int kcp = (tid + ((tid >= 128) ? 0 : 0)); // (placeholder keeps compiler calm)

    for (int c = 0; c < SK / 64; c++) {
        uint32_t* cur = kvbuf + (c & 1) * KV_WORDS;
        uint32_t* nxt = kvbuf + ((c + 1) & 1) * KV_WORDS;

        // ---- prefetch next chunk to registers ----
        float4 kf0[2], kf1[2], vf[4];
        if (c + 1 < SK / 64) {
            int k0n = (c + 1) * 64;
#pragma unroll
            for (int t2 = 0; t2 < 2; t2++) {
                int task = tid + t2 * 128;
                int cp = task >> 4, kk = (task & 15) * 4;
                kf0[t2] = *(const float4*)&k[(size_t)(2 * cp) * SK + k0n + kk];
                kf1[t2] = *(const float4*)&k[(size_t)(2 * cp + 1) * SK + k0n + kk];
            }
#pragma unroll
            for (int t4 = 0; t4 < 4; t4++) {
                int task = tid + t4 * 128;
                int cc = task >> 4, kk = (task & 15) * 4;
                vf[t4] = *(const float4*)&v[(size_t)cc * SK + k0n + kk];
            }
        }

        uint32_t* ksh_b = cur;
        uint32_t* ksl_b = cur + 1152;
        uint32_t* vsh_b = cur + 2304;
        uint32_t* vsl_b = cur + 3456;

        // ---- S = Q K^T ----
        float sacc[2][8][4];
#pragma unroll
        for (int im = 0; im < 2; im++)
#pragma unroll
            for (int in = 0; in < 8; in++)
#pragma unroll
                for (int t = 0; t < 4; t++) sacc[im][in][t] = 0.f;

#pragma unroll
        for (int ks = 0; ks < 2; ks++) {
            uint32_t bh[8][2], bl[8][2];
#pragma unroll
            for (int in = 0; in < 8; in++) {
                int cp = (lane & 3) + ks * 8;
                int ky = in * 8 + (lane >> 2);
                bh[in][0] = ksh_b[cp * KP + ky];
                bh[in][1] = ksh_b[(cp + 4) * KP + ky];
                bl[in][0] = ksl_b[cp * KP + ky];
                bl[in][1] = ksl_b[(cp + 4) * KP + ky];
            }
#pragma unroll
            for (int im = 0; im < 2; im++)
#pragma unroll
                for (int in = 0; in < 8; in++) {
                    mma_bf16(sacc[im][in], qfh[im][ks], bh[in][0], bh[in][1]);
                    mma_bf16(sacc[im][in], qfh[im][ks], bl[in][0], bl[in][1]);
                    mma_bf16(sacc[im][in], qfl[im][ks], bh[in][0], bh[in][1]);
                }
        }

        // ---- online softmax ----
#pragma unroll
        for (int im = 0; im < 2; im++) {
#pragma unroll
            for (int rs = 0; rs < 2; rs++) {
                float mx = rowm[im][rs];
#pragma unroll
                for (int in = 0; in < 8; in++)
                    mx = fmaxf(mx, fmaxf(sacc[im][in][rs * 2], sacc[im][in][rs * 2 + 1]));
                mx = fmaxf(mx, __shfl_xor_sync(0xffffffffu, mx, 1));
                mx = fmaxf(mx, __shfl_xor_sync(0xffffffffu, mx, 2));
                float corr = ex2f((rowm[im][rs] - mx) * SC2);
                rowm[im][rs] = mx;
                float sum = 0.f;
#pragma unroll
                for (int in = 0; in < 8; in++) {
                    float e0 = ex2f((sacc[im][in][rs * 2] - mx) * SC2);
                    float e1 = ex2f((sacc[im][in][rs * 2 + 1] - mx) * SC2);
                    sacc[im][in][rs * 2] = e0;
                    sacc[im][in][rs * 2 + 1] = e1;
                    sum += e0 + e1;
                }
                rowl[im][rs] = rowl[im][rs] * corr + sum;
#pragma unroll
                for (int nt = 0; nt < 4; nt++) {
                    oacc[im][nt][rs * 2] *= corr;
                    oacc[im][nt][rs * 2 + 1] *= corr;
                }
            }
        }

        // ---- O += P V^T ----
#pragma unroll
        for (int ks4 = 0; ks4 < 4; ks4++) {
            uint32_t pfh[2][4], pfl[2][4];
#pragma unroll
            for (int im = 0; im < 2; im++) {
                const float* t0 = sacc[im][2 * ks4];
                const float* t1 = sacc[im][2 * ks4 + 1];
                split2(t0[0], t0[1], pfh[im][0], pfl[im][0]);
                split2(t0[2], t0[3], pfh[im][1], pfl[im][1]);
                split2(t1[0], t1[1], pfh[im][2], pfl[im][2]);
                split2(t1[2], t1[3], pfh[im][3], pfl[im][3]);
            }
            uint32_t bh[4][2], bl[4][2];
#pragma unroll
            for (int nt = 0; nt < 4; nt++) {
                int cc = nt * 8 + (lane >> 2);
                int kp = (lane & 3) + ks4 * 8;
                bh[nt][0] = vsh_b[cc * VP + kp];
                bh[nt][1] = vsh_b[cc * VP + kp + 4];
                bl[nt][0] = vsl_b[cc * VP + kp];
                bl[nt][1] = vsl_b[cc * VP + kp + 4];
            }
#pragma unroll
            for (int im = 0; im < 2; im++)
#pragma unroll
                for (int nt = 0; nt < 4; nt++) {
                    mma_bf16(oacc[im][nt], pfh[im], bh[nt][0], bh[nt][1]);
                    mma_bf16(oacc[im][nt], pfl[im], bh[nt][0], bh[nt][1]);
                    mma_bf16(oacc[im][nt], pfh[im], bl[nt][0], bl[nt][1]);
                }
        }

        // ---- convert prefetched regs into next buffer ----
        if (c + 1 < SK / 64) {
#pragma unroll
            for (int t2 = 0; t2 < 2; t2++) {
                int task = tid + t2 * 128;
                int cp = task >> 4, kk = (task & 15) * 4;
                uint4 hh, ll;
                split2(kf0[t2].x, kf1[t2].x, hh.x, ll.x);
                split2(kf0[t2].y, kf1[t2].y, hh.y, ll.y);
                split2(kf0[t2].z, kf1[t2].z, hh.z, ll.z);
                split2(kf0[t2].w, kf1[t2].w, hh.w, ll.w);
                *(uint4*)&nxt[cp * KP + kk] = hh;
                *(uint4*)&nxt[1152 + cp * KP + kk] = ll;
            }
#pragma unroll
            for (int t4 = 0; t4 < 4; t4++) {
                int task = tid + t4 * 128;
                int cc = task >> 4, kk = (task & 15) * 4;
                uint2 hh, ll;
                split2(vf[t4].x, vf[t4].y, hh.x, ll.x);
                split2(vf[t4].z, vf[t4].w, hh.y, ll.y);
                *(uint2*)&nxt[2304 + cc * VP + (kk >> 1)] = hh;
                *(uint2*)&nxt[3456 + cc * VP + (kk >> 1)] = ll;
            }
        }
        __syncthreads();
    }

    // ---- finalize ----
#pragma unroll
    for (int im = 0; im < 2; im++) {
#pragma unroll
        for (int rs = 0; rs < 2; rs++) {
            float l = rowl[im][rs];
            l += __shfl_xor_sync(0xffffffffu, l, 1);
            l += __shfl_xor_sync(0xffffffffu, l, 2);
            float inv = 1.f / l;
#pragma unroll
            for (int nt = 0; nt < 4; nt++) {
                oacc[im][nt][rs * 2] *= inv;
                oacc[im][nt][rs * 2 + 1] *= inv;
            }
        }
    }
    float* __restrict__ xout = g_x + (size_t)n * SQ * INNER + h * HD;
#pragma unroll
    for (int im = 0; im < 2; im++) {
#pragma unroll
        for (int nt = 0; nt < 4; nt++) {
            int row = p0 + w * 32 + im * 16 + (lane >> 2);
            int col = nt * 8 + (lane & 3) * 2;
            *(float2*)&xout[(size_t)row * INNER + col] =
                make_float2(oacc[im][nt][0], oacc[im][nt][1]);
            *(float2*)&xout[(size_t)(row + 8) * INNER + col] =
                make_float2(oacc[im][nt][2], oacc[im][nt][3]);
        }
    }
}

// ---------------------------------------------------------------------------
extern "C" void kernel_launch(void* const* d_in, const int* in_sizes, int n_in,
                              void* d_out, int out_size) {
    const float* query    = (const float*)d_in[0];
    const float* key_feat = (const float*)d_in[1];
    const float* Wq       = (const float*)d_in[2];
    const float* Wk       = (const float*)d_in[3];
    const float* Wv       = (const float*)d_in[4];
    const float* Wup      = (const float*)d_in[5];
    float* out            = (float*)d_out;

    static bool attr_done = false;
    if (!attr_done) {
        cudaFuncSetAttribute(proj_mma, cudaFuncAttributeMaxDynamicSharedMemorySize, GEMM_SMEM);
        cudaFuncSetAttribute(up_mma,   cudaFuncAttributeMaxDynamicSharedMemorySize, GEMM_SMEM);
        cudaFuncSetAttribute(attn_mma, cudaFuncAttributeMaxDynamicSharedMemorySize, ATTN_SMEM);
        attr_done = true;
    }

    dim3 g1(SK / 128, NB, 3);
    proj_mma<<<g1, 256, GEMM_SMEM>>>(query, key_feat, Wq, Wk, Wv);

    dim3 g2(SQ / 128, NH, NB);
    attn_mma<<<g2, 128, ATTN_SMEM>>>();

    dim3 g3(DIM / 128, (NB * SQ) / 128);
    up_mma<<<g3, 256, GEMM_SMEM>>>(Wup, out);
}

// round 8
// speedup vs baseline: 1.0601x; 1.0601x over previous
#include <cuda_runtime.h>
#include <cuda_bf16.h>
#include <cstdint>

#define SQ 2048
#define SK 2048
#define NB 8
#define DIM 1024
#define INNER 128
#define NH 4
#define HD 32

// Scratch (allocation-free)
__device__ float g_qkv[3u * NB * INNER * SK];   // [sel][n][e][s]
__device__ float g_x[(size_t)NB * SQ * INNER];  // [n][p][e]

// ============================ warp-MMA helpers =============================
__device__ __forceinline__ uint32_t smem_u32(const void* p) {
    return (uint32_t)__cvta_generic_to_shared(p);
}
__device__ __forceinline__ void ldsm_x4(uint32_t& r0, uint32_t& r1,
                                        uint32_t& r2, uint32_t& r3, uint32_t addr) {
    asm volatile("ldmatrix.sync.aligned.m8n8.x4.shared.b16 {%0,%1,%2,%3}, [%4];"
                 : "=r"(r0), "=r"(r1), "=r"(r2), "=r"(r3) : "r"(addr));
}
__device__ __forceinline__ void mma_bf16(float* d, const uint32_t* a,
                                         uint32_t b0, uint32_t b1) {
    asm volatile(
        "mma.sync.aligned.m16n8k16.row.col.f32.bf16.bf16.f32 "
        "{%0,%1,%2,%3}, {%4,%5,%6,%7}, {%8,%9}, {%0,%1,%2,%3};"
        : "+f"(d[0]), "+f"(d[1]), "+f"(d[2]), "+f"(d[3])
        : "r"(a[0]), "r"(a[1]), "r"(a[2]), "r"(a[3]), "r"(b0), "r"(b1));
}
__device__ __forceinline__ float ex2f(float x) {
    float y;
    asm("ex2.approx.f32 %0, %1;" : "=f"(y) : "f"(x));
    return y;
}

__device__ __forceinline__ void split2(float x, float y, uint32_t& hi, uint32_t& lo) {
    __nv_bfloat16 hx = __float2bfloat16(x);
    __nv_bfloat16 hy = __float2bfloat16(y);
    __nv_bfloat16 lx = __float2bfloat16(x - __bfloat162float(hx));
    __nv_bfloat16 ly = __float2bfloat16(y - __bfloat162float(hy));
    hi = (uint32_t)__bfloat16_as_ushort(hx) | ((uint32_t)__bfloat16_as_ushort(hy) << 16);
    lo = (uint32_t)__bfloat16_as_ushort(lx) | ((uint32_t)__bfloat16_as_ushort(ly) << 16);
}

// ===================== GEMM template (512 threads, 16 warps) ===============
// Block tile 128x128, BK=32, warp tile 32x32 (2 m-frags x 4 n-frags).
#define ROWB   80
#define TILE   (128 * ROWB)
#define SM_AH  0
#define SM_AL  TILE
#define SM_BH  (2 * TILE)
#define SM_BL  (3 * TILE)

__device__ __forceinline__ void cvt_store2(const float4* va, const float4* vb,
                                           char* buf, int rbase, int seg) {
#pragma unroll
    for (int p = 0; p < 2; p++) {
        int off = (rbase + 64 * p) * ROWB + seg * 8;
        uint2 h, l;
        split2(va[p].x, va[p].y, h.x, l.x);
        split2(va[p].z, va[p].w, h.y, l.y);
        *(uint2*)(buf + SM_AH + off) = h;
        *(uint2*)(buf + SM_AL + off) = l;
        split2(vb[p].x, vb[p].y, h.x, l.x);
        split2(vb[p].z, vb[p].w, h.y, l.y);
        *(uint2*)(buf + SM_BH + off) = h;
        *(uint2*)(buf + SM_BL + off) = l;
    }
}

template <int KCHUNKS>
__device__ __forceinline__ void mma_gemm(const float* __restrict__ A, size_t lda,
                                         const float* __restrict__ B, size_t ldb,
                                         float acc[2][4][4], char* sm) {
    const int tid  = threadIdx.x;
    const int lane = tid & 31;
    const int wid  = tid >> 5;          // 0..15
    const int wm   = (wid >> 2) * 32;   // 4 m-warps
    const int wn   = (wid & 3) * 32;    // 4 n-warps
    const int seg  = tid & 7;
    const int rbase = tid >> 3;         // 0..63
    const uint32_t smb = smem_u32(sm);

    float4 va[2], vb[2];
#pragma unroll
    for (int p = 0; p < 2; p++) {
        va[p] = *(const float4*)(A + (size_t)(rbase + 64 * p) * lda + seg * 4);
        vb[p] = *(const float4*)(B + (size_t)(rbase + 64 * p) * ldb + seg * 4);
    }

    for (int c = 0; c < KCHUNKS; c++) {
        cvt_store2(va, vb, sm, rbase, seg);
        __syncthreads();

        if (c + 1 < KCHUNKS) {
            int co = (c + 1) * 32;
#pragma unroll
            for (int p = 0; p < 2; p++) {
                va[p] = *(const float4*)(A + (size_t)(rbase + 64 * p) * lda + co + seg * 4);
                vb[p] = *(const float4*)(B + (size_t)(rbase + 64 * p) * ldb + co + seg * 4);
            }
        }

#pragma unroll
        for (int ks = 0; ks < 2; ks++) {
            const int kb = ks * 32;
            uint32_t ah[2][4], al[2][4];
#pragma unroll
            for (int im = 0; im < 2; im++) {
                uint32_t ra = smb + (wm + im * 16 + (lane & 15)) * ROWB + (lane >> 4) * 16 + kb;
                ldsm_x4(ah[im][0], ah[im][1], ah[im][2], ah[im][3], ra + SM_AH);
                ldsm_x4(al[im][0], al[im][1], al[im][2], al[im][3], ra + SM_AL);
            }
            uint32_t bh[2][4], bl[2][4];
#pragma unroll
            for (int i2 = 0; i2 < 2; i2++) {
                uint32_t rb = smb + (wn + i2 * 16 + (lane & 15)) * ROWB + (lane >> 4) * 16 + kb;
                ldsm_x4(bh[i2][0], bh[i2][1], bh[i2][2], bh[i2][3], rb + SM_BH);
                ldsm_x4(bl[i2][0], bl[i2][1], bl[i2][2], bl[i2][3], rb + SM_BL);
            }
#pragma unroll
            for (int im = 0; im < 2; im++) {
#pragma unroll
                for (int in = 0; in < 4; in++) {
                    int i2 = in >> 1, sub = in & 1;
                    mma_bf16(acc[im][in], ah[im], bh[i2][sub], bh[i2][sub + 2]);
                    mma_bf16(acc[im][in], ah[im], bl[i2][sub], bl[i2][sub + 2]);
                    mma_bf16(acc[im][in], al[im], bh[i2][sub], bh[i2][sub + 2]);
                }
            }
        }
        __syncthreads();
    }
}

__global__ __launch_bounds__(512, 1)
void proj_mma(const float* __restrict__ query, const float* __restrict__ key_feat,
              const float* __restrict__ Wq, const float* __restrict__ Wk,
              const float* __restrict__ Wv) {
    __shared__ __align__(16) char sm[4 * TILE];
    const int s0  = blockIdx.x * 128;
    const int n   = blockIdx.y;
    const int sel = blockIdx.z;
    const float* __restrict__ X = (sel == 0) ? query : key_feat;
    const float* __restrict__ W = (sel == 0) ? Wq : (sel == 1 ? Wk : Wv);

    float acc[2][4][4];
#pragma unroll
    for (int i = 0; i < 2; i++)
#pragma unroll
        for (int j = 0; j < 4; j++)
#pragma unroll
            for (int t = 0; t < 4; t++) acc[i][j][t] = 0.f;

    mma_gemm<32>(W, DIM, X + (size_t)s0 * (NB * DIM) + (size_t)n * DIM, (size_t)NB * DIM,
                 acc, sm);

    const int lane = threadIdx.x & 31, wid = threadIdx.x >> 5;
    const int wm = (wid >> 2) * 32, wn = (wid & 3) * 32;
    float* __restrict__ outp = g_qkv + ((size_t)sel * NB + n) * ((size_t)INNER * SK);
#pragma unroll
    for (int im = 0; im < 2; im++) {
#pragma unroll
        for (int in = 0; in < 4; in++) {
            int e = wm + im * 16 + (lane >> 2);
            int s = s0 + wn + in * 8 + (lane & 3) * 2;
            *(float2*)&outp[(size_t)e * SK + s]       = make_float2(acc[im][in][0], acc[im][in][1]);
            *(float2*)&outp[(size_t)(e + 8) * SK + s] = make_float2(acc[im][in][2], acc[im][in][3]);
        }
    }
}

__global__ __launch_bounds__(512, 1)
void up_mma(const float* __restrict__ Wup, float* __restrict__ out) {
    __shared__ __align__(16) char sm[4 * TILE];
    const int d0 = blockIdx.x * 128;
    const int r0 = blockIdx.y * 128;

    float acc[2][4][4];
#pragma unroll
    for (int i = 0; i < 2; i++)
#pragma unroll
        for (int j = 0; j < 4; j++)
#pragma unroll
            for (int t = 0; t < 4; t++) acc[i][j][t] = 0.f;

    mma_gemm<4>(g_x + (size_t)r0 * INNER, INNER, Wup + (size_t)d0 * INNER, INNER, acc, sm);

    const int lane = threadIdx.x & 31, wid = threadIdx.x >> 5;
    const int wm = (wid >> 2) * 32, wn = (wid & 3) * 32;
#pragma unroll
    for (int im = 0; im < 2; im++) {
#pragma unroll
        for (int in = 0; in < 4; in++) {
            int d = d0 + wn + in * 8 + (lane & 3) * 2;
#pragma unroll
            for (int half = 0; half < 2; half++) {
                int r = r0 + wm + im * 16 + (lane >> 2) + half * 8;
                int nn = r >> 11, pp = r & 2047;
                *(float2*)&out[((size_t)pp * NB + nn) * DIM + d] =
                    make_float2(acc[im][in][half * 2], acc[im][in][half * 2 + 1]);
            }
        }
    }
}

// ===================== Flash attention on HMMA (R5 proven version) =========
#define QP 136
#define KP 72
#define VP 36

__global__ __launch_bounds__(128, 2)
void attn_mma() {
    const int p0 = blockIdx.x * 128;
    const int h  = blockIdx.y;
    const int n  = blockIdx.z;

    const float* __restrict__ q = g_qkv + ((size_t)0 * NB + n) * ((size_t)INNER * SK) + (size_t)(h * HD) * SK;
    const float* __restrict__ k = g_qkv + ((size_t)1 * NB + n) * ((size_t)INNER * SK) + (size_t)(h * HD) * SK;
    const float* __restrict__ v = g_qkv + ((size_t)2 * NB + n) * ((size_t)INNER * SK) + (size_t)(h * HD) * SK;

    __shared__ uint32_t qsh[16 * QP], qsl[16 * QP];
    __shared__ uint32_t ksh[16 * KP], ksl[16 * KP];
    __shared__ uint32_t vsh[32 * VP], vsl[32 * VP];

    const int tid  = threadIdx.x;
    const int lane = tid & 31;
    const int w    = tid >> 5;

#pragma unroll
    for (int t4 = 0; t4 < 4; t4++) {
        int task = tid + t4 * 128;
        int cp = task >> 5, qg = task & 31;
        int qq = qg * 4;
        float4 f0 = *(const float4*)&q[(size_t)(2 * cp) * SK + p0 + qq];
        float4 f1 = *(const float4*)&q[(size_t)(2 * cp + 1) * SK + p0 + qq];
        uint4 hh, ll;
        split2(f0.x, f1.x, hh.x, ll.x);
        split2(f0.y, f1.y, hh.y, ll.y);
        split2(f0.z, f1.z, hh.z, ll.z);
        split2(f0.w, f1.w, hh.w, ll.w);
        *(uint4*)&qsh[cp * QP + qq] = hh;
        *(uint4*)&qsl[cp * QP + qq] = ll;
    }
    __syncthreads();

    uint32_t qfh[2][2][4], qfl[2][2][4];
#pragma unroll
    for (int im = 0; im < 2; im++) {
#pragma unroll
        for (int ks = 0; ks < 2; ks++) {
            int row = w * 32 + im * 16 + (lane >> 2);
            int cp  = (lane & 3) + ks * 8;
            qfh[im][ks][0] = qsh[cp * QP + row];
            qfh[im][ks][1] = qsh[cp * QP + row + 8];
            qfh[im][ks][2] = qsh[(cp + 4) * QP + row];
            qfh[im][ks][3] = qsh[(cp + 4) * QP + row + 8];
            qfl[im][ks][0] = qsl[cp * QP + row];
            qfl[im][ks][1] = qsl[cp * QP + row + 8];
            qfl[im][ks][2] = qsl[(cp + 4) * QP + row];
            qfl[im][ks][3] = qsl[(cp + 4) * QP + row + 8];
        }
    }

    float oacc[2][4][4];
#pragma unroll
    for (int im = 0; im < 2; im++)
#pragma unroll
        for (int nt = 0; nt < 4; nt++)
#pragma unroll
            for (int t = 0; t < 4; t++) oacc[im][nt][t] = 0.f;
    float rowm[2][2] = {{-1e30f, -1e30f}, {-1e30f, -1e30f}};
    float rowl[2][2] = {{0.f, 0.f}, {0.f, 0.f}};

    const float SC2 = 0.17677669529663687f * 1.4426950408889634f;

    for (int k0 = 0; k0 < SK; k0 += 64) {
#pragma unroll
        for (int t2 = 0; t2 < 2; t2++) {
            int task = tid + t2 * 128;
            int cp = task >> 4, kg = task & 15;
            int kk = kg * 4;
            float4 f0 = *(const float4*)&k[(size_t)(2 * cp) * SK + k0 + kk];
            float4 f1 = *(const float4*)&k[(size_t)(2 * cp + 1) * SK + k0 + kk];
            uint4 hh, ll;
            split2(f0.x, f1.x, hh.x, ll.x);
            split2(f0.y, f1.y, hh.y, ll.y);
            split2(f0.z, f1.z, hh.z, ll.z);
            split2(f0.w, f1.w, hh.w, ll.w);
            *(uint4*)&ksh[cp * KP + kk] = hh;
            *(uint4*)&ksl[cp * KP + kk] = ll;
        }
#pragma unroll
        for (int t4 = 0; t4 < 4; t4++) {
            int task = tid + t4 * 128;
            int c = task >> 4, kg = task & 15;
            int kk = kg * 4;
            float4 f = *(const float4*)&v[(size_t)c * SK + k0 + kk];
            uint2 hh, ll;
            split2(f.x, f.y, hh.x, ll.x);
            split2(f.z, f.w, hh.y, ll.y);
            *(uint2*)&vsh[c * VP + (kk >> 1)] = hh;
            *(uint2*)&vsl[c * VP + (kk >> 1)] = ll;
        }
        __syncthreads();

        float sacc[2][8][4];
#pragma unroll
        for (int im = 0; im < 2; im++)
#pragma unroll
            for (int in = 0; in < 8; in++)
#pragma unroll
                for (int t = 0; t < 4; t++) sacc[im][in][t] = 0.f;

#pragma unroll
        for (int ks = 0; ks < 2; ks++) {
            uint32_t bh[8][2], bl[8][2];
#pragma unroll
            for (int in = 0; in < 8; in++) {
                int cp = (lane & 3) + ks * 8;
                int ky = in * 8 + (lane >> 2);
                bh[in][0] = ksh[cp * KP + ky];
                bh[in][1] = ksh[(cp + 4) * KP + ky];
                bl[in][0] = ksl[cp * KP + ky];
                bl[in][1] = ksl[(cp + 4) * KP + ky];
            }
#pragma unroll
            for (int im = 0; im < 2; im++)
#pragma unroll
                for (int in = 0; in < 8; in++) {
                    mma_bf16(sacc[im][in], qfh[im][ks], bh[in][0], bh[in][1]);
                    mma_bf16(sacc[im][in], qfh[im][ks], bl[in][0], bl[in][1]);
                    mma_bf16(sacc[im][in], qfl[im][ks], bh[in][0], bh[in][1]);
                }
        }

#pragma unroll
        for (int im = 0; im < 2; im++) {
#pragma unroll
            for (int rs = 0; rs < 2; rs++) {
                float mx = rowm[im][rs];
#pragma unroll
                for (int in = 0; in < 8; in++)
                    mx = fmaxf(mx, fmaxf(sacc[im][in][rs * 2], sacc[im][in][rs * 2 + 1]));
                mx = fmaxf(mx, __shfl_xor_sync(0xffffffffu, mx, 1));
                mx = fmaxf(mx, __shfl_xor_sync(0xffffffffu, mx, 2));
                float corr = ex2f((rowm[im][rs] - mx) * SC2);
                rowm[im][rs] = mx;
                float sum = 0.f;
#pragma unroll
                for (int in = 0; in < 8; in++) {
                    float e0 = ex2f((sacc[im][in][rs * 2] - mx) * SC2);
                    float e1 = ex2f((sacc[im][in][rs * 2 + 1] - mx) * SC2);
                    sacc[im][in][rs * 2] = e0;
                    sacc[im][in][rs * 2 + 1] = e1;
                    sum += e0 + e1;
                }
                rowl[im][rs] = rowl[im][rs] * corr + sum;
#pragma unroll
                for (int nt = 0; nt < 4; nt++) {
                    oacc[im][nt][rs * 2] *= corr;
                    oacc[im][nt][rs * 2 + 1] *= corr;
                }
            }
        }

#pragma unroll
        for (int ks4 = 0; ks4 < 4; ks4++) {
            uint32_t pfh[2][4], pfl[2][4];
#pragma unroll
            for (int im = 0; im < 2; im++) {
                const float* t0 = sacc[im][2 * ks4];
                const float* t1 = sacc[im][2 * ks4 + 1];
                split2(t0[0], t0[1], pfh[im][0], pfl[im][0]);
                split2(t0[2], t0[3], pfh[im][1], pfl[im][1]);
                split2(t1[0], t1[1], pfh[im][2], pfl[im][2]);
                split2(t1[2], t1[3], pfh[im][3], pfl[im][3]);
            }
            uint32_t bh[4][2], bl[4][2];
#pragma unroll
            for (int nt = 0; nt < 4; nt++) {
                int c  = nt * 8 + (lane >> 2);
                int kp = (lane & 3) + ks4 * 8;
                bh[nt][0] = vsh[c * VP + kp];
                bh[nt][1] = vsh[c * VP + kp + 4];
                bl[nt][0] = vsl[c * VP + kp];
                bl[nt][1] = vsl[c * VP + kp + 4];
            }
#pragma unroll
            for (int im = 0; im < 2; im++)
#pragma unroll
                for (int nt = 0; nt < 4; nt++) {
                    mma_bf16(oacc[im][nt], pfh[im], bh[nt][0], bh[nt][1]);
                    mma_bf16(oacc[im][nt], pfl[im], bh[nt][0], bh[nt][1]);
                    mma_bf16(oacc[im][nt], pfh[im], bl[nt][0], bl[nt][1]);
                }
        }
        __syncthreads();
    }

#pragma unroll
    for (int im = 0; im < 2; im++) {
#pragma unroll
        for (int rs = 0; rs < 2; rs++) {
            float l = rowl[im][rs];
            l += __shfl_xor_sync(0xffffffffu, l, 1);
            l += __shfl_xor_sync(0xffffffffu, l, 2);
            float inv = 1.f / l;
#pragma unroll
            for (int nt = 0; nt < 4; nt++) {
                oacc[im][nt][rs * 2] *= inv;
                oacc[im][nt][rs * 2 + 1] *= inv;
            }
        }
    }
    float* __restrict__ xout = g_x + (size_t)n * SQ * INNER + h * HD;
#pragma unroll
    for (int im = 0; im < 2; im++) {
#pragma unroll
        for (int nt = 0; nt < 4; nt++) {
            int row = p0 + w * 32 + im * 16 + (lane >> 2);
            int col = nt * 8 + (lane & 3) * 2;
            *(float2*)&xout[(size_t)row * INNER + col] =
                make_float2(oacc[im][nt][0], oacc[im][nt][1]);
            *(float2*)&xout[(size_t)(row + 8) * INNER + col] =
                make_float2(oacc[im][nt][2], oacc[im][nt][3]);
        }
    }
}

// ---------------------------------------------------------------------------
extern "C" void kernel_launch(void* const* d_in, const int* in_sizes, int n_in,
                              void* d_out, int out_size) {
    const float* query    = (const float*)d_in[0];
    const float* key_feat = (const float*)d_in[1];
    const float* Wq       = (const float*)d_in[2];
    const float* Wk       = (const float*)d_in[3];
    const float* Wv       = (const float*)d_in[4];
    const float* Wup      = (const float*)d_in[5];
    float* out            = (float*)d_out;

    dim3 g1(SK / 128, NB, 3);
    proj_mma<<<g1, 512>>>(query, key_feat, Wq, Wk, Wv);

    dim3 g2(SQ / 128, NH, NB);
    attn_mma<<<g2, 128>>>();

    dim3 g3(DIM / 128, (NB * SQ) / 128);
    up_mma<<<g3, 512>>>(Wup, out);
}

// round 9
// speedup vs baseline: 1.2171x; 1.1481x over previous
#include <cuda_runtime.h>
#include <cuda_fp16.h>
#include <cstdint>

#define SQ 2048
#define SK 2048
#define NB 8
#define DIM 1024
#define INNER 128
#define NH 4
#define HD 32

// Scratch (allocation-free)
__device__ float g_qkv[3u * NB * INNER * SK];   // [sel][n][e][s]
__device__ float g_x[(size_t)NB * SQ * INNER];  // [n][p][e]

// ============================ warp-MMA helpers =============================
__device__ __forceinline__ uint32_t smem_u32(const void* p) {
    return (uint32_t)__cvta_generic_to_shared(p);
}
__device__ __forceinline__ void ldsm_x4(uint32_t& r0, uint32_t& r1,
                                        uint32_t& r2, uint32_t& r3, uint32_t addr) {
    asm volatile("ldmatrix.sync.aligned.m8n8.x4.shared.b16 {%0,%1,%2,%3}, [%4];"
                 : "=r"(r0), "=r"(r1), "=r"(r2), "=r"(r3) : "r"(addr));
}
__device__ __forceinline__ void mma_f16(float* d, const uint32_t* a,
                                        uint32_t b0, uint32_t b1) {
    asm volatile(
        "mma.sync.aligned.m16n8k16.row.col.f32.f16.f16.f32 "
        "{%0,%1,%2,%3}, {%4,%5,%6,%7}, {%8,%9}, {%0,%1,%2,%3};"
        : "+f"(d[0]), "+f"(d[1]), "+f"(d[2]), "+f"(d[3])
        : "r"(a[0]), "r"(a[1]), "r"(a[2]), "r"(a[3]), "r"(b0), "r"(b1));
}
__device__ __forceinline__ float ex2f(float x) {
    float y;
    asm("ex2.approx.f32 %0, %1;" : "=f"(y) : "f"(x));
    return y;
}

// fp16 hi/lo split of a float pair.
__device__ __forceinline__ void split2(float x, float y, uint32_t& hi, uint32_t& lo) {
    __half hx = __float2half_rn(x);
    __half hy = __float2half_rn(y);
    __half lx = __float2half_rn(x - __half2float(hx));
    __half ly = __float2half_rn(y - __half2float(hy));
    hi = (uint32_t)__half_as_ushort(hx) | ((uint32_t)__half_as_ushort(hy) << 16);
    lo = (uint32_t)__half_as_ushort(lx) | ((uint32_t)__half_as_ushort(ly) << 16);
}
// single fp16 round of a float pair.
__device__ __forceinline__ uint32_t pack1(float x, float y) {
    return (uint32_t)__half_as_ushort(__float2half_rn(x))
         | ((uint32_t)__half_as_ushort(__float2half_rn(y)) << 16);
}

// ===================== GEMM template (512 threads, 16 warps) ===============
// Block tile 128x128, BK=32, warp tile 32x32.
// TERMS=3: A split, B split -> AhBh + AhBl + AlBh  (err ~u^2)
// TERMS=2: A split, B single -> AhBh + AlBh        (err ~u on B)
#define ROWB   80
#define TILE   (128 * ROWB)
#define SM_AH  0
#define SM_AL  TILE
#define SM_BH  (2 * TILE)
#define SM_BL  (3 * TILE)

template <int TERMS>
__device__ __forceinline__ void cvt_store2(const float4* va, const float4* vb,
                                           char* buf, int rbase, int seg) {
#pragma unroll
    for (int p = 0; p < 2; p++) {
        int off = (rbase + 64 * p) * ROWB + seg * 8;
        uint2 h, l;
        split2(va[p].x, va[p].y, h.x, l.x);
        split2(va[p].z, va[p].w, h.y, l.y);
        *(uint2*)(buf + SM_AH + off) = h;
        *(uint2*)(buf + SM_AL + off) = l;
        if (TERMS == 3) {
            split2(vb[p].x, vb[p].y, h.x, l.x);
            split2(vb[p].z, vb[p].w, h.y, l.y);
            *(uint2*)(buf + SM_BH + off) = h;
            *(uint2*)(buf + SM_BL + off) = l;
        } else {
            h.x = pack1(vb[p].x, vb[p].y);
            h.y = pack1(vb[p].z, vb[p].w);
            *(uint2*)(buf + SM_BH + off) = h;
        }
    }
}

template <int KCHUNKS, int TERMS>
__device__ __forceinline__ void mma_gemm(const float* __restrict__ A, size_t lda,
                                         const float* __restrict__ B, size_t ldb,
                                         float acc[2][4][4], char* sm) {
    const int tid  = threadIdx.x;
    const int lane = tid & 31;
    const int wid  = tid >> 5;
    const int wm   = (wid >> 2) * 32;
    const int wn   = (wid & 3) * 32;
    const int seg  = tid & 7;
    const int rbase = tid >> 3;
    const uint32_t smb = smem_u32(sm);

    float4 va[2], vb[2];
#pragma unroll
    for (int p = 0; p < 2; p++) {
        va[p] = *(const float4*)(A + (size_t)(rbase + 64 * p) * lda + seg * 4);
        vb[p] = *(const float4*)(B + (size_t)(rbase + 64 * p) * ldb + seg * 4);
    }

    for (int c = 0; c < KCHUNKS; c++) {
        cvt_store2<TERMS>(va, vb, sm, rbase, seg);
        __syncthreads();

        if (c + 1 < KCHUNKS) {
            int co = (c + 1) * 32;
#pragma unroll
            for (int p = 0; p < 2; p++) {
                va[p] = *(const float4*)(A + (size_t)(rbase + 64 * p) * lda + co + seg * 4);
                vb[p] = *(const float4*)(B + (size_t)(rbase + 64 * p) * ldb + co + seg * 4);
            }
        }

#pragma unroll
        for (int ks = 0; ks < 2; ks++) {
            const int kb = ks * 32;
            uint32_t ah[2][4], al[2][4];
#pragma unroll
            for (int im = 0; im < 2; im++) {
                uint32_t ra = smb + (wm + im * 16 + (lane & 15)) * ROWB + (lane >> 4) * 16 + kb;
                ldsm_x4(ah[im][0], ah[im][1], ah[im][2], ah[im][3], ra + SM_AH);
                ldsm_x4(al[im][0], al[im][1], al[im][2], al[im][3], ra + SM_AL);
            }
            uint32_t bh[2][4], bl[2][4];
#pragma unroll
            for (int i2 = 0; i2 < 2; i2++) {
                uint32_t rb = smb + (wn + i2 * 16 + (lane & 15)) * ROWB + (lane >> 4) * 16 + kb;
                ldsm_x4(bh[i2][0], bh[i2][1], bh[i2][2], bh[i2][3], rb + SM_BH);
                if (TERMS == 3)
                    ldsm_x4(bl[i2][0], bl[i2][1], bl[i2][2], bl[i2][3], rb + SM_BL);
            }
#pragma unroll
            for (int im = 0; im < 2; im++) {
#pragma unroll
                for (int in = 0; in < 4; in++) {
                    int i2 = in >> 1, sub = in & 1;
                    mma_f16(acc[im][in], ah[im], bh[i2][sub], bh[i2][sub + 2]);
                    if (TERMS == 3)
                        mma_f16(acc[im][in], ah[im], bl[i2][sub], bl[i2][sub + 2]);
                    mma_f16(acc[im][in], al[im], bh[i2][sub], bh[i2][sub + 2]);
                }
            }
        }
        __syncthreads();
    }
}

// proj for q,k (TERMS=3) and v (TERMS=2); shared body.
template <int TERMS>
__device__ __forceinline__ void proj_body(const float* __restrict__ X,
                                          const float* __restrict__ W,
                                          int s0, int n, int sel, char* sm) {
    float acc[2][4][4];
#pragma unroll
    for (int i = 0; i < 2; i++)
#pragma unroll
        for (int j = 0; j < 4; j++)
#pragma unroll
            for (int t = 0; t < 4; t++) acc[i][j][t] = 0.f;

    mma_gemm<32, TERMS>(W, DIM, X + (size_t)s0 * (NB * DIM) + (size_t)n * DIM,
                        (size_t)NB * DIM, acc, sm);

    const int lane = threadIdx.x & 31, wid = threadIdx.x >> 5;
    const int wm = (wid >> 2) * 32, wn = (wid & 3) * 32;
    float* __restrict__ outp = g_qkv + ((size_t)sel * NB + n) * ((size_t)INNER * SK);
#pragma unroll
    for (int im = 0; im < 2; im++) {
#pragma unroll
        for (int in = 0; in < 4; in++) {
            int e = wm + im * 16 + (lane >> 2);
            int s = s0 + wn + in * 8 + (lane & 3) * 2;
            *(float2*)&outp[(size_t)e * SK + s]       = make_float2(acc[im][in][0], acc[im][in][1]);
            *(float2*)&outp[(size_t)(e + 8) * SK + s] = make_float2(acc[im][in][2], acc[im][in][3]);
        }
    }
}

__global__ __launch_bounds__(512, 1)
void proj_qk(const float* __restrict__ query, const float* __restrict__ key_feat,
             const float* __restrict__ Wq, const float* __restrict__ Wk) {
    __shared__ __align__(16) char sm[4 * TILE];
    const int s0  = blockIdx.x * 128;
    const int n   = blockIdx.y;
    const int sel = blockIdx.z;
    proj_body<3>((sel == 0) ? query : key_feat, (sel == 0) ? Wq : Wk, s0, n, sel, sm);
}

__global__ __launch_bounds__(512, 1)
void proj_v(const float* __restrict__ key_feat, const float* __restrict__ Wv) {
    __shared__ __align__(16) char sm[3 * TILE];
    const int s0 = blockIdx.x * 128;
    const int n  = blockIdx.y;
    proj_body<2>(key_feat, Wv, s0, n, 2, sm);
}

__global__ __launch_bounds__(512, 1)
void up_mma(const float* __restrict__ Wup, float* __restrict__ out) {
    __shared__ __align__(16) char sm[3 * TILE];
    const int d0 = blockIdx.x * 128;
    const int r0 = blockIdx.y * 128;

    float acc[2][4][4];
#pragma unroll
    for (int i = 0; i < 2; i++)
#pragma unroll
        for (int j = 0; j < 4; j++)
#pragma unroll
            for (int t = 0; t < 4; t++) acc[i][j][t] = 0.f;

    mma_gemm<4, 2>(g_x + (size_t)r0 * INNER, INNER, Wup + (size_t)d0 * INNER, INNER, acc, sm);

    const int lane = threadIdx.x & 31, wid = threadIdx.x >> 5;
    const int wm = (wid >> 2) * 32, wn = (wid & 3) * 32;
#pragma unroll
    for (int im = 0; im < 2; im++) {
#pragma unroll
        for (int in = 0; in < 4; in++) {
            int d = d0 + wn + in * 8 + (lane & 3) * 2;
#pragma unroll
            for (int half = 0; half < 2; half++) {
                int r = r0 + wm + im * 16 + (lane >> 2) + half * 8;
                int nn = r >> 11, pp = r & 2047;
                *(float2*)&out[((size_t)pp * NB + nn) * DIM + d] =
                    make_float2(acc[im][in][half * 2], acc[im][in][half * 2 + 1]);
            }
        }
    }
}

// ===================== Flash attention on HMMA =============================
// Q split (hi/lo regs), K single fp16, P split, V single fp16.
#define QP 136
#define KP 72
#define VP 36

__global__ __launch_bounds__(128, 2)
void attn_mma() {
    const int p0 = blockIdx.x * 128;
    const int h  = blockIdx.y;
    const int n  = blockIdx.z;

    const float* __restrict__ q = g_qkv + ((size_t)0 * NB + n) * ((size_t)INNER * SK) + (size_t)(h * HD) * SK;
    const float* __restrict__ k = g_qkv + ((size_t)1 * NB + n) * ((size_t)INNER * SK) + (size_t)(h * HD) * SK;
    const float* __restrict__ v = g_qkv + ((size_t)2 * NB + n) * ((size_t)INNER * SK) + (size_t)(h * HD) * SK;

    __shared__ uint32_t qsh[16 * QP], qsl[16 * QP];
    __shared__ uint32_t ksh[16 * KP];
    __shared__ uint32_t vsh[32 * VP];

    const int tid  = threadIdx.x;
    const int lane = tid & 31;
    const int w    = tid >> 5;

#pragma unroll
    for (int t4 = 0; t4 < 4; t4++) {
        int task = tid + t4 * 128;
        int cp = task >> 5, qg = task & 31;
        int qq = qg * 4;
        float4 f0 = *(const float4*)&q[(size_t)(2 * cp) * SK + p0 + qq];
        float4 f1 = *(const float4*)&q[(size_t)(2 * cp + 1) * SK + p0 + qq];
        uint4 hh, ll;
        split2(f0.x, f1.x, hh.x, ll.x);
        split2(f0.y, f1.y, hh.y, ll.y);
        split2(f0.z, f1.z, hh.z, ll.z);
        split2(f0.w, f1.w, hh.w, ll.w);
        *(uint4*)&qsh[cp * QP + qq] = hh;
        *(uint4*)&qsl[cp * QP + qq] = ll;
    }
    __syncthreads();

    uint32_t qfh[2][2][4], qfl[2][2][4];
#pragma unroll
    for (int im = 0; im < 2; im++) {
#pragma unroll
        for (int ks = 0; ks < 2; ks++) {
            int row = w * 32 + im * 16 + (lane >> 2);
            int cp  = (lane & 3) + ks * 8;
            qfh[im][ks][0] = qsh[cp * QP + row];
            qfh[im][ks][1] = qsh[cp * QP + row + 8];
            qfh[im][ks][2] = qsh[(cp + 4) * QP + row];
            qfh[im][ks][3] = qsh[(cp + 4) * QP + row + 8];
            qfl[im][ks][0] = qsl[cp * QP + row];
            qfl[im][ks][1] = qsl[cp * QP + row + 8];
            qfl[im][ks][2] = qsl[(cp + 4) * QP + row];
            qfl[im][ks][3] = qsl[(cp + 4) * QP + row + 8];
        }
    }

    float oacc[2][4][4];
#pragma unroll
    for (int im = 0; im < 2; im++)
#pragma unroll
        for (int nt = 0; nt < 4; nt++)
#pragma unroll
            for (int t = 0; t < 4; t++) oacc[im][nt][t] = 0.f;
    float rowm[2][2] = {{-1e30f, -1e30f}, {-1e30f, -1e30f}};
    float rowl[2][2] = {{0.f, 0.f}, {0.f, 0.f}};

    const float SC2 = 0.17677669529663687f * 1.4426950408889634f;

    for (int k0 = 0; k0 < SK; k0 += 64) {
        // stage K (single fp16) and V (single fp16)
#pragma unroll
        for (int t2 = 0; t2 < 2; t2++) {
            int task = tid + t2 * 128;
            int cp = task >> 4, kg = task & 15;
            int kk = kg * 4;
            float4 f0 = *(const float4*)&k[(size_t)(2 * cp) * SK + k0 + kk];
            float4 f1 = *(const float4*)&k[(size_t)(2 * cp + 1) * SK + k0 + kk];
            uint4 hh;
            hh.x = pack1(f0.x, f1.x);
            hh.y = pack1(f0.y, f1.y);
            hh.z = pack1(f0.z, f1.z);
            hh.w = pack1(f0.w, f1.w);
            *(uint4*)&ksh[cp * KP + kk] = hh;
        }
#pragma unroll
        for (int t4 = 0; t4 < 4; t4++) {
            int task = tid + t4 * 128;
            int c = task >> 4, kg = task & 15;
            int kk = kg * 4;
            float4 f = *(const float4*)&v[(size_t)c * SK + k0 + kk];
            uint2 hh;
            hh.x = pack1(f.x, f.y);
            hh.y = pack1(f.z, f.w);
            *(uint2*)&vsh[c * VP + (kk >> 1)] = hh;
        }
        __syncthreads();

        // S = Q K^T: 2 MMAs per frag (Qh·K + Ql·K)
        float sacc[2][8][4];
#pragma unroll
        for (int im = 0; im < 2; im++)
#pragma unroll
            for (int in = 0; in < 8; in++)
#pragma unroll
                for (int t = 0; t < 4; t++) sacc[im][in][t] = 0.f;

#pragma unroll
        for (int ks = 0; ks < 2; ks++) {
            uint32_t bh[8][2];
#pragma unroll
            for (int in = 0; in < 8; in++) {
                int cp = (lane & 3) + ks * 8;
                int ky = in * 8 + (lane >> 2);
                bh[in][0] = ksh[cp * KP + ky];
                bh[in][1] = ksh[(cp + 4) * KP + ky];
            }
#pragma unroll
            for (int im = 0; im < 2; im++)
#pragma unroll
                for (int in = 0; in < 8; in++) {
                    mma_f16(sacc[im][in], qfh[im][ks], bh[in][0], bh[in][1]);
                    mma_f16(sacc[im][in], qfl[im][ks], bh[in][0], bh[in][1]);
                }
        }

        // online softmax
#pragma unroll
        for (int im = 0; im < 2; im++) {
#pragma unroll
            for (int rs = 0; rs < 2; rs++) {
                float mx = rowm[im][rs];
#pragma unroll
                for (int in = 0; in < 8; in++)
                    mx = fmaxf(mx, fmaxf(sacc[im][in][rs * 2], sacc[im][in][rs * 2 + 1]));
                mx = fmaxf(mx, __shfl_xor_sync(0xffffffffu, mx, 1));
                mx = fmaxf(mx, __shfl_xor_sync(0xffffffffu, mx, 2));
                float corr = ex2f((rowm[im][rs] - mx) * SC2);
                rowm[im][rs] = mx;
                float sum = 0.f;
#pragma unroll
                for (int in = 0; in < 8; in++) {
                    float e0 = ex2f((sacc[im][in][rs * 2] - mx) * SC2);
                    float e1 = ex2f((sacc[im][in][rs * 2 + 1] - mx) * SC2);
                    sacc[im][in][rs * 2] = e0;
                    sacc[im][in][rs * 2 + 1] = e1;
                    sum += e0 + e1;
                }
                rowl[im][rs] = rowl[im][rs] * corr + sum;
#pragma unroll
                for (int nt = 0; nt < 4; nt++) {
                    oacc[im][nt][rs * 2] *= corr;
                    oacc[im][nt][rs * 2 + 1] *= corr;
                }
            }
        }

        // O += P V^T: P split hi/lo, V single -> 2 MMAs per frag
#pragma unroll
        for (int ks4 = 0; ks4 < 4; ks4++) {
            uint32_t pfh[2][4], pfl[2][4];
#pragma unroll
            for (int im = 0; im < 2; im++) {
                const float* t0 = sacc[im][2 * ks4];
                const float* t1 = sacc[im][2 * ks4 + 1];
                split2(t0[0], t0[1], pfh[im][0], pfl[im][0]);
                split2(t0[2], t0[3], pfh[im][1], pfl[im][1]);
                split2(t1[0], t1[1], pfh[im][2], pfl[im][2]);
                split2(t1[2], t1[3], pfh[im][3], pfl[im][3]);
            }
            uint32_t bh[4][2];
#pragma unroll
            for (int nt = 0; nt < 4; nt++) {
                int c  = nt * 8 + (lane >> 2);
                int kp = (lane & 3) + ks4 * 8;
                bh[nt][0] = vsh[c * VP + kp];
                bh[nt][1] = vsh[c * VP + kp + 4];
            }
#pragma unroll
            for (int im = 0; im < 2; im++)
#pragma unroll
                for (int nt = 0; nt < 4; nt++) {
                    mma_f16(oacc[im][nt], pfh[im], bh[nt][0], bh[nt][1]);
                    mma_f16(oacc[im][nt], pfl[im], bh[nt][0], bh[nt][1]);
                }
        }
        __syncthreads();
    }

#pragma unroll
    for (int im = 0; im < 2; im++) {
#pragma unroll
        for (int rs = 0; rs < 2; rs++) {
            float l = rowl[im][rs];
            l += __shfl_xor_sync(0xffffffffu, l, 1);
            l += __shfl_xor_sync(0xffffffffu, l, 2);
            float inv = 1.f / l;
#pragma unroll
            for (int nt = 0; nt < 4; nt++) {
                oacc[im][nt][rs * 2] *= inv;
                oacc[im][nt][rs * 2 + 1] *= inv;
            }
        }
    }
    float* __restrict__ xout = g_x + (size_t)n * SQ * INNER + h * HD;
#pragma unroll
    for (int im = 0; im < 2; im++) {
#pragma unroll
        for (int nt = 0; nt < 4; nt++) {
            int row = p0 + w * 32 + im * 16 + (lane >> 2);
            int col = nt * 8 + (lane & 3) * 2;
            *(float2*)&xout[(size_t)row * INNER + col] =
                make_float2(oacc[im][nt][0], oacc[im][nt][1]);
            *(float2*)&xout[(size_t)(row + 8) * INNER + col] =
                make_float2(oacc[im][nt][2], oacc[im][nt][3]);
        }
    }
}

// ---------------------------------------------------------------------------
extern "C" void kernel_launch(void* const* d_in, const int* in_sizes, int n_in,
                              void* d_out, int out_size) {
    const float* query    = (const float*)d_in[0];
    const float* key_feat = (const float*)d_in[1];
    const float* Wq       = (const float*)d_in[2];
    const float* Wk       = (const float*)d_in[3];
    const float* Wv       = (const float*)d_in[4];
    const float* Wup      = (const float*)d_in[5];
    float* out            = (float*)d_out;

    dim3 g1(SK / 128, NB, 2);
    proj_qk<<<g1, 512>>>(query, key_feat, Wq, Wk);

    dim3 g1v(SK / 128, NB, 1);
    proj_v<<<g1v, 512>>>(key_feat, Wv);

    dim3 g2(SQ / 128, NH, NB);
    attn_mma<<<g2, 128>>>();

    dim3 g3(DIM / 128, (NB * SQ) / 128);
    up_mma<<<g3, 512>>>(Wup, out);
}

// round 10
// speedup vs baseline: 1.2854x; 1.0561x over previous
#include <cuda_runtime.h>
#include <cuda_fp16.h>
#include <cstdint>

#define SQ 2048
#define SK 2048
#define NB 8
#define DIM 1024
#define INNER 128
#define NH 4
#define HD 32

// Scratch (allocation-free): packed-fp16 projections + fp32 attention output
__device__ uint32_t g_qh[(size_t)NB * 64 * SK];        // q hi  [n][cpair][s]
__device__ uint32_t g_ql[(size_t)NB * 64 * SK];        // q lo
__device__ uint32_t g_kk[(size_t)NB * 64 * SK];        // k     [n][cpair][s]
__device__ uint32_t g_vv[(size_t)NB * 128 * (SK / 2)]; // v     [n][c][spair]
__device__ float    g_x[(size_t)NB * SQ * INNER];      // [n][p][e]

// ============================ warp-MMA helpers =============================
__device__ __forceinline__ uint32_t smem_u32(const void* p) {
    return (uint32_t)__cvta_generic_to_shared(p);
}
__device__ __forceinline__ void ldsm_x4(uint32_t& r0, uint32_t& r1,
                                        uint32_t& r2, uint32_t& r3, uint32_t addr) {
    asm volatile("ldmatrix.sync.aligned.m8n8.x4.shared.b16 {%0,%1,%2,%3}, [%4];"
                 : "=r"(r0), "=r"(r1), "=r"(r2), "=r"(r3) : "r"(addr));
}
__device__ __forceinline__ void mma_f16(float* d, const uint32_t* a,
                                        uint32_t b0, uint32_t b1) {
    asm volatile(
        "mma.sync.aligned.m16n8k16.row.col.f32.f16.f16.f32 "
        "{%0,%1,%2,%3}, {%4,%5,%6,%7}, {%8,%9}, {%0,%1,%2,%3};"
        : "+f"(d[0]), "+f"(d[1]), "+f"(d[2]), "+f"(d[3])
        : "r"(a[0]), "r"(a[1]), "r"(a[2]), "r"(a[3]), "r"(b0), "r"(b1));
}
__device__ __forceinline__ float ex2f(float x) {
    float y;
    asm("ex2.approx.f32 %0, %1;" : "=f"(y) : "f"(x));
    return y;
}

__device__ __forceinline__ void split2(float x, float y, uint32_t& hi, uint32_t& lo) {
    __half hx = __float2half_rn(x);
    __half hy = __float2half_rn(y);
    __half lx = __float2half_rn(x - __half2float(hx));
    __half ly = __float2half_rn(y - __half2float(hy));
    hi = (uint32_t)__half_as_ushort(hx) | ((uint32_t)__half_as_ushort(hy) << 16);
    lo = (uint32_t)__half_as_ushort(lx) | ((uint32_t)__half_as_ushort(ly) << 16);
}
__device__ __forceinline__ uint32_t pack1(float x, float y) {
    return (uint32_t)__half_as_ushort(__float2half_rn(x))
         | ((uint32_t)__half_as_ushort(__float2half_rn(y)) << 16);
}

// ===================== GEMM template (512 threads, 16 warps) ===============
#define ROWB   80
#define TILE   (128 * ROWB)
#define SM_AH  0
#define SM_AL  TILE
#define SM_BH  (2 * TILE)
#define SM_BL  (3 * TILE)

template <int TERMS>
__device__ __forceinline__ void cvt_store2(const float4* va, const float4* vb,
                                           char* buf, int rbase, int seg) {
#pragma unroll
    for (int p = 0; p < 2; p++) {
        int off = (rbase + 64 * p) * ROWB + seg * 8;
        uint2 h, l;
        split2(va[p].x, va[p].y, h.x, l.x);
        split2(va[p].z, va[p].w, h.y, l.y);
        *(uint2*)(buf + SM_AH + off) = h;
        *(uint2*)(buf + SM_AL + off) = l;
        if (TERMS == 3) {
            split2(vb[p].x, vb[p].y, h.x, l.x);
            split2(vb[p].z, vb[p].w, h.y, l.y);
            *(uint2*)(buf + SM_BH + off) = h;
            *(uint2*)(buf + SM_BL + off) = l;
        } else {
            h.x = pack1(vb[p].x, vb[p].y);
            h.y = pack1(vb[p].z, vb[p].w);
            *(uint2*)(buf + SM_BH + off) = h;
        }
    }
}

template <int KCHUNKS, int TERMS>
__device__ __forceinline__ void mma_gemm(const float* __restrict__ A, size_t lda,
                                         const float* __restrict__ B, size_t ldb,
                                         float acc[2][4][4], char* sm) {
    const int tid  = threadIdx.x;
    const int lane = tid & 31;
    const int wid  = tid >> 5;
    const int wm   = (wid >> 2) * 32;
    const int wn   = (wid & 3) * 32;
    const int seg  = tid & 7;
    const int rbase = tid >> 3;
    const uint32_t smb = smem_u32(sm);

    float4 va[2], vb[2];
#pragma unroll
    for (int p = 0; p < 2; p++) {
        va[p] = *(const float4*)(A + (size_t)(rbase + 64 * p) * lda + seg * 4);
        vb[p] = *(const float4*)(B + (size_t)(rbase + 64 * p) * ldb + seg * 4);
    }

    for (int c = 0; c < KCHUNKS; c++) {
        cvt_store2<TERMS>(va, vb, sm, rbase, seg);
        __syncthreads();

        if (c + 1 < KCHUNKS) {
            int co = (c + 1) * 32;
#pragma unroll
            for (int p = 0; p < 2; p++) {
                va[p] = *(const float4*)(A + (size_t)(rbase + 64 * p) * lda + co + seg * 4);
                vb[p] = *(const float4*)(B + (size_t)(rbase + 64 * p) * ldb + co + seg * 4);
            }
        }

#pragma unroll
        for (int ks = 0; ks < 2; ks++) {
            const int kb = ks * 32;
            uint32_t ah[2][4], al[2][4];
#pragma unroll
            for (int im = 0; im < 2; im++) {
                uint32_t ra = smb + (wm + im * 16 + (lane & 15)) * ROWB + (lane >> 4) * 16 + kb;
                ldsm_x4(ah[im][0], ah[im][1], ah[im][2], ah[im][3], ra + SM_AH);
                ldsm_x4(al[im][0], al[im][1], al[im][2], al[im][3], ra + SM_AL);
            }
            uint32_t bh[2][4], bl[2][4];
#pragma unroll
            for (int i2 = 0; i2 < 2; i2++) {
                uint32_t rb = smb + (wn + i2 * 16 + (lane & 15)) * ROWB + (lane >> 4) * 16 + kb;
                ldsm_x4(bh[i2][0], bh[i2][1], bh[i2][2], bh[i2][3], rb + SM_BH);
                if (TERMS == 3)
                    ldsm_x4(bl[i2][0], bl[i2][1], bl[i2][2], bl[i2][3], rb + SM_BL);
            }
#pragma unroll
            for (int im = 0; im < 2; im++) {
#pragma unroll
                for (int in = 0; in < 4; in++) {
                    int i2 = in >> 1, sub = in & 1;
                    mma_f16(acc[im][in], ah[im], bh[i2][sub], bh[i2][sub + 2]);
                    if (TERMS == 3)
                        mma_f16(acc[im][in], ah[im], bl[i2][sub], bl[i2][sub + 2]);
                    mma_f16(acc[im][in], al[im], bh[i2][sub], bh[i2][sub + 2]);
                }
            }
        }
        __syncthreads();
    }
}

// q/k projection: 3-term; epilogue writes packed-fp16 pair layout.
__global__ __launch_bounds__(512, 1)
void proj_qk(const float* __restrict__ query, const float* __restrict__ key_feat,
             const float* __restrict__ Wq, const float* __restrict__ Wk) {
    __shared__ __align__(16) char sm[4 * TILE];
    const int s0  = blockIdx.x * 128;
    const int n   = blockIdx.y;
    const int sel = blockIdx.z;
    const float* __restrict__ X = (sel == 0) ? query : key_feat;
    const float* __restrict__ W = (sel == 0) ? Wq : Wk;

    float acc[2][4][4];
#pragma unroll
    for (int i = 0; i < 2; i++)
#pragma unroll
        for (int j = 0; j < 4; j++)
#pragma unroll
            for (int t = 0; t < 4; t++) acc[i][j][t] = 0.f;

    mma_gemm<32, 3>(W, DIM, X + (size_t)s0 * (NB * DIM) + (size_t)n * DIM,
                    (size_t)NB * DIM, acc, sm);

    const int lane = threadIdx.x & 31, wid = threadIdx.x >> 5;
    const int wm = (wid >> 2) * 32, wn = (wid & 3) * 32;
    const bool even = ((lane >> 2) & 1) == 0;

#pragma unroll
    for (int im = 0; im < 2; im++) {
#pragma unroll
        for (int in = 0; in < 4; in++) {
#pragma unroll
            for (int half = 0; half < 2; half++) {
                int row = wm + im * 16 + (lane >> 2) + half * 8;
                int s = s0 + wn + in * 8 + (lane & 3) * 2;
                int cp = row >> 1;
                size_t base = ((size_t)n * 64 + cp) * SK + s;
                if (sel == 0) {
                    uint32_t hi, lo;
                    split2(acc[im][in][2 * half], acc[im][in][2 * half + 1], hi, lo);
                    uint32_t hp = __shfl_xor_sync(0xffffffffu, hi, 4);
                    uint32_t lp = __shfl_xor_sync(0xffffffffu, lo, 4);
                    if (even) {
                        uint2 o;
                        o.x = (hi & 0xFFFFu) | (hp << 16);
                        o.y = (hi >> 16) | (hp & 0xFFFF0000u);
                        *(uint2*)&g_qh[base] = o;
                    } else {
                        uint2 o;
                        o.x = (lp & 0xFFFFu) | (lo << 16);
                        o.y = (lp >> 16) | (lo & 0xFFFF0000u);
                        *(uint2*)&g_ql[base] = o;
                    }
                } else {
                    uint32_t w = pack1(acc[im][in][2 * half], acc[im][in][2 * half + 1]);
                    uint32_t wp = __shfl_xor_sync(0xffffffffu, w, 4);
                    if (even) {
                        uint2 o;
                        o.x = (w & 0xFFFFu) | (wp << 16);
                        o.y = (w >> 16) | (wp & 0xFFFF0000u);
                        *(uint2*)&g_kk[base] = o;
                    }
                }
            }
        }
    }
}

// v projection: 2-term; epilogue packs fp16 pairs along s.
__global__ __launch_bounds__(512, 1)
void proj_v(const float* __restrict__ key_feat, const float* __restrict__ Wv) {
    __shared__ __align__(16) char sm[3 * TILE];
    const int s0 = blockIdx.x * 128;
    const int n  = blockIdx.y;

    float acc[2][4][4];
#pragma unroll
    for (int i = 0; i < 2; i++)
#pragma unroll
        for (int j = 0; j < 4; j++)
#pragma unroll
            for (int t = 0; t < 4; t++) acc[i][j][t] = 0.f;

    mma_gemm<32, 2>(Wv, DIM, key_feat + (size_t)s0 * (NB * DIM) + (size_t)n * DIM,
                    (size_t)NB * DIM, acc, sm);

    const int lane = threadIdx.x & 31, wid = threadIdx.x >> 5;
    const int wm = (wid >> 2) * 32, wn = (wid & 3) * 32;
#pragma unroll
    for (int im = 0; im < 2; im++) {
#pragma unroll
        for (int in = 0; in < 4; in++) {
#pragma unroll
            for (int half = 0; half < 2; half++) {
                int row = wm + im * 16 + (lane >> 2) + half * 8;
                int s = s0 + wn + in * 8 + (lane & 3) * 2;
                g_vv[((size_t)n * 128 + row) * (SK / 2) + (s >> 1)] =
                    pack1(acc[im][in][2 * half], acc[im][in][2 * half + 1]);
            }
        }
    }
}

__global__ __launch_bounds__(512, 1)
void up_mma(const float* __restrict__ Wup, float* __restrict__ out) {
    __shared__ __align__(16) char sm[3 * TILE];
    const int d0 = blockIdx.x * 128;
    const int r0 = blockIdx.y * 128;

    float acc[2][4][4];
#pragma unroll
    for (int i = 0; i < 2; i++)
#pragma unroll
        for (int j = 0; j < 4; j++)
#pragma unroll
            for (int t = 0; t < 4; t++) acc[i][j][t] = 0.f;

    mma_gemm<4, 2>(g_x + (size_t)r0 * INNER, INNER, Wup + (size_t)d0 * INNER, INNER, acc, sm);

    const int lane = threadIdx.x & 31, wid = threadIdx.x >> 5;
    const int wm = (wid >> 2) * 32, wn = (wid & 3) * 32;
#pragma unroll
    for (int im = 0; im < 2; im++) {
#pragma unroll
        for (int in = 0; in < 4; in++) {
            int d = d0 + wn + in * 8 + (lane & 3) * 2;
#pragma unroll
            for (int half = 0; half < 2; half++) {
                int r = r0 + wm + im * 16 + (lane >> 2) + half * 8;
                int nn = r >> 11, pp = r & 2047;
                *(float2*)&out[((size_t)pp * NB + nn) * DIM + d] =
                    make_float2(acc[im][in][half * 2], acc[im][in][half * 2 + 1]);
            }
        }
    }
}

// ===================== Flash attention on HMMA =============================
// All operands pre-converted to fp16 by proj: staging = pure uint4 copies.
#define QP 136
#define KP 72
#define VP 36

__global__ __launch_bounds__(128, 2)
void attn_mma() {
    const int p0 = blockIdx.x * 128;
    const int h  = blockIdx.y;
    const int n  = blockIdx.z;

    const uint32_t* __restrict__ qh = g_qh + ((size_t)n * 64 + h * 16) * SK;
    const uint32_t* __restrict__ ql = g_ql + ((size_t)n * 64 + h * 16) * SK;
    const uint32_t* __restrict__ kp = g_kk + ((size_t)n * 64 + h * 16) * SK;
    const uint32_t* __restrict__ vp = g_vv + ((size_t)n * 128 + h * 32) * (SK / 2);

    __shared__ uint32_t qsh[16 * QP], qsl[16 * QP];
    __shared__ uint32_t ksh[16 * KP];
    __shared__ uint32_t vsh[32 * VP];

    const int tid  = threadIdx.x;
    const int lane = tid & 31;
    const int w    = tid >> 5;

    // ---- stage Q (pure copy) ----
#pragma unroll
    for (int t4 = 0; t4 < 4; t4++) {
        int idx = tid + t4 * 128;           // 0..511 uint4 tasks
        int cp = idx >> 5, q4 = (idx & 31) * 4;
        *(uint4*)&qsh[cp * QP + q4] = *(const uint4*)&qh[(size_t)cp * SK + p0 + q4];
        *(uint4*)&qsl[cp * QP + q4] = *(const uint4*)&ql[(size_t)cp * SK + p0 + q4];
    }
    __syncthreads();

    uint32_t qfh[2][2][4], qfl[2][2][4];
#pragma unroll
    for (int im = 0; im < 2; im++) {
#pragma unroll
        for (int ks = 0; ks < 2; ks++) {
            int row = w * 32 + im * 16 + (lane >> 2);
            int cp = (lane & 3) + ks * 8;
            qfh[im][ks][0] = qsh[cp * QP + row];
            qfh[im][ks][1] = qsh[cp * QP + row + 8];
            qfh[im][ks][2] = qsh[(cp + 4) * QP + row];
            qfh[im][ks][3] = qsh[(cp + 4) * QP + row + 8];
            qfl[im][ks][0] = qsl[cp * QP + row];
            qfl[im][ks][1] = qsl[cp * QP + row + 8];
            qfl[im][ks][2] = qsl[(cp + 4) * QP + row];
            qfl[im][ks][3] = qsl[(cp + 4) * QP + row + 8];
        }
    }

    float oacc[2][4][4];
#pragma unroll
    for (int im = 0; im < 2; im++)
#pragma unroll
        for (int nt = 0; nt < 4; nt++)
#pragma unroll
            for (int t = 0; t < 4; t++) oacc[im][nt][t] = 0.f;
    float rowm[2][2] = {{-1e30f, -1e30f}, {-1e30f, -1e30f}};
    float rowl[2][2] = {{0.f, 0.f}, {0.f, 0.f}};

    const float SC2 = 0.17677669529663687f * 1.4426950408889634f;

    for (int k0 = 0; k0 < SK; k0 += 64) {
        // ---- stage K/V (pure copies) ----
#pragma unroll
        for (int t2 = 0; t2 < 2; t2++) {
            int idx = tid + t2 * 128;       // 0..255
            int cp = idx >> 4, k4 = (idx & 15) * 4;
            *(uint4*)&ksh[cp * KP + k4] = *(const uint4*)&kp[(size_t)cp * SK + k0 + k4];
            int c = idx >> 3, p4 = (idx & 7) * 4;
            *(uint4*)&vsh[c * VP + p4] = *(const uint4*)&vp[(size_t)c * (SK / 2) + (k0 >> 1) + p4];
        }
        __syncthreads();

        // ---- S = Q K^T ----
        float sacc[2][8][4];
#pragma unroll
        for (int im = 0; im < 2; im++)
#pragma unroll
            for (int in = 0; in < 8; in++)
#pragma unroll
                for (int t = 0; t < 4; t++) sacc[im][in][t] = 0.f;

#pragma unroll
        for (int ks = 0; ks < 2; ks++) {
            uint32_t bh[8][2];
#pragma unroll
            for (int in = 0; in < 8; in++) {
                int cp = (lane & 3) + ks * 8;
                int ky = in * 8 + (lane >> 2);
                bh[in][0] = ksh[cp * KP + ky];
                bh[in][1] = ksh[(cp + 4) * KP + ky];
            }
#pragma unroll
            for (int im = 0; im < 2; im++)
#pragma unroll
                for (int in = 0; in < 8; in++) {
                    mma_f16(sacc[im][in], qfh[im][ks], bh[in][0], bh[in][1]);
                    mma_f16(sacc[im][in], qfl[im][ks], bh[in][0], bh[in][1]);
                }
        }

        // ---- online softmax ----
#pragma unroll
        for (int im = 0; im < 2; im++) {
#pragma unroll
            for (int rs = 0; rs < 2; rs++) {
                float mx = rowm[im][rs];
#pragma unroll
                for (int in = 0; in < 8; in++)
                    mx = fmaxf(mx, fmaxf(sacc[im][in][rs * 2], sacc[im][in][rs * 2 + 1]));
                mx = fmaxf(mx, __shfl_xor_sync(0xffffffffu, mx, 1));
                mx = fmaxf(mx, __shfl_xor_sync(0xffffffffu, mx, 2));
                float corr = ex2f((rowm[im][rs] - mx) * SC2);
                rowm[im][rs] = mx;
                float sum = 0.f;
#pragma unroll
                for (int in = 0; in < 8; in++) {
                    float e0 = ex2f((sacc[im][in][rs * 2] - mx) * SC2);
                    float e1 = ex2f((sacc[im][in][rs * 2 + 1] - mx) * SC2);
                    sacc[im][in][rs * 2] = e0;
                    sacc[im][in][rs * 2 + 1] = e1;
                    sum += e0 + e1;
                }
                rowl[im][rs] = rowl[im][rs] * corr + sum;
#pragma unroll
                for (int nt = 0; nt < 4; nt++) {
                    oacc[im][nt][rs * 2] *= corr;
                    oacc[im][nt][rs * 2 + 1] *= corr;
                }
            }
        }

        // ---- O += P V^T ----
#pragma unroll
        for (int ks4 = 0; ks4 < 4; ks4++) {
            uint32_t pfh[2][4], pfl[2][4];
#pragma unroll
            for (int im = 0; im < 2; im++) {
                const float* t0 = sacc[im][2 * ks4];
                const float* t1 = sacc[im][2 * ks4 + 1];
                split2(t0[0], t0[1], pfh[im][0], pfl[im][0]);
                split2(t0[2], t0[3], pfh[im][1], pfl[im][1]);
                split2(t1[0], t1[1], pfh[im][2], pfl[im][2]);
                split2(t1[2], t1[3], pfh[im][3], pfl[im][3]);
            }
            uint32_t bh[4][2];
#pragma unroll
            for (int nt = 0; nt < 4; nt++) {
                int c  = nt * 8 + (lane >> 2);
                int kq = (lane & 3) + ks4 * 8;
                bh[nt][0] = vsh[c * VP + kq];
                bh[nt][1] = vsh[c * VP + kq + 4];
            }
#pragma unroll
            for (int im = 0; im < 2; im++)
#pragma unroll
                for (int nt = 0; nt < 4; nt++) {
                    mma_f16(oacc[im][nt], pfh[im], bh[nt][0], bh[nt][1]);
                    mma_f16(oacc[im][nt], pfl[im], bh[nt][0], bh[nt][1]);
                }
        }
        __syncthreads();
    }

#pragma unroll
    for (int im = 0; im < 2; im++) {
#pragma unroll
        for (int rs = 0; rs < 2; rs++) {
            float l = rowl[im][rs];
            l += __shfl_xor_sync(0xffffffffu, l, 1);
            l += __shfl_xor_sync(0xffffffffu, l, 2);
            float inv = 1.f / l;
#pragma unroll
            for (int nt = 0; nt < 4; nt++) {
                oacc[im][nt][rs * 2] *= inv;
                oacc[im][nt][rs * 2 + 1] *= inv;
            }
        }
    }
    float* __restrict__ xout = g_x + (size_t)n * SQ * INNER + h * HD;
#pragma unroll
    for (int im = 0; im < 2; im++) {
#pragma unroll
        for (int nt = 0; nt < 4; nt++) {
            int row = p0 + w * 32 + im * 16 + (lane >> 2);
            int col = nt * 8 + (lane & 3) * 2;
            *(float2*)&xout[(size_t)row * INNER + col] =
                make_float2(oacc[im][nt][0], oacc[im][nt][1]);
            *(float2*)&xout[(size_t)(row + 8) * INNER + col] =
                make_float2(oacc[im][nt][2], oacc[im][nt][3]);
        }
    }
}

// ---------------------------------------------------------------------------
extern "C" void kernel_launch(void* const* d_in, const int* in_sizes, int n_in,
                              void* d_out, int out_size) {
    const float* query    = (const float*)d_in[0];
    const float* key_feat = (const float*)d_in[1];
    const float* Wq       = (const float*)d_in[2];
    const float* Wk       = (const float*)d_in[3];
    const float* Wv       = (const float*)d_in[4];
    const float* Wup      = (const float*)d_in[5];
    float* out            = (float*)d_out;

    dim3 g1(SK / 128, NB, 2);
    proj_qk<<<g1, 512>>>(query, key_feat, Wq, Wk);

    dim3 g1v(SK / 128, NB, 1);
    proj_v<<<g1v, 512>>>(key_feat, Wv);

    dim3 g2(SQ / 128, NH, NB);
    attn_mma<<<g2, 128>>>();

    dim3 g3(DIM / 128, (NB * SQ) / 128);
    up_mma<<<g3, 512>>>(Wup, out);
}

// round 11
// speedup vs baseline: 1.4281x; 1.1110x over previous
#include <cuda_runtime.h>
#include <cuda_fp16.h>
#include <cstdint>

#define SQ 2048
#define SK 2048
#define NB 8
#define DIM 1024
#define INNER 128
#define NH 4
#define HD 32

// Scratch (allocation-free): packed-fp16 projections + fp32 attention output
__device__ uint32_t g_qh[(size_t)NB * 64 * SK];        // q hi  [n][cpair][s]
__device__ uint32_t g_ql[(size_t)NB * 64 * SK];        // q lo
__device__ uint32_t g_kk[(size_t)NB * 64 * SK];        // k     [n][cpair][s]
__device__ uint32_t g_vv[(size_t)NB * 128 * (SK / 2)]; // v     [n][c][spair]
__device__ float    g_x[(size_t)NB * SQ * INNER];      // [n][p][e]

// ============================ warp-MMA helpers =============================
__device__ __forceinline__ uint32_t smem_u32(const void* p) {
    return (uint32_t)__cvta_generic_to_shared(p);
}
__device__ __forceinline__ void ldsm_x4(uint32_t& r0, uint32_t& r1,
                                        uint32_t& r2, uint32_t& r3, uint32_t addr) {
    asm volatile("ldmatrix.sync.aligned.m8n8.x4.shared.b16 {%0,%1,%2,%3}, [%4];"
                 : "=r"(r0), "=r"(r1), "=r"(r2), "=r"(r3) : "r"(addr));
}
__device__ __forceinline__ void mma_f16(float* d, const uint32_t* a,
                                        uint32_t b0, uint32_t b1) {
    asm volatile(
        "mma.sync.aligned.m16n8k16.row.col.f32.f16.f16.f32 "
        "{%0,%1,%2,%3}, {%4,%5,%6,%7}, {%8,%9}, {%0,%1,%2,%3};"
        : "+f"(d[0]), "+f"(d[1]), "+f"(d[2]), "+f"(d[3])
        : "r"(a[0]), "r"(a[1]), "r"(a[2]), "r"(a[3]), "r"(b0), "r"(b1));
}
__device__ __forceinline__ float ex2f(float x) {
    float y;
    asm("ex2.approx.f32 %0, %1;" : "=f"(y) : "f"(x));
    return y;
}

__device__ __forceinline__ void split2(float x, float y, uint32_t& hi, uint32_t& lo) {
    __half hx = __float2half_rn(x);
    __half hy = __float2half_rn(y);
    __half lx = __float2half_rn(x - __half2float(hx));
    __half ly = __float2half_rn(y - __half2float(hy));
    hi = (uint32_t)__half_as_ushort(hx) | ((uint32_t)__half_as_ushort(hy) << 16);
    lo = (uint32_t)__half_as_ushort(lx) | ((uint32_t)__half_as_ushort(ly) << 16);
}
__device__ __forceinline__ uint32_t pack1(float x, float y) {
    return (uint32_t)__half_as_ushort(__float2half_rn(x))
         | ((uint32_t)__half_as_ushort(__float2half_rn(y)) << 16);
}

// ===================== GEMM template (512 threads, 16 warps) ===============
#define ROWB   80
#define TILE   (128 * ROWB)
#define SM_AH  0
#define SM_AL  TILE
#define SM_BH  (2 * TILE)
#define SM_BL  (3 * TILE)

template <int TERMS>
__device__ __forceinline__ void cvt_store2(const float4* va, const float4* vb,
                                           char* buf, int rbase, int seg) {
#pragma unroll
    for (int p = 0; p < 2; p++) {
        int off = (rbase + 64 * p) * ROWB + seg * 8;
        uint2 h, l;
        split2(va[p].x, va[p].y, h.x, l.x);
        split2(va[p].z, va[p].w, h.y, l.y);
        *(uint2*)(buf + SM_AH + off) = h;
        *(uint2*)(buf + SM_AL + off) = l;
        if (TERMS == 3) {
            split2(vb[p].x, vb[p].y, h.x, l.x);
            split2(vb[p].z, vb[p].w, h.y, l.y);
            *(uint2*)(buf + SM_BH + off) = h;
            *(uint2*)(buf + SM_BL + off) = l;
        } else {
            h.x = pack1(vb[p].x, vb[p].y);
            h.y = pack1(vb[p].z, vb[p].w);
            *(uint2*)(buf + SM_BH + off) = h;
        }
    }
}

template <int KCHUNKS, int TERMS>
__device__ __forceinline__ void mma_gemm(const float* __restrict__ A, size_t lda,
                                         const float* __restrict__ B, size_t ldb,
                                         float acc[2][4][4], char* sm) {
    const int tid  = threadIdx.x;
    const int lane = tid & 31;
    const int wid  = tid >> 5;
    const int wm   = (wid >> 2) * 32;
    const int wn   = (wid & 3) * 32;
    const int seg  = tid & 7;
    const int rbase = tid >> 3;
    const uint32_t smb = smem_u32(sm);

    float4 va[2], vb[2];
#pragma unroll
    for (int p = 0; p < 2; p++) {
        va[p] = *(const float4*)(A + (size_t)(rbase + 64 * p) * lda + seg * 4);
        vb[p] = *(const float4*)(B + (size_t)(rbase + 64 * p) * ldb + seg * 4);
    }

    for (int c = 0; c < KCHUNKS; c++) {
        cvt_store2<TERMS>(va, vb, sm, rbase, seg);
        __syncthreads();

        if (c + 1 < KCHUNKS) {
            int co = (c + 1) * 32;
#pragma unroll
            for (int p = 0; p < 2; p++) {
                va[p] = *(const float4*)(A + (size_t)(rbase + 64 * p) * lda + co + seg * 4);
                vb[p] = *(const float4*)(B + (size_t)(rbase + 64 * p) * ldb + co + seg * 4);
            }
        }

#pragma unroll
        for (int ks = 0; ks < 2; ks++) {
            const int kb = ks * 32;
            uint32_t ah[2][4], al[2][4];
#pragma unroll
            for (int im = 0; im < 2; im++) {
                uint32_t ra = smb + (wm + im * 16 + (lane & 15)) * ROWB + (lane >> 4) * 16 + kb;
                ldsm_x4(ah[im][0], ah[im][1], ah[im][2], ah[im][3], ra + SM_AH);
                ldsm_x4(al[im][0], al[im][1], al[im][2], al[im][3], ra + SM_AL);
            }
            uint32_t bh[2][4], bl[2][4];
#pragma unroll
            for (int i2 = 0; i2 < 2; i2++) {
                uint32_t rb = smb + (wn + i2 * 16 + (lane & 15)) * ROWB + (lane >> 4) * 16 + kb;
                ldsm_x4(bh[i2][0], bh[i2][1], bh[i2][2], bh[i2][3], rb + SM_BH);
                if (TERMS == 3)
                    ldsm_x4(bl[i2][0], bl[i2][1], bl[i2][2], bl[i2][3], rb + SM_BL);
            }
#pragma unroll
            for (int im = 0; im < 2; im++) {
#pragma unroll
                for (int in = 0; in < 4; in++) {
                    int i2 = in >> 1, sub = in & 1;
                    mma_f16(acc[im][in], ah[im], bh[i2][sub], bh[i2][sub + 2]);
                    if (TERMS == 3)
                        mma_f16(acc[im][in], ah[im], bl[i2][sub], bl[i2][sub + 2]);
                    mma_f16(acc[im][in], al[im], bh[i2][sub], bh[i2][sub + 2]);
                }
            }
        }
        __syncthreads();
    }
}

// Merged projection: sel 0 = q (3-term), 1 = k (3-term), 2 = v (2-term).
__global__ __launch_bounds__(512, 1)
void proj_all(const float* __restrict__ query, const float* __restrict__ key_feat,
              const float* __restrict__ Wq, const float* __restrict__ Wk,
              const float* __restrict__ Wv) {
    __shared__ __align__(16) char sm[4 * TILE];
    const int s0  = blockIdx.x * 128;
    const int n   = blockIdx.y;
    const int sel = blockIdx.z;

    const int lane = threadIdx.x & 31, wid = threadIdx.x >> 5;
    const int wm = (wid >> 2) * 32, wn = (wid & 3) * 32;

    float acc[2][4][4];
#pragma unroll
    for (int i = 0; i < 2; i++)
#pragma unroll
        for (int j = 0; j < 4; j++)
#pragma unroll
            for (int t = 0; t < 4; t++) acc[i][j][t] = 0.f;

    if (sel == 2) {
        // ---- v: 2-term, pack fp16 pairs along s ----
        mma_gemm<32, 2>(Wv, DIM, key_feat + (size_t)s0 * (NB * DIM) + (size_t)n * DIM,
                        (size_t)NB * DIM, acc, sm);
#pragma unroll
        for (int im = 0; im < 2; im++) {
#pragma unroll
            for (int in = 0; in < 4; in++) {
#pragma unroll
                for (int half = 0; half < 2; half++) {
                    int row = wm + im * 16 + (lane >> 2) + half * 8;
                    int s = s0 + wn + in * 8 + (lane & 3) * 2;
                    g_vv[((size_t)n * 128 + row) * (SK / 2) + (s >> 1)] =
                        pack1(acc[im][in][2 * half], acc[im][in][2 * half + 1]);
                }
            }
        }
    } else {
        // ---- q / k: 3-term, packed-fp16 pair layout ----
        const float* __restrict__ X = (sel == 0) ? query : key_feat;
        const float* __restrict__ W = (sel == 0) ? Wq : Wk;
        mma_gemm<32, 3>(W, DIM, X + (size_t)s0 * (NB * DIM) + (size_t)n * DIM,
                        (size_t)NB * DIM, acc, sm);

        const bool even = ((lane >> 2) & 1) == 0;
#pragma unroll
        for (int im = 0; im < 2; im++) {
#pragma unroll
            for (int in = 0; in < 4; in++) {
#pragma unroll
                for (int half = 0; half < 2; half++) {
                    int row = wm + im * 16 + (lane >> 2) + half * 8;
                    int s = s0 + wn + in * 8 + (lane & 3) * 2;
                    int cp = row >> 1;
                    size_t base = ((size_t)n * 64 + cp) * SK + s;
                    if (sel == 0) {
                        uint32_t hi, lo;
                        split2(acc[im][in][2 * half], acc[im][in][2 * half + 1], hi, lo);
                        uint32_t hp = __shfl_xor_sync(0xffffffffu, hi, 4);
                        uint32_t lp = __shfl_xor_sync(0xffffffffu, lo, 4);
                        if (even) {
                            uint2 o;
                            o.x = (hi & 0xFFFFu) | (hp << 16);
                            o.y = (hi >> 16) | (hp & 0xFFFF0000u);
                            *(uint2*)&g_qh[base] = o;
                        } else {
                            uint2 o;
                            o.x = (lp & 0xFFFFu) | (lo << 16);
                            o.y = (lp >> 16) | (lo & 0xFFFF0000u);
                            *(uint2*)&g_ql[base] = o;
                        }
                    } else {
                        uint32_t w = pack1(acc[im][in][2 * half], acc[im][in][2 * half + 1]);
                        uint32_t wp = __shfl_xor_sync(0xffffffffu, w, 4);
                        if (even) {
                            uint2 o;
                            o.x = (w & 0xFFFFu) | (wp << 16);
                            o.y = (w >> 16) | (wp & 0xFFFF0000u);
                            *(uint2*)&g_kk[base] = o;
                        }
                    }
                }
            }
        }
    }
}

__global__ __launch_bounds__(512, 1)
void up_mma(const float* __restrict__ Wup, float* __restrict__ out) {
    __shared__ __align__(16) char sm[3 * TILE];
    const int d0 = blockIdx.x * 128;
    const int r0 = blockIdx.y * 128;

    float acc[2][4][4];
#pragma unroll
    for (int i = 0; i < 2; i++)
#pragma unroll
        for (int j = 0; j < 4; j++)
#pragma unroll
            for (int t = 0; t < 4; t++) acc[i][j][t] = 0.f;

    mma_gemm<4, 2>(g_x + (size_t)r0 * INNER, INNER, Wup + (size_t)d0 * INNER, INNER, acc, sm);

    const int lane = threadIdx.x & 31, wid = threadIdx.x >> 5;
    const int wm = (wid >> 2) * 32, wn = (wid & 3) * 32;
#pragma unroll
    for (int im = 0; im < 2; im++) {
#pragma unroll
        for (int in = 0; in < 4; in++) {
            int d = d0 + wn + in * 8 + (lane & 3) * 2;
#pragma unroll
            for (int half = 0; half < 2; half++) {
                int r = r0 + wm + im * 16 + (lane >> 2) + half * 8;
                int nn = r >> 11, pp = r & 2047;
                *(float2*)&out[((size_t)pp * NB + nn) * DIM + d] =
                    make_float2(acc[im][in][half * 2], acc[im][in][half * 2 + 1]);
            }
        }
    }
}

// ===================== Flash attention on HMMA =============================
// Q split (hi/lo), K single, P single, V single.
#define QP 136
#define KP 72
#define VP 36

__global__ __launch_bounds__(128, 2)
void attn_mma() {
    const int p0 = blockIdx.x * 128;
    const int h  = blockIdx.y;
    const int n  = blockIdx.z;

    const uint32_t* __restrict__ qh = g_qh + ((size_t)n * 64 + h * 16) * SK;
    const uint32_t* __restrict__ ql = g_ql + ((size_t)n * 64 + h * 16) * SK;
    const uint32_t* __restrict__ kp = g_kk + ((size_t)n * 64 + h * 16) * SK;
    const uint32_t* __restrict__ vp = g_vv + ((size_t)n * 128 + h * 32) * (SK / 2);

    __shared__ uint32_t qsh[16 * QP], qsl[16 * QP];
    __shared__ uint32_t ksh[16 * KP];
    __shared__ uint32_t vsh[32 * VP];

    const int tid  = threadIdx.x;
    const int lane = tid & 31;
    const int w    = tid >> 5;

    // ---- stage Q (pure copy) ----
#pragma unroll
    for (int t4 = 0; t4 < 4; t4++) {
        int idx = tid + t4 * 128;
        int cp = idx >> 5, q4 = (idx & 31) * 4;
        *(uint4*)&qsh[cp * QP + q4] = *(const uint4*)&qh[(size_t)cp * SK + p0 + q4];
        *(uint4*)&qsl[cp * QP + q4] = *(const uint4*)&ql[(size_t)cp * SK + p0 + q4];
    }
    __syncthreads();

    uint32_t qfh[2][2][4], qfl[2][2][4];
#pragma unroll
    for (int im = 0; im < 2; im++) {
#pragma unroll
        for (int ks = 0; ks < 2; ks++) {
            int row = w * 32 + im * 16 + (lane >> 2);
            int cp = (lane & 3) + ks * 8;
            qfh[im][ks][0] = qsh[cp * QP + row];
            qfh[im][ks][1] = qsh[cp * QP + row + 8];
            qfh[im][ks][2] = qsh[(cp + 4) * QP + row];
            qfh[im][ks][3] = qsh[(cp + 4) * QP + row + 8];
            qfl[im][ks][0] = qsl[cp * QP + row];
            qfl[im][ks][1] = qsl[cp * QP + row + 8];
            qfl[im][ks][2] = qsl[(cp + 4) * QP + row];
            qfl[im][ks][3] = qsl[(cp + 4) * QP + row + 8];
        }
    }

    float oacc[2][4][4];
#pragma unroll
    for (int im = 0; im < 2; im++)
#pragma unroll
        for (int nt = 0; nt < 4; nt++)
#pragma unroll
            for (int t = 0; t < 4; t++) oacc[im][nt][t] = 0.f;
    float rowm[2][2] = {{-1e30f, -1e30f}, {-1e30f, -1e30f}};
    float rowl[2][2] = {{0.f, 0.f}, {0.f, 0.f}};

    const float SC2 = 0.17677669529663687f * 1.4426950408889634f;

    for (int k0 = 0; k0 < SK; k0 += 64) {
        // ---- stage K/V (pure copies) ----
#pragma unroll
        for (int t2 = 0; t2 < 2; t2++) {
            int idx = tid + t2 * 128;
            int cp = idx >> 4, k4 = (idx & 15) * 4;
            *(uint4*)&ksh[cp * KP + k4] = *(const uint4*)&kp[(size_t)cp * SK + k0 + k4];
            int c = idx >> 3, p4 = (idx & 7) * 4;
            *(uint4*)&vsh[c * VP + p4] = *(const uint4*)&vp[(size_t)c * (SK / 2) + (k0 >> 1) + p4];
        }
        __syncthreads();

        // ---- S = Q K^T (Qh + Ql terms) ----
        float sacc[2][8][4];
#pragma unroll
        for (int im = 0; im < 2; im++)
#pragma unroll
            for (int in = 0; in < 8; in++)
#pragma unroll
                for (int t = 0; t < 4; t++) sacc[im][in][t] = 0.f;

#pragma unroll
        for (int ks = 0; ks < 2; ks++) {
            uint32_t bh[8][2];
#pragma unroll
            for (int in = 0; in < 8; in++) {
                int cp = (lane & 3) + ks * 8;
                int ky = in * 8 + (lane >> 2);
                bh[in][0] = ksh[cp * KP + ky];
                bh[in][1] = ksh[(cp + 4) * KP + ky];
            }
#pragma unroll
            for (int im = 0; im < 2; im++)
#pragma unroll
                for (int in = 0; in < 8; in++) {
                    mma_f16(sacc[im][in], qfh[im][ks], bh[in][0], bh[in][1]);
                    mma_f16(sacc[im][in], qfl[im][ks], bh[in][0], bh[in][1]);
                }
        }

        // ---- online softmax ----
#pragma unroll
        for (int im = 0; im < 2; im++) {
#pragma unroll
            for (int rs = 0; rs < 2; rs++) {
                float mx = rowm[im][rs];
#pragma unroll
                for (int in = 0; in < 8; in++)
                    mx = fmaxf(mx, fmaxf(sacc[im][in][rs * 2], sacc[im][in][rs * 2 + 1]));
                mx = fmaxf(mx, __shfl_xor_sync(0xffffffffu, mx, 1));
                mx = fmaxf(mx, __shfl_xor_sync(0xffffffffu, mx, 2));
                float corr = ex2f((rowm[im][rs] - mx) * SC2);
                rowm[im][rs] = mx;
                float sum = 0.f;
#pragma unroll
                for (int in = 0; in < 8; in++) {
                    float e0 = ex2f((sacc[im][in][rs * 2] - mx) * SC2);
                    float e1 = ex2f((sacc[im][in][rs * 2 + 1] - mx) * SC2);
                    sacc[im][in][rs * 2] = e0;
                    sacc[im][in][rs * 2 + 1] = e1;
                    sum += e0 + e1;
                }
                rowl[im][rs] = rowl[im][rs] * corr + sum;
#pragma unroll
                for (int nt = 0; nt < 4; nt++) {
                    oacc[im][nt][rs * 2] *= corr;
                    oacc[im][nt][rs * 2 + 1] *= corr;
                }
            }
        }

        // ---- O += P V^T (single-rounded P: one MMA per fragment) ----
#pragma unroll
        for (int ks4 = 0; ks4 < 4; ks4++) {
            uint32_t pf[2][4];
#pragma unroll
            for (int im = 0; im < 2; im++) {
                const float* t0 = sacc[im][2 * ks4];
                const float* t1 = sacc[im][2 * ks4 + 1];
                pf[im][0] = pack1(t0[0], t0[1]);
                pf[im][1] = pack1(t0[2], t0[3]);
                pf[im][2] = pack1(t1[0], t1[1]);
                pf[im][3] = pack1(t1[2], t1[3]);
            }
            uint32_t bh[4][2];
#pragma unroll
            for (int nt = 0; nt < 4; nt++) {
                int c  = nt * 8 + (lane >> 2);
                int kq = (lane & 3) + ks4 * 8;
                bh[nt][0] = vsh[c * VP + kq];
                bh[nt][1] = vsh[c * VP + kq + 4];
            }
#pragma unroll
            for (int im = 0; im < 2; im++)
#pragma unroll
                for (int nt = 0; nt < 4; nt++)
                    mma_f16(oacc[im][nt], pf[im], bh[nt][0], bh[nt][1]);
        }
        __syncthreads();
    }

#pragma unroll
    for (int im = 0; im < 2; im++) {
#pragma unroll
        for (int rs = 0; rs < 2; rs++) {
            float l = rowl[im][rs];
            l += __shfl_xor_sync(0xffffffffu, l, 1);
            l += __shfl_xor_sync(0xffffffffu, l, 2);
            float inv = 1.f / l;
#pragma unroll
            for (int nt = 0; nt < 4; nt++) {
                oacc[im][nt][rs * 2] *= inv;
                oacc[im][nt][rs * 2 + 1] *= inv;
            }
        }
    }
    float* __restrict__ xout = g_x + (size_t)n * SQ * INNER + h * HD;
#pragma unroll
    for (int im = 0; im < 2; im++) {
#pragma unroll
        for (int nt = 0; nt < 4; nt++) {
            int row = p0 + w * 32 + im * 16 + (lane >> 2);
            int col = nt * 8 + (lane & 3) * 2;
            *(float2*)&xout[(size_t)row * INNER + col] =
                make_float2(oacc[im][nt][0], oacc[im][nt][1]);
            *(float2*)&xout[(size_t)(row + 8) * INNER + col] =
                make_float2(oacc[im][nt][2], oacc[im][nt][3]);
        }
    }
}

// ---------------------------------------------------------------------------
extern "C" void kernel_launch(void* const* d_in, const int* in_sizes, int n_in,
                              void* d_out, int out_size) {
    const float* query    = (const float*)d_in[0];
    const float* key_feat = (const float*)d_in[1];
    const float* Wq       = (const float*)d_in[2];
    const float* Wk       = (const float*)d_in[3];
    const float* Wv       = (const float*)d_in[4];
    const float* Wup      = (const float*)d_in[5];
    float* out            = (float*)d_out;

    dim3 g1(SK / 128, NB, 3);
    proj_all<<<g1, 512>>>(query, key_feat, Wq, Wk, Wv);

    dim3 g2(SQ / 128, NH, NB);
    attn_mma<<<g2, 128>>>();

    dim3 g3(DIM / 128, (NB * SQ) / 128);
    up_mma<<<g3, 512>>>(Wup, out);
}

// round 12
// speedup vs baseline: 1.5385x; 1.0773x over previous
#include <cuda_runtime.h>
#include <cuda_fp16.h>
#include <cstdint>

#define SQ 2048
#define SK 2048
#define NB 8
#define DIM 1024
#define INNER 128
#define NH 4
#define HD 32

// Scratch (allocation-free): packed-fp16 projections + packed-fp16 attn output
__device__ uint32_t g_qh[(size_t)NB * 64 * SK];        // q     [n][cpair][s]
__device__ uint32_t g_kk[(size_t)NB * 64 * SK];        // k     [n][cpair][s]
__device__ uint32_t g_vv[(size_t)NB * 128 * (SK / 2)]; // v     [n][c][spair]
__device__ uint32_t g_x16[(size_t)NB * SQ * 64];       // x     [n*SQ+p][epair]

// ============================ warp-MMA helpers =============================
__device__ __forceinline__ uint32_t smem_u32(const void* p) {
    return (uint32_t)__cvta_generic_to_shared(p);
}
__device__ __forceinline__ void ldsm_x4(uint32_t& r0, uint32_t& r1,
                                        uint32_t& r2, uint32_t& r3, uint32_t addr) {
    asm volatile("ldmatrix.sync.aligned.m8n8.x4.shared.b16 {%0,%1,%2,%3}, [%4];"
                 : "=r"(r0), "=r"(r1), "=r"(r2), "=r"(r3) : "r"(addr));
}
__device__ __forceinline__ void mma_f16(float* d, const uint32_t* a,
                                        uint32_t b0, uint32_t b1) {
    asm volatile(
        "mma.sync.aligned.m16n8k16.row.col.f32.f16.f16.f32 "
        "{%0,%1,%2,%3}, {%4,%5,%6,%7}, {%8,%9}, {%0,%1,%2,%3};"
        : "+f"(d[0]), "+f"(d[1]), "+f"(d[2]), "+f"(d[3])
        : "r"(a[0]), "r"(a[1]), "r"(a[2]), "r"(a[3]), "r"(b0), "r"(b1));
}
__device__ __forceinline__ float ex2f(float x) {
    float y;
    asm("ex2.approx.f32 %0, %1;" : "=f"(y) : "f"(x));
    return y;
}

__device__ __forceinline__ void split2(float x, float y, uint32_t& hi, uint32_t& lo) {
    __half hx = __float2half_rn(x);
    __half hy = __float2half_rn(y);
    __half lx = __float2half_rn(x - __half2float(hx));
    __half ly = __float2half_rn(y - __half2float(hy));
    hi = (uint32_t)__half_as_ushort(hx) | ((uint32_t)__half_as_ushort(hy) << 16);
    lo = (uint32_t)__half_as_ushort(lx) | ((uint32_t)__half_as_ushort(ly) << 16);
}
__device__ __forceinline__ uint32_t pack1(float x, float y) {
    return (uint32_t)__half_as_ushort(__float2half_rn(x))
         | ((uint32_t)__half_as_ushort(__float2half_rn(y)) << 16);
}

// ===================== GEMM template (512 threads, 16 warps) ===============
#define ROWB   80
#define TILE   (128 * ROWB)
#define SM_AH  0
#define SM_AL  TILE
#define SM_BH  (2 * TILE)
#define SM_BL  (3 * TILE)

template <int TERMS>
__device__ __forceinline__ void cvt_store2(const float4* va, const float4* vb,
                                           char* buf, int rbase, int seg) {
#pragma unroll
    for (int p = 0; p < 2; p++) {
        int off = (rbase + 64 * p) * ROWB + seg * 8;
        uint2 h, l;
        split2(va[p].x, va[p].y, h.x, l.x);
        split2(va[p].z, va[p].w, h.y, l.y);
        *(uint2*)(buf + SM_AH + off) = h;
        *(uint2*)(buf + SM_AL + off) = l;
        if (TERMS == 3) {
            split2(vb[p].x, vb[p].y, h.x, l.x);
            split2(vb[p].z, vb[p].w, h.y, l.y);
            *(uint2*)(buf + SM_BH + off) = h;
            *(uint2*)(buf + SM_BL + off) = l;
        } else {
            h.x = pack1(vb[p].x, vb[p].y);
            h.y = pack1(vb[p].z, vb[p].w);
            *(uint2*)(buf + SM_BH + off) = h;
        }
    }
}

template <int KCHUNKS, int TERMS>
__device__ __forceinline__ void mma_gemm(const float* __restrict__ A, size_t lda,
                                         const float* __restrict__ B, size_t ldb,
                                         float acc[2][4][4], char* sm) {
    const int tid  = threadIdx.x;
    const int lane = tid & 31;
    const int wid  = tid >> 5;
    const int wm   = (wid >> 2) * 32;
    const int wn   = (wid & 3) * 32;
    const int seg  = tid & 7;
    const int rbase = tid >> 3;
    const uint32_t smb = smem_u32(sm);

    float4 va[2], vb[2];
#pragma unroll
    for (int p = 0; p < 2; p++) {
        va[p] = *(const float4*)(A + (size_t)(rbase + 64 * p) * lda + seg * 4);
        vb[p] = *(const float4*)(B + (size_t)(rbase + 64 * p) * ldb + seg * 4);
    }

    for (int c = 0; c < KCHUNKS; c++) {
        cvt_store2<TERMS>(va, vb, sm, rbase, seg);
        __syncthreads();

        if (c + 1 < KCHUNKS) {
            int co = (c + 1) * 32;
#pragma unroll
            for (int p = 0; p < 2; p++) {
                va[p] = *(const float4*)(A + (size_t)(rbase + 64 * p) * lda + co + seg * 4);
                vb[p] = *(const float4*)(B + (size_t)(rbase + 64 * p) * ldb + co + seg * 4);
            }
        }

#pragma unroll
        for (int ks = 0; ks < 2; ks++) {
            const int kb = ks * 32;
            uint32_t ah[2][4], al[2][4];
#pragma unroll
            for (int im = 0; im < 2; im++) {
                uint32_t ra = smb + (wm + im * 16 + (lane & 15)) * ROWB + (lane >> 4) * 16 + kb;
                ldsm_x4(ah[im][0], ah[im][1], ah[im][2], ah[im][3], ra + SM_AH);
                ldsm_x4(al[im][0], al[im][1], al[im][2], al[im][3], ra + SM_AL);
            }
            uint32_t bh[2][4], bl[2][4];
#pragma unroll
            for (int i2 = 0; i2 < 2; i2++) {
                uint32_t rb = smb + (wn + i2 * 16 + (lane & 15)) * ROWB + (lane >> 4) * 16 + kb;
                ldsm_x4(bh[i2][0], bh[i2][1], bh[i2][2], bh[i2][3], rb + SM_BH);
                if (TERMS == 3)
                    ldsm_x4(bl[i2][0], bl[i2][1], bl[i2][2], bl[i2][3], rb + SM_BL);
            }
#pragma unroll
            for (int im = 0; im < 2; im++) {
#pragma unroll
                for (int in = 0; in < 4; in++) {
                    int i2 = in >> 1, sub = in & 1;
                    mma_f16(acc[im][in], ah[im], bh[i2][sub], bh[i2][sub + 2]);
                    if (TERMS == 3)
                        mma_f16(acc[im][in], ah[im], bl[i2][sub], bl[i2][sub + 2]);
                    mma_f16(acc[im][in], al[im], bh[i2][sub], bh[i2][sub + 2]);
                }
            }
        }
        __syncthreads();
    }
}

// Merged projection: sel 0 = q (3-term), 1 = k (3-term), 2 = v (2-term).
// q and k both stored single fp16 in [cpair][s] layout; v packed along s.
__global__ __launch_bounds__(512, 1)
void proj_all(const float* __restrict__ query, const float* __restrict__ key_feat,
              const float* __restrict__ Wq, const float* __restrict__ Wk,
              const float* __restrict__ Wv) {
    __shared__ __align__(16) char sm[4 * TILE];
    const int s0  = blockIdx.x * 128;
    const int n   = blockIdx.y;
    const int sel = blockIdx.z;

    const int lane = threadIdx.x & 31, wid = threadIdx.x >> 5;
    const int wm = (wid >> 2) * 32, wn = (wid & 3) * 32;

    float acc[2][4][4];
#pragma unroll
    for (int i = 0; i < 2; i++)
#pragma unroll
        for (int j = 0; j < 4; j++)
#pragma unroll
            for (int t = 0; t < 4; t++) acc[i][j][t] = 0.f;

    if (sel == 2) {
        mma_gemm<32, 2>(Wv, DIM, key_feat + (size_t)s0 * (NB * DIM) + (size_t)n * DIM,
                        (size_t)NB * DIM, acc, sm);
#pragma unroll
        for (int im = 0; im < 2; im++) {
#pragma unroll
            for (int in = 0; in < 4; in++) {
#pragma unroll
                for (int half = 0; half < 2; half++) {
                    int row = wm + im * 16 + (lane >> 2) + half * 8;
                    int s = s0 + wn + in * 8 + (lane & 3) * 2;
                    g_vv[((size_t)n * 128 + row) * (SK / 2) + (s >> 1)] =
                        pack1(acc[im][in][2 * half], acc[im][in][2 * half + 1]);
                }
            }
        }
    } else {
        const float* __restrict__ X = (sel == 0) ? query : key_feat;
        const float* __restrict__ W = (sel == 0) ? Wq : Wk;
        mma_gemm<32, 3>(W, DIM, X + (size_t)s0 * (NB * DIM) + (size_t)n * DIM,
                        (size_t)NB * DIM, acc, sm);

        uint32_t* __restrict__ dst = (sel == 0) ? g_qh : g_kk;
        const bool even = ((lane >> 2) & 1) == 0;
#pragma unroll
        for (int im = 0; im < 2; im++) {
#pragma unroll
            for (int in = 0; in < 4; in++) {
#pragma unroll
                for (int half = 0; half < 2; half++) {
                    int row = wm + im * 16 + (lane >> 2) + half * 8;
                    int s = s0 + wn + in * 8 + (lane & 3) * 2;
                    int cp = row >> 1;
                    size_t base = ((size_t)n * 64 + cp) * SK + s;
                    uint32_t w = pack1(acc[im][in][2 * half], acc[im][in][2 * half + 1]);
                    uint32_t wp = __shfl_xor_sync(0xffffffffu, w, 4);
                    if (even) {
                        uint2 o;
                        o.x = (w & 0xFFFFu) | (wp << 16);
                        o.y = (w >> 16) | (wp & 0xFFFF0000u);
                        *(uint2*)&dst[base] = o;
                    }
                }
            }
        }
    }
}

// up: 1-term fp16 GEMM. A = g_x16 (pre-packed fp16), B = Wup single-rounded.
#define USM_A 0
#define USM_B TILE

__global__ __launch_bounds__(512, 1)
void up_mma(const float* __restrict__ Wup, float* __restrict__ out) {
    __shared__ __align__(16) char sm[2 * TILE];
    const int d0 = blockIdx.x * 128;
    const int r0 = blockIdx.y * 128;

    const int tid  = threadIdx.x;
    const int lane = tid & 31;
    const int wid  = tid >> 5;
    const int wm   = (wid >> 2) * 32;
    const int wn   = (wid & 3) * 32;
    const uint32_t smb = smem_u32(sm);

    float acc[2][4][4];
#pragma unroll
    for (int i = 0; i < 2; i++)
#pragma unroll
        for (int j = 0; j < 4; j++)
#pragma unroll
            for (int t = 0; t < 4; t++) acc[i][j][t] = 0.f;

    const int arow = tid >> 2, aseg = tid & 3;

    for (int c = 0; c < 4; c++) {
        // A: copy packed fp16 x rows (8 halfs per thread)
        *(uint4*)(sm + USM_A + arow * ROWB + aseg * 16) =
            *(const uint4*)&g_x16[(size_t)(r0 + arow) * 64 + c * 16 + aseg * 4];
        // B: convert Wup fp32 -> fp16 (8 floats per thread)
        {
            const float* src = Wup + (size_t)(d0 + arow) * INNER + c * 32 + aseg * 8;
            float4 f0 = *(const float4*)src;
            float4 f1 = *(const float4*)(src + 4);
            uint4 o;
            o.x = pack1(f0.x, f0.y);
            o.y = pack1(f0.z, f0.w);
            o.z = pack1(f1.x, f1.y);
            o.w = pack1(f1.z, f1.w);
            *(uint4*)(sm + USM_B + arow * ROWB + aseg * 16) = o;
        }
        __syncthreads();

#pragma unroll
        for (int ks = 0; ks < 2; ks++) {
            const int kb = ks * 32;
            uint32_t ah[2][4];
#pragma unroll
            for (int im = 0; im < 2; im++) {
                uint32_t ra = smb + USM_A + (wm + im * 16 + (lane & 15)) * ROWB + (lane >> 4) * 16 + kb;
                ldsm_x4(ah[im][0], ah[im][1], ah[im][2], ah[im][3], ra);
            }
            uint32_t bh[2][4];
#pragma unroll
            for (int i2 = 0; i2 < 2; i2++) {
                uint32_t rb = smb + USM_B + (wn + i2 * 16 + (lane & 15)) * ROWB + (lane >> 4) * 16 + kb;
                ldsm_x4(bh[i2][0], bh[i2][1], bh[i2][2], bh[i2][3], rb);
            }
#pragma unroll
            for (int im = 0; im < 2; im++)
#pragma unroll
                for (int in = 0; in < 4; in++) {
                    int i2 = in >> 1, sub = in & 1;
                    mma_f16(acc[im][in], ah[im], bh[i2][sub], bh[i2][sub + 2]);
                }
        }
        __syncthreads();
    }

#pragma unroll
    for (int im = 0; im < 2; im++) {
#pragma unroll
        for (int in = 0; in < 4; in++) {
            int d = d0 + wn + in * 8 + (lane & 3) * 2;
#pragma unroll
            for (int half = 0; half < 2; half++) {
                int r = r0 + wm + im * 16 + (lane >> 2) + half * 8;
                int nn = r >> 11, pp = r & 2047;
                *(float2*)&out[((size_t)pp * NB + nn) * DIM + d] =
                    make_float2(acc[im][in][half * 2], acc[im][in][half * 2 + 1]);
            }
        }
    }
}

// ===================== Flash attention on HMMA =============================
// Q single, K single, P single, V single: 1 MMA per fragment everywhere.
#define QP 136
#define KP 72
#define VP 36

__global__ __launch_bounds__(128, 2)
void attn_mma() {
    const int p0 = blockIdx.x * 128;
    const int h  = blockIdx.y;
    const int n  = blockIdx.z;

    const uint32_t* __restrict__ qh = g_qh + ((size_t)n * 64 + h * 16) * SK;
    const uint32_t* __restrict__ kp = g_kk + ((size_t)n * 64 + h * 16) * SK;
    const uint32_t* __restrict__ vp = g_vv + ((size_t)n * 128 + h * 32) * (SK / 2);

    __shared__ uint32_t qsh[16 * QP];
    __shared__ uint32_t ksh[16 * KP];
    __shared__ uint32_t vsh[32 * VP];

    const int tid  = threadIdx.x;
    const int lane = tid & 31;
    const int w    = tid >> 5;

    // ---- stage Q (pure copy) ----
#pragma unroll
    for (int t4 = 0; t4 < 4; t4++) {
        int idx = tid + t4 * 128;
        int cp = idx >> 5, q4 = (idx & 31) * 4;
        *(uint4*)&qsh[cp * QP + q4] = *(const uint4*)&qh[(size_t)cp * SK + p0 + q4];
    }
    __syncthreads();

    uint32_t qf[2][2][4];
#pragma unroll
    for (int im = 0; im < 2; im++) {
#pragma unroll
        for (int ks = 0; ks < 2; ks++) {
            int row = w * 32 + im * 16 + (lane >> 2);
            int cp = (lane & 3) + ks * 8;
            qf[im][ks][0] = qsh[cp * QP + row];
            qf[im][ks][1] = qsh[cp * QP + row + 8];
            qf[im][ks][2] = qsh[(cp + 4) * QP + row];
            qf[im][ks][3] = qsh[(cp + 4) * QP + row + 8];
        }
    }

    float oacc[2][4][4];
#pragma unroll
    for (int im = 0; im < 2; im++)
#pragma unroll
        for (int nt = 0; nt < 4; nt++)
#pragma unroll
            for (int t = 0; t < 4; t++) oacc[im][nt][t] = 0.f;
    float rowm[2][2] = {{-1e30f, -1e30f}, {-1e30f, -1e30f}};
    float rowl[2][2] = {{0.f, 0.f}, {0.f, 0.f}};

    const float SC2 = 0.17677669529663687f * 1.4426950408889634f;

    for (int k0 = 0; k0 < SK; k0 += 64) {
        // ---- stage K/V (pure copies) ----
#pragma unroll
        for (int t2 = 0; t2 < 2; t2++) {
            int idx = tid + t2 * 128;
            int cp = idx >> 4, k4 = (idx & 15) * 4;
            *(uint4*)&ksh[cp * KP + k4] = *(const uint4*)&kp[(size_t)cp * SK + k0 + k4];
            int c = idx >> 3, p4 = (idx & 7) * 4;
            *(uint4*)&vsh[c * VP + p4] = *(const uint4*)&vp[(size_t)c * (SK / 2) + (k0 >> 1) + p4];
        }
        __syncthreads();

        // ---- S = Q K^T (single term) ----
        float sacc[2][8][4];
#pragma unroll
        for (int im = 0; im < 2; im++)
#pragma unroll
            for (int in = 0; in < 8; in++)
#pragma unroll
                for (int t = 0; t < 4; t++) sacc[im][in][t] = 0.f;

#pragma unroll
        for (int ks = 0; ks < 2; ks++) {
            uint32_t bh[8][2];
#pragma unroll
            for (int in = 0; in < 8; in++) {
                int cp = (lane & 3) + ks * 8;
                int ky = in * 8 + (lane >> 2);
                bh[in][0] = ksh[cp * KP + ky];
                bh[in][1] = ksh[(cp + 4) * KP + ky];
            }
#pragma unroll
            for (int im = 0; im < 2; im++)
#pragma unroll
                for (int in = 0; in < 8; in++)
                    mma_f16(sacc[im][in], qf[im][ks], bh[in][0], bh[in][1]);
        }

        // ---- online softmax ----
#pragma unroll
        for (int im = 0; im < 2; im++) {
#pragma unroll
            for (int rs = 0; rs < 2; rs++) {
                float mx = rowm[im][rs];
#pragma unroll
                for (int in = 0; in < 8; in++)
                    mx = fmaxf(mx, fmaxf(sacc[im][in][rs * 2], sacc[im][in][rs * 2 + 1]));
                mx = fmaxf(mx, __shfl_xor_sync(0xffffffffu, mx, 1));
                mx = fmaxf(mx, __shfl_xor_sync(0xffffffffu, mx, 2));
                float corr = ex2f((rowm[im][rs] - mx) * SC2);
                rowm[im][rs] = mx;
                float sum = 0.f;
#pragma unroll
                for (int in = 0; in < 8; in++) {
                    float e0 = ex2f((sacc[im][in][rs * 2] - mx) * SC2);
                    float e1 = ex2f((sacc[im][in][rs * 2 + 1] - mx) * SC2);
                    sacc[im][in][rs * 2] = e0;
                    sacc[im][in][rs * 2 + 1] = e1;
                    sum += e0 + e1;
                }
                rowl[im][rs] = rowl[im][rs] * corr + sum;
#pragma unroll
                for (int nt = 0; nt < 4; nt++) {
                    oacc[im][nt][rs * 2] *= corr;
                    oacc[im][nt][rs * 2 + 1] *= corr;
                }
            }
        }

        // ---- O += P V^T (single term) ----
#pragma unroll
        for (int ks4 = 0; ks4 < 4; ks4++) {
            uint32_t pf[2][4];
#pragma unroll
            for (int im = 0; im < 2; im++) {
                const float* t0 = sacc[im][2 * ks4];
                const float* t1 = sacc[im][2 * ks4 + 1];
                pf[im][0] = pack1(t0[0], t0[1]);
                pf[im][1] = pack1(t0[2], t0[3]);
                pf[im][2] = pack1(t1[0], t1[1]);
                pf[im][3] = pack1(t1[2], t1[3]);
            }
            uint32_t bh[4][2];
#pragma unroll
            for (int nt = 0; nt < 4; nt++) {
                int c  = nt * 8 + (lane >> 2);
                int kq = (lane & 3) + ks4 * 8;
                bh[nt][0] = vsh[c * VP + kq];
                bh[nt][1] = vsh[c * VP + kq + 4];
            }
#pragma unroll
            for (int im = 0; im < 2; im++)
#pragma unroll
                for (int nt = 0; nt < 4; nt++)
                    mma_f16(oacc[im][nt], pf[im], bh[nt][0], bh[nt][1]);
        }
        __syncthreads();
    }

    // ---- finalize: 1/l, pack fp16, store ----
#pragma unroll
    for (int im = 0; im < 2; im++) {
#pragma unroll
        for (int rs = 0; rs < 2; rs++) {
            float l = rowl[im][rs];
            l += __shfl_xor_sync(0xffffffffu, l, 1);
            l += __shfl_xor_sync(0xffffffffu, l, 2);
            float inv = 1.f / l;
#pragma unroll
            for (int nt = 0; nt < 4; nt++) {
                oacc[im][nt][rs * 2] *= inv;
                oacc[im][nt][rs * 2 + 1] *= inv;
            }
        }
    }
    uint32_t* __restrict__ xout = g_x16 + (size_t)n * SQ * 64 + h * 16;
#pragma unroll
    for (int im = 0; im < 2; im++) {
#pragma unroll
        for (int nt = 0; nt < 4; nt++) {
            int row = p0 + w * 32 + im * 16 + (lane >> 2);
            int wc = nt * 4 + (lane & 3);
            xout[(size_t)row * 64 + wc]       = pack1(oacc[im][nt][0], oacc[im][nt][1]);
            xout[(size_t)(row + 8) * 64 + wc] = pack1(oacc[im][nt][2], oacc[im][nt][3]);
        }
    }
}

// ---------------------------------------------------------------------------
extern "C" void kernel_launch(void* const* d_in, const int* in_sizes, int n_in,
                              void* d_out, int out_size) {
    const float* query    = (const float*)d_in[0];
    const float* key_feat = (const float*)d_in[1];
    const float* Wq       = (const float*)d_in[2];
    const float* Wk       = (const float*)d_in[3];
    const float* Wv       = (const float*)d_in[4];
    const float* Wup      = (const float*)d_in[5];
    float* out            = (float*)d_out;

    dim3 g1(SK / 128, NB, 3);
    proj_all<<<g1, 512>>>(query, key_feat, Wq, Wk, Wv);

    dim3 g2(SQ / 128, NH, NB);
    attn_mma<<<g2, 128>>>();

    dim3 g3(DIM / 128, (NB * SQ) / 128);
    up_mma<<<g3, 512>>>(Wup, out);
}

// round 13
// speedup vs baseline: 1.6636x; 1.0813x over previous
#include <cuda_runtime.h>
#include <cuda_fp16.h>
#include <cstdint>

#define SQ 2048
#define SK 2048
#define NB 8
#define DIM 1024
#define INNER 128
#define NH 4
#define HD 32

// Scratch (allocation-free): packed-fp16 projections + packed-fp16 attn output
__device__ uint32_t g_qh[(size_t)NB * 64 * SK];        // q     [n][cpair][s]
__device__ uint32_t g_kk[(size_t)NB * 64 * SK];        // k     [n][cpair][s]
__device__ uint32_t g_vv[(size_t)NB * 128 * (SK / 2)]; // v     [n][c][spair]
__device__ uint32_t g_x16[(size_t)NB * SQ * 64];       // x     [n*SQ+p][epair]

// ============================ warp-MMA helpers =============================
__device__ __forceinline__ uint32_t smem_u32(const void* p) {
    return (uint32_t)__cvta_generic_to_shared(p);
}
__device__ __forceinline__ void ldsm_x4(uint32_t& r0, uint32_t& r1,
                                        uint32_t& r2, uint32_t& r3, uint32_t addr) {
    asm volatile("ldmatrix.sync.aligned.m8n8.x4.shared.b16 {%0,%1,%2,%3}, [%4];"
                 : "=r"(r0), "=r"(r1), "=r"(r2), "=r"(r3) : "r"(addr));
}
__device__ __forceinline__ void mma_f16(float* d, const uint32_t* a,
                                        uint32_t b0, uint32_t b1) {
    asm volatile(
        "mma.sync.aligned.m16n8k16.row.col.f32.f16.f16.f32 "
        "{%0,%1,%2,%3}, {%4,%5,%6,%7}, {%8,%9}, {%0,%1,%2,%3};"
        : "+f"(d[0]), "+f"(d[1]), "+f"(d[2]), "+f"(d[3])
        : "r"(a[0]), "r"(a[1]), "r"(a[2]), "r"(a[3]), "r"(b0), "r"(b1));
}
__device__ __forceinline__ float ex2f(float x) {
    float y;
    asm("ex2.approx.f32 %0, %1;" : "=f"(y) : "f"(x));
    return y;
}

__device__ __forceinline__ void split2(float x, float y, uint32_t& hi, uint32_t& lo) {
    __half hx = __float2half_rn(x);
    __half hy = __float2half_rn(y);
    __half lx = __float2half_rn(x - __half2float(hx));
    __half ly = __float2half_rn(y - __half2float(hy));
    hi = (uint32_t)__half_as_ushort(hx) | ((uint32_t)__half_as_ushort(hy) << 16);
    lo = (uint32_t)__half_as_ushort(lx) | ((uint32_t)__half_as_ushort(ly) << 16);
}
__device__ __forceinline__ uint32_t pack1(float x, float y) {
    return (uint32_t)__half_as_ushort(__float2half_rn(x))
         | ((uint32_t)__half_as_ushort(__float2half_rn(y)) << 16);
}

// ===================== GEMM template (512 threads, 16 warps) ===============
#define ROWB   80
#define TILE   (128 * ROWB)
#define SM_AH  0
#define SM_AL  TILE
#define SM_BH  (2 * TILE)
#define SM_BL  (3 * TILE)

template <int TERMS>
__device__ __forceinline__ void cvt_store2(const float4* va, const float4* vb,
                                           char* buf, int rbase, int seg) {
#pragma unroll
    for (int p = 0; p < 2; p++) {
        int off = (rbase + 64 * p) * ROWB + seg * 8;
        uint2 h, l;
        split2(va[p].x, va[p].y, h.x, l.x);
        split2(va[p].z, va[p].w, h.y, l.y);
        *(uint2*)(buf + SM_AH + off) = h;
        *(uint2*)(buf + SM_AL + off) = l;
        if (TERMS == 3) {
            split2(vb[p].x, vb[p].y, h.x, l.x);
            split2(vb[p].z, vb[p].w, h.y, l.y);
            *(uint2*)(buf + SM_BH + off) = h;
            *(uint2*)(buf + SM_BL + off) = l;
        } else {
            h.x = pack1(vb[p].x, vb[p].y);
            h.y = pack1(vb[p].z, vb[p].w);
            *(uint2*)(buf + SM_BH + off) = h;
        }
    }
}

template <int KCHUNKS, int TERMS>
__device__ __forceinline__ void mma_gemm(const float* __restrict__ A, size_t lda,
                                         const float* __restrict__ B, size_t ldb,
                                         float acc[2][4][4], char* sm) {
    const int tid  = threadIdx.x;
    const int lane = tid & 31;
    const int wid  = tid >> 5;
    const int wm   = (wid >> 2) * 32;
    const int wn   = (wid & 3) * 32;
    const int seg  = tid & 7;
    const int rbase = tid >> 3;
    const uint32_t smb = smem_u32(sm);

    float4 va[2], vb[2];
#pragma unroll
    for (int p = 0; p < 2; p++) {
        va[p] = *(const float4*)(A + (size_t)(rbase + 64 * p) * lda + seg * 4);
        vb[p] = *(const float4*)(B + (size_t)(rbase + 64 * p) * ldb + seg * 4);
    }

    for (int c = 0; c < KCHUNKS; c++) {
        cvt_store2<TERMS>(va, vb, sm, rbase, seg);
        __syncthreads();

        if (c + 1 < KCHUNKS) {
            int co = (c + 1) * 32;
#pragma unroll
            for (int p = 0; p < 2; p++) {
                va[p] = *(const float4*)(A + (size_t)(rbase + 64 * p) * lda + co + seg * 4);
                vb[p] = *(const float4*)(B + (size_t)(rbase + 64 * p) * ldb + co + seg * 4);
            }
        }

#pragma unroll
        for (int ks = 0; ks < 2; ks++) {
            const int kb = ks * 32;
            uint32_t ah[2][4], al[2][4];
#pragma unroll
            for (int im = 0; im < 2; im++) {
                uint32_t ra = smb + (wm + im * 16 + (lane & 15)) * ROWB + (lane >> 4) * 16 + kb;
                ldsm_x4(ah[im][0], ah[im][1], ah[im][2], ah[im][3], ra + SM_AH);
                ldsm_x4(al[im][0], al[im][1], al[im][2], al[im][3], ra + SM_AL);
            }
            uint32_t bh[2][4], bl[2][4];
#pragma unroll
            for (int i2 = 0; i2 < 2; i2++) {
                uint32_t rb = smb + (wn + i2 * 16 + (lane & 15)) * ROWB + (lane >> 4) * 16 + kb;
                ldsm_x4(bh[i2][0], bh[i2][1], bh[i2][2], bh[i2][3], rb + SM_BH);
                if (TERMS == 3)
                    ldsm_x4(bl[i2][0], bl[i2][1], bl[i2][2], bl[i2][3], rb + SM_BL);
            }
#pragma unroll
            for (int im = 0; im < 2; im++) {
#pragma unroll
                for (int in = 0; in < 4; in++) {
                    int i2 = in >> 1, sub = in & 1;
                    mma_f16(acc[im][in], ah[im], bh[i2][sub], bh[i2][sub + 2]);
                    if (TERMS == 3)
                        mma_f16(acc[im][in], ah[im], bl[i2][sub], bl[i2][sub + 2]);
                    mma_f16(acc[im][in], al[im], bh[i2][sub], bh[i2][sub + 2]);
                }
            }
        }
        __syncthreads();
    }
}

// Merged projection: sel 0 = q (3-term), 1 = k (2-term), 2 = v (2-term).
// q and k stored single fp16 in [cpair][s] layout; v packed along s.
__global__ __launch_bounds__(512, 1)
void proj_all(const float* __restrict__ query, const float* __restrict__ key_feat,
              const float* __restrict__ Wq, const float* __restrict__ Wk,
              const float* __restrict__ Wv) {
    __shared__ __align__(16) char sm[4 * TILE];
    const int s0  = blockIdx.x * 128;
    const int n   = blockIdx.y;
    const int sel = blockIdx.z;

    const int lane = threadIdx.x & 31, wid = threadIdx.x >> 5;
    const int wm = (wid >> 2) * 32, wn = (wid & 3) * 32;

    float acc[2][4][4];
#pragma unroll
    for (int i = 0; i < 2; i++)
#pragma unroll
        for (int j = 0; j < 4; j++)
#pragma unroll
            for (int t = 0; t < 4; t++) acc[i][j][t] = 0.f;

    if (sel == 2) {
        mma_gemm<32, 2>(Wv, DIM, key_feat + (size_t)s0 * (NB * DIM) + (size_t)n * DIM,
                        (size_t)NB * DIM, acc, sm);
#pragma unroll
        for (int im = 0; im < 2; im++) {
#pragma unroll
            for (int in = 0; in < 4; in++) {
#pragma unroll
                for (int half = 0; half < 2; half++) {
                    int row = wm + im * 16 + (lane >> 2) + half * 8;
                    int s = s0 + wn + in * 8 + (lane & 3) * 2;
                    g_vv[((size_t)n * 128 + row) * (SK / 2) + (s >> 1)] =
                        pack1(acc[im][in][2 * half], acc[im][in][2 * half + 1]);
                }
            }
        }
    } else {
        if (sel == 0)
            mma_gemm<32, 3>(Wq, DIM, query + (size_t)s0 * (NB * DIM) + (size_t)n * DIM,
                            (size_t)NB * DIM, acc, sm);
        else
            mma_gemm<32, 2>(Wk, DIM, key_feat + (size_t)s0 * (NB * DIM) + (size_t)n * DIM,
                            (size_t)NB * DIM, acc, sm);

        uint32_t* __restrict__ dst = (sel == 0) ? g_qh : g_kk;
        const bool even = ((lane >> 2) & 1) == 0;
#pragma unroll
        for (int im = 0; im < 2; im++) {
#pragma unroll
            for (int in = 0; in < 4; in++) {
#pragma unroll
                for (int half = 0; half < 2; half++) {
                    int row = wm + im * 16 + (lane >> 2) + half * 8;
                    int s = s0 + wn + in * 8 + (lane & 3) * 2;
                    int cp = row >> 1;
                    size_t base = ((size_t)n * 64 + cp) * SK + s;
                    uint32_t w = pack1(acc[im][in][2 * half], acc[im][in][2 * half + 1]);
                    uint32_t wp = __shfl_xor_sync(0xffffffffu, w, 4);
                    if (even) {
                        uint2 o;
                        o.x = (w & 0xFFFFu) | (wp << 16);
                        o.y = (w >> 16) | (wp & 0xFFFF0000u);
                        *(uint2*)&dst[base] = o;
                    }
                }
            }
        }
    }
}

// up: 1-term fp16 GEMM. A = g_x16 (pre-packed fp16), B = Wup single-rounded.
#define USM_A 0
#define USM_B TILE

__global__ __launch_bounds__(512, 1)
void up_mma(const float* __restrict__ Wup, float* __restrict__ out) {
    __shared__ __align__(16) char sm[2 * TILE];
    const int d0 = blockIdx.x * 128;
    const int r0 = blockIdx.y * 128;

    const int tid  = threadIdx.x;
    const int lane = tid & 31;
    const int wid  = tid >> 5;
    const int wm   = (wid >> 2) * 32;
    const int wn   = (wid & 3) * 32;
    const uint32_t smb = smem_u32(sm);

    float acc[2][4][4];
#pragma unroll
    for (int i = 0; i < 2; i++)
#pragma unroll
        for (int j = 0; j < 4; j++)
#pragma unroll
            for (int t = 0; t < 4; t++) acc[i][j][t] = 0.f;

    const int arow = tid >> 2, aseg = tid & 3;

    for (int c = 0; c < 4; c++) {
        *(uint4*)(sm + USM_A + arow * ROWB + aseg * 16) =
            *(const uint4*)&g_x16[(size_t)(r0 + arow) * 64 + c * 16 + aseg * 4];
        {
            const float* src = Wup + (size_t)(d0 + arow) * INNER + c * 32 + aseg * 8;
            float4 f0 = *(const float4*)src;
            float4 f1 = *(const float4*)(src + 4);
            uint4 o;
            o.x = pack1(f0.x, f0.y);
            o.y = pack1(f0.z, f0.w);
            o.z = pack1(f1.x, f1.y);
            o.w = pack1(f1.z, f1.w);
            *(uint4*)(sm + USM_B + arow * ROWB + aseg * 16) = o;
        }
        __syncthreads();

#pragma unroll
        for (int ks = 0; ks < 2; ks++) {
            const int kb = ks * 32;
            uint32_t ah[2][4];
#pragma unroll
            for (int im = 0; im < 2; im++) {
                uint32_t ra = smb + USM_A + (wm + im * 16 + (lane & 15)) * ROWB + (lane >> 4) * 16 + kb;
                ldsm_x4(ah[im][0], ah[im][1], ah[im][2], ah[im][3], ra);
            }
            uint32_t bh[2][4];
#pragma unroll
            for (int i2 = 0; i2 < 2; i2++) {
                uint32_t rb = smb + USM_B + (wn + i2 * 16 + (lane & 15)) * ROWB + (lane >> 4) * 16 + kb;
                ldsm_x4(bh[i2][0], bh[i2][1], bh[i2][2], bh[i2][3], rb);
            }
#pragma unroll
            for (int im = 0; im < 2; im++)
#pragma unroll
                for (int in = 0; in < 4; in++) {
                    int i2 = in >> 1, sub = in & 1;
                    mma_f16(acc[im][in], ah[im], bh[i2][sub], bh[i2][sub + 2]);
                }
        }
        __syncthreads();
    }

#pragma unroll
    for (int im = 0; im < 2; im++) {
#pragma unroll
        for (int in = 0; in < 4; in++) {
            int d = d0 + wn + in * 8 + (lane & 3) * 2;
#pragma unroll
            for (int half = 0; half < 2; half++) {
                int r = r0 + wm + im * 16 + (lane >> 2) + half * 8;
                int nn = r >> 11, pp = r & 2047;
                *(float2*)&out[((size_t)pp * NB + nn) * DIM + d] =
                    make_float2(acc[im][in][half * 2], acc[im][in][half * 2 + 1]);
            }
        }
    }
}

// ===================== Flash attention on HMMA =============================
// Q single, K single, P single, V single; occupancy 3 to hide MUFU softmax.
#define QP 136
#define KP 72
#define VP 36

__global__ __launch_bounds__(128, 3)
void attn_mma() {
    const int p0 = blockIdx.x * 128;
    const int h  = blockIdx.y;
    const int n  = blockIdx.z;

    const uint32_t* __restrict__ qh = g_qh + ((size_t)n * 64 + h * 16) * SK;
    const uint32_t* __restrict__ kp = g_kk + ((size_t)n * 64 + h * 16) * SK;
    const uint32_t* __restrict__ vp = g_vv + ((size_t)n * 128 + h * 32) * (SK / 2);

    __shared__ uint32_t qsh[16 * QP];
    __shared__ uint32_t ksh[16 * KP];
    __shared__ uint32_t vsh[32 * VP];

    const int tid  = threadIdx.x;
    const int lane = tid & 31;
    const int w    = tid >> 5;

    // ---- stage Q (pure copy) ----
#pragma unroll
    for (int t4 = 0; t4 < 4; t4++) {
        int idx = tid + t4 * 128;
        int cp = idx >> 5, q4 = (idx & 31) * 4;
        *(uint4*)&qsh[cp * QP + q4] = *(const uint4*)&qh[(size_t)cp * SK + p0 + q4];
    }
    __syncthreads();

    uint32_t qf[2][2][4];
#pragma unroll
    for (int im = 0; im < 2; im++) {
#pragma unroll
        for (int ks = 0; ks < 2; ks++) {
            int row = w * 32 + im * 16 + (lane >> 2);
            int cp = (lane & 3) + ks * 8;
            qf[im][ks][0] = qsh[cp * QP + row];
            qf[im][ks][1] = qsh[cp * QP + row + 8];
            qf[im][ks][2] = qsh[(cp + 4) * QP + row];
            qf[im][ks][3] = qsh[(cp + 4) * QP + row + 8];
        }
    }

    float oacc[2][4][4];
#pragma unroll
    for (int im = 0; im < 2; im++)
#pragma unroll
        for (int nt = 0; nt < 4; nt++)
#pragma unroll
            for (int t = 0; t < 4; t++) oacc[im][nt][t] = 0.f;
    float rowm[2][2] = {{-1e30f, -1e30f}, {-1e30f, -1e30f}};
    float rowl[2][2] = {{0.f, 0.f}, {0.f, 0.f}};

    const float SC2 = 0.17677669529663687f * 1.4426950408889634f;

    for (int k0 = 0; k0 < SK; k0 += 64) {
        // ---- stage K/V (pure copies) ----
#pragma unroll
        for (int t2 = 0; t2 < 2; t2++) {
            int idx = tid + t2 * 128;
            int cp = idx >> 4, k4 = (idx & 15) * 4;
            *(uint4*)&ksh[cp * KP + k4] = *(const uint4*)&kp[(size_t)cp * SK + k0 + k4];
            int c = idx >> 3, p4 = (idx & 7) * 4;
            *(uint4*)&vsh[c * VP + p4] = *(const uint4*)&vp[(size_t)c * (SK / 2) + (k0 >> 1) + p4];
        }
        __syncthreads();

        // ---- S = Q K^T (single term) ----
        float sacc[2][8][4];
#pragma unroll
        for (int im = 0; im < 2; im++)
#pragma unroll
            for (int in = 0; in < 8; in++)
#pragma unroll
                for (int t = 0; t < 4; t++) sacc[im][in][t] = 0.f;

#pragma unroll
        for (int ks = 0; ks < 2; ks++) {
            uint32_t bh[8][2];
#pragma unroll
            for (int in = 0; in < 8; in++) {
                int cp = (lane & 3) + ks * 8;
                int ky = in * 8 + (lane >> 2);
                bh[in][0] = ksh[cp * KP + ky];
                bh[in][1] = ksh[(cp + 4) * KP + ky];
            }
#pragma unroll
            for (int im = 0; im < 2; im++)
#pragma unroll
                for (int in = 0; in < 8; in++)
                    mma_f16(sacc[im][in], qf[im][ks], bh[in][0], bh[in][1]);
        }

        // ---- online softmax ----
#pragma unroll
        for (int im = 0; im < 2; im++) {
#pragma unroll
            for (int rs = 0; rs < 2; rs++) {
                float mx = rowm[im][rs];
#pragma unroll
                for (int in = 0; in < 8; in++)
                    mx = fmaxf(mx, fmaxf(sacc[im][in][rs * 2], sacc[im][in][rs * 2 + 1]));
                mx = fmaxf(mx, __shfl_xor_sync(0xffffffffu, mx, 1));
                mx = fmaxf(mx, __shfl_xor_sync(0xffffffffu, mx, 2));
                float corr = ex2f((rowm[im][rs] - mx) * SC2);
                rowm[im][rs] = mx;
                float sum = 0.f;
#pragma unroll
                for (int in = 0; in < 8; in++) {
                    float e0 = ex2f((sacc[im][in][rs * 2] - mx) * SC2);
                    float e1 = ex2f((sacc[im][in][rs * 2 + 1] - mx) * SC2);
                    sacc[im][in][rs * 2] = e0;
                    sacc[im][in][rs * 2 + 1] = e1;
                    sum += e0 + e1;
                }
                rowl[im][rs] = rowl[im][rs] * corr + sum;
#pragma unroll
                for (int nt = 0; nt < 4; nt++) {
                    oacc[im][nt][rs * 2] *= corr;
                    oacc[im][nt][rs * 2 + 1] *= corr;
                }
            }
        }

        // ---- O += P V^T (single term) ----
#pragma unroll
        for (int ks4 = 0; ks4 < 4; ks4++) {
            uint32_t pf[2][4];
#pragma unroll
            for (int im = 0; im < 2; im++) {
                const float* t0 = sacc[im][2 * ks4];
                const float* t1 = sacc[im][2 * ks4 + 1];
                pf[im][0] = pack1(t0[0], t0[1]);
                pf[im][1] = pack1(t0[2], t0[3]);
                pf[im][2] = pack1(t1[0], t1[1]);
                pf[im][3] = pack1(t1[2], t1[3]);
            }
            uint32_t bh[4][2];
#pragma unroll
            for (int nt = 0; nt < 4; nt++) {
                int c  = nt * 8 + (lane >> 2);
                int kq = (lane & 3) + ks4 * 8;
                bh[nt][0] = vsh[c * VP + kq];
                bh[nt][1] = vsh[c * VP + kq + 4];
            }
#pragma unroll
            for (int im = 0; im < 2; im++)
#pragma unroll
                for (int nt = 0; nt < 4; nt++)
                    mma_f16(oacc[im][nt], pf[im], bh[nt][0], bh[nt][1]);
        }
        __syncthreads();
    }

    // ---- finalize: 1/l, pack fp16, store ----
#pragma unroll
    for (int im = 0; im < 2; im++) {
#pragma unroll
        for (int rs = 0; rs < 2; rs++) {
            float l = rowl[im][rs];
            l += __shfl_xor_sync(0xffffffffu, l, 1);
            l += __shfl_xor_sync(0xffffffffu, l, 2);
            float inv = 1.f / l;
#pragma unroll
            for (int nt = 0; nt < 4; nt++) {
                oacc[im][nt][rs * 2] *= inv;
                oacc[im][nt][rs * 2 + 1] *= inv;
            }
        }
    }
    uint32_t* __restrict__ xout = g_x16 + (size_t)n * SQ * 64 + h * 16;
#pragma unroll
    for (int im = 0; im < 2; im++) {
#pragma unroll
        for (int nt = 0; nt < 4; nt++) {
            int row = p0 + w * 32 + im * 16 + (lane >> 2);
            int wc = nt * 4 + (lane & 3);
            xout[(size_t)row * 64 + wc]       = pack1(oacc[im][nt][0], oacc[im][nt][1]);
            xout[(size_t)(row + 8) * 64 + wc] = pack1(oacc[im][nt][2], oacc[im][nt][3]);
        }
    }
}

// ---------------------------------------------------------------------------
extern "C" void kernel_launch(void* const* d_in, const int* in_sizes, int n_in,
                              void* d_out, int out_size) {
    const float* query    = (const float*)d_in[0];
    const float* key_feat = (const float*)d_in[1];
    const float* Wq       = (const float*)d_in[2];
    const float* Wk       = (const float*)d_in[3];
    const float* Wv       = (const float*)d_in[4];
    const float* Wup      = (const float*)d_in[5];
    float* out            = (float*)d_out;

    dim3 g1(SK / 128, NB, 3);
    proj_all<<<g1, 512>>>(query, key_feat, Wq, Wk, Wv);

    dim3 g2(SQ / 128, NH, NB);
    attn_mma<<<g2, 128>>>();

    dim3 g3(DIM / 128, (NB * SQ) / 128);
    up_mma<<<g3, 512>>>(Wup, out);
}

// round 14
// speedup vs baseline: 1.7568x; 1.0561x over previous
#include <cuda_runtime.h>
#include <cuda_fp16.h>
#include <cstdint>

#define SQ 2048
#define SK 2048
#define NB 8
#define DIM 1024
#define INNER 128
#define NH 4
#define HD 32

// Scratch (allocation-free): packed-fp16 projections + packed-fp16 attn output
__device__ uint32_t g_qh[(size_t)NB * 64 * SK];        // q     [n][cpair][s]
__device__ uint32_t g_kk[(size_t)NB * 64 * SK];        // k     [n][cpair][s]
__device__ uint32_t g_vv[(size_t)NB * 128 * (SK / 2)]; // v     [n][c][spair]
__device__ uint32_t g_x16[(size_t)NB * SQ * 64];       // x     [n*SQ+p][epair]

// ============================ warp-MMA helpers =============================
__device__ __forceinline__ uint32_t smem_u32(const void* p) {
    return (uint32_t)__cvta_generic_to_shared(p);
}
__device__ __forceinline__ void ldsm_x4(uint32_t& r0, uint32_t& r1,
                                        uint32_t& r2, uint32_t& r3, uint32_t addr) {
    asm volatile("ldmatrix.sync.aligned.m8n8.x4.shared.b16 {%0,%1,%2,%3}, [%4];"
                 : "=r"(r0), "=r"(r1), "=r"(r2), "=r"(r3) : "r"(addr));
}
__device__ __forceinline__ void mma_f16(float* d, const uint32_t* a,
                                        uint32_t b0, uint32_t b1) {
    asm volatile(
        "mma.sync.aligned.m16n8k16.row.col.f32.f16.f16.f32 "
        "{%0,%1,%2,%3}, {%4,%5,%6,%7}, {%8,%9}, {%0,%1,%2,%3};"
        : "+f"(d[0]), "+f"(d[1]), "+f"(d[2]), "+f"(d[3])
        : "r"(a[0]), "r"(a[1]), "r"(a[2]), "r"(a[3]), "r"(b0), "r"(b1));
}
__device__ __forceinline__ float ex2f(float x) {
    float y;
    asm("ex2.approx.f32 %0, %1;" : "=f"(y) : "f"(x));
    return y;
}

__device__ __forceinline__ void split2(float x, float y, uint32_t& hi, uint32_t& lo) {
    __half hx = __float2half_rn(x);
    __half hy = __float2half_rn(y);
    __half lx = __float2half_rn(x - __half2float(hx));
    __half ly = __float2half_rn(y - __half2float(hy));
    hi = (uint32_t)__half_as_ushort(hx) | ((uint32_t)__half_as_ushort(hy) << 16);
    lo = (uint32_t)__half_as_ushort(lx) | ((uint32_t)__half_as_ushort(ly) << 16);
}
__device__ __forceinline__ uint32_t pack1(float x, float y) {
    return (uint32_t)__half_as_ushort(__float2half_rn(x))
         | ((uint32_t)__half_as_ushort(__float2half_rn(y)) << 16);
}

// ===================== GEMM template (512 threads, 16 warps) ===============
// 2-term: A split (hi/lo), B single-rounded -> AhBh + AlBh.
#define ROWB   80
#define TILE   (128 * ROWB)
#define SM_AH  0
#define SM_AL  TILE
#define SM_BH  (2 * TILE)

__device__ __forceinline__ void cvt_store2(const float4* va, const float4* vb,
                                           char* buf, int rbase, int seg) {
#pragma unroll
    for (int p = 0; p < 2; p++) {
        int off = (rbase + 64 * p) * ROWB + seg * 8;
        uint2 h, l;
        split2(va[p].x, va[p].y, h.x, l.x);
        split2(va[p].z, va[p].w, h.y, l.y);
        *(uint2*)(buf + SM_AH + off) = h;
        *(uint2*)(buf + SM_AL + off) = l;
        h.x = pack1(vb[p].x, vb[p].y);
        h.y = pack1(vb[p].z, vb[p].w);
        *(uint2*)(buf + SM_BH + off) = h;
    }
}

template <int KCHUNKS>
__device__ __forceinline__ void mma_gemm(const float* __restrict__ A, size_t lda,
                                         const float* __restrict__ B, size_t ldb,
                                         float acc[2][4][4], char* sm) {
    const int tid  = threadIdx.x;
    const int lane = tid & 31;
    const int wid  = tid >> 5;
    const int wm   = (wid >> 2) * 32;
    const int wn   = (wid & 3) * 32;
    const int seg  = tid & 7;
    const int rbase = tid >> 3;
    const uint32_t smb = smem_u32(sm);

    float4 va[2], vb[2];
#pragma unroll
    for (int p = 0; p < 2; p++) {
        va[p] = *(const float4*)(A + (size_t)(rbase + 64 * p) * lda + seg * 4);
        vb[p] = *(const float4*)(B + (size_t)(rbase + 64 * p) * ldb + seg * 4);
    }

    for (int c = 0; c < KCHUNKS; c++) {
        cvt_store2(va, vb, sm, rbase, seg);
        __syncthreads();

        if (c + 1 < KCHUNKS) {
            int co = (c + 1) * 32;
#pragma unroll
            for (int p = 0; p < 2; p++) {
                va[p] = *(const float4*)(A + (size_t)(rbase + 64 * p) * lda + co + seg * 4);
                vb[p] = *(const float4*)(B + (size_t)(rbase + 64 * p) * ldb + co + seg * 4);
            }
        }

#pragma unroll
        for (int ks = 0; ks < 2; ks++) {
            const int kb = ks * 32;
            uint32_t ah[2][4], al[2][4];
#pragma unroll
            for (int im = 0; im < 2; im++) {
                uint32_t ra = smb + (wm + im * 16 + (lane & 15)) * ROWB + (lane >> 4) * 16 + kb;
                ldsm_x4(ah[im][0], ah[im][1], ah[im][2], ah[im][3], ra + SM_AH);
                ldsm_x4(al[im][0], al[im][1], al[im][2], al[im][3], ra + SM_AL);
            }
            uint32_t bh[2][4];
#pragma unroll
            for (int i2 = 0; i2 < 2; i2++) {
                uint32_t rb = smb + (wn + i2 * 16 + (lane & 15)) * ROWB + (lane >> 4) * 16 + kb;
                ldsm_x4(bh[i2][0], bh[i2][1], bh[i2][2], bh[i2][3], rb + SM_BH);
            }
#pragma unroll
            for (int im = 0; im < 2; im++) {
#pragma unroll
                for (int in = 0; in < 4; in++) {
                    int i2 = in >> 1, sub = in & 1;
                    mma_f16(acc[im][in], ah[im], bh[i2][sub], bh[i2][sub + 2]);
                    mma_f16(acc[im][in], al[im], bh[i2][sub], bh[i2][sub + 2]);
                }
            }
        }
        __syncthreads();
    }
}

// Merged projection (all 2-term): sel 0 = q, 1 = k, 2 = v.
// q and k stored single fp16 in [cpair][s] layout; v packed along s.
__global__ __launch_bounds__(512, 1)
void proj_all(const float* __restrict__ query, const float* __restrict__ key_feat,
              const float* __restrict__ Wq, const float* __restrict__ Wk,
              const float* __restrict__ Wv) {
    __shared__ __align__(16) char sm[3 * TILE];
    const int s0  = blockIdx.x * 128;
    const int n   = blockIdx.y;
    const int sel = blockIdx.z;

    const int lane = threadIdx.x & 31, wid = threadIdx.x >> 5;
    const int wm = (wid >> 2) * 32, wn = (wid & 3) * 32;

    const float* __restrict__ X = (sel == 0) ? query : key_feat;
    const float* __restrict__ W = (sel == 0) ? Wq : (sel == 1 ? Wk : Wv);

    float acc[2][4][4];
#pragma unroll
    for (int i = 0; i < 2; i++)
#pragma unroll
        for (int j = 0; j < 4; j++)
#pragma unroll
            for (int t = 0; t < 4; t++) acc[i][j][t] = 0.f;

    mma_gemm<32>(W, DIM, X + (size_t)s0 * (NB * DIM) + (size_t)n * DIM,
                 (size_t)NB * DIM, acc, sm);

    if (sel == 2) {
#pragma unroll
        for (int im = 0; im < 2; im++) {
#pragma unroll
            for (int in = 0; in < 4; in++) {
#pragma unroll
                for (int half = 0; half < 2; half++) {
                    int row = wm + im * 16 + (lane >> 2) + half * 8;
                    int s = s0 + wn + in * 8 + (lane & 3) * 2;
                    g_vv[((size_t)n * 128 + row) * (SK / 2) + (s >> 1)] =
                        pack1(acc[im][in][2 * half], acc[im][in][2 * half + 1]);
                }
            }
        }
    } else {
        uint32_t* __restrict__ dst = (sel == 0) ? g_qh : g_kk;
        const bool even = ((lane >> 2) & 1) == 0;
#pragma unroll
        for (int im = 0; im < 2; im++) {
#pragma unroll
            for (int in = 0; in < 4; in++) {
#pragma unroll
                for (int half = 0; half < 2; half++) {
                    int row = wm + im * 16 + (lane >> 2) + half * 8;
                    int s = s0 + wn + in * 8 + (lane & 3) * 2;
                    int cp = row >> 1;
                    size_t base = ((size_t)n * 64 + cp) * SK + s;
                    uint32_t w = pack1(acc[im][in][2 * half], acc[im][in][2 * half + 1]);
                    uint32_t wp = __shfl_xor_sync(0xffffffffu, w, 4);
                    if (even) {
                        uint2 o;
                        o.x = (w & 0xFFFFu) | (wp << 16);
                        o.y = (w >> 16) | (wp & 0xFFFF0000u);
                        *(uint2*)&dst[base] = o;
                    }
                }
            }
        }
    }
}

// up: 1-term fp16 GEMM. A = g_x16 (pre-packed fp16), B = Wup single-rounded.
#define USM_A 0
#define USM_B TILE

__global__ __launch_bounds__(512, 1)
void up_mma(const float* __restrict__ Wup, float* __restrict__ out) {
    __shared__ __align__(16) char sm[2 * TILE];
    const int d0 = blockIdx.x * 128;
    const int r0 = blockIdx.y * 128;

    const int tid  = threadIdx.x;
    const int lane = tid & 31;
    const int wid  = tid >> 5;
    const int wm   = (wid >> 2) * 32;
    const int wn   = (wid & 3) * 32;
    const uint32_t smb = smem_u32(sm);

    float acc[2][4][4];
#pragma unroll
    for (int i = 0; i < 2; i++)
#pragma unroll
        for (int j = 0; j < 4; j++)
#pragma unroll
            for (int t = 0; t < 4; t++) acc[i][j][t] = 0.f;

    const int arow = tid >> 2, aseg = tid & 3;

    for (int c = 0; c < 4; c++) {
        *(uint4*)(sm + USM_A + arow * ROWB + aseg * 16) =
            *(const uint4*)&g_x16[(size_t)(r0 + arow) * 64 + c * 16 + aseg * 4];
        {
            const float* src = Wup + (size_t)(d0 + arow) * INNER + c * 32 + aseg * 8;
            float4 f0 = *(const float4*)src;
            float4 f1 = *(const float4*)(src + 4);
            uint4 o;
            o.x = pack1(f0.x, f0.y);
            o.y = pack1(f0.z, f0.w);
            o.z = pack1(f1.x, f1.y);
            o.w = pack1(f1.z, f1.w);
            *(uint4*)(sm + USM_B + arow * ROWB + aseg * 16) = o;
        }
        __syncthreads();

#pragma unroll
        for (int ks = 0; ks < 2; ks++) {
            const int kb = ks * 32;
            uint32_t ah[2][4];
#pragma unroll
            for (int im = 0; im < 2; im++) {
                uint32_t ra = smb + USM_A + (wm + im * 16 + (lane & 15)) * ROWB + (lane >> 4) * 16 + kb;
                ldsm_x4(ah[im][0], ah[im][1], ah[im][2], ah[im][3], ra);
            }
            uint32_t bh[2][4];
#pragma unroll
            for (int i2 = 0; i2 < 2; i2++) {
                uint32_t rb = smb + USM_B + (wn + i2 * 16 + (lane & 15)) * ROWB + (lane >> 4) * 16 + kb;
                ldsm_x4(bh[i2][0], bh[i2][1], bh[i2][2], bh[i2][3], rb);
            }
#pragma unroll
            for (int im = 0; im < 2; im++)
#pragma unroll
                for (int in = 0; in < 4; in++) {
                    int i2 = in >> 1, sub = in & 1;
                    mma_f16(acc[im][in], ah[im], bh[i2][sub], bh[i2][sub + 2]);
                }
        }
        __syncthreads();
    }

#pragma unroll
    for (int im = 0; im < 2; im++) {
#pragma unroll
        for (int in = 0; in < 4; in++) {
            int d = d0 + wn + in * 8 + (lane & 3) * 2;
#pragma unroll
            for (int half = 0; half < 2; half++) {
                int r = r0 + wm + im * 16 + (lane >> 2) + half * 8;
                int nn = r >> 11, pp = r & 2047;
                *(float2*)&out[((size_t)pp * NB + nn) * DIM + d] =
                    make_float2(acc[im][in][half * 2], acc[im][in][half * 2 + 1]);
            }
        }
    }
}

// ===================== Flash attention on HMMA =============================
// Q single, K single, P single, V single; occupancy 3 to hide MUFU softmax.
#define QP 136
#define KP 72
#define VP 36

__global__ __launch_bounds__(128, 3)
void attn_mma() {
    const int p0 = blockIdx.x * 128;
    const int h  = blockIdx.y;
    const int n  = blockIdx.z;

    const uint32_t* __restrict__ qh = g_qh + ((size_t)n * 64 + h * 16) * SK;
    const uint32_t* __restrict__ kp = g_kk + ((size_t)n * 64 + h * 16) * SK;
    const uint32_t* __restrict__ vp = g_vv + ((size_t)n * 128 + h * 32) * (SK / 2);

    __shared__ uint32_t qsh[16 * QP];
    __shared__ uint32_t ksh[16 * KP];
    __shared__ uint32_t vsh[32 * VP];

    const int tid  = threadIdx.x;
    const int lane = tid & 31;
    const int w    = tid >> 5;

    // ---- stage Q (pure copy) ----
#pragma unroll
    for (int t4 = 0; t4 < 4; t4++) {
        int idx = tid + t4 * 128;
        int cp = idx >> 5, q4 = (idx & 31) * 4;
        *(uint4*)&qsh[cp * QP + q4] = *(const uint4*)&qh[(size_t)cp * SK + p0 + q4];
    }
    __syncthreads();

    uint32_t qf[2][2][4];
#pragma unroll
    for (int im = 0; im < 2; im++) {
#pragma unroll
        for (int ks = 0; ks < 2; ks++) {
            int row = w * 32 + im * 16 + (lane >> 2);
            int cp = (lane & 3) + ks * 8;
            qf[im][ks][0] = qsh[cp * QP + row];
            qf[im][ks][1] = qsh[cp * QP + row + 8];
            qf[im][ks][2] = qsh[(cp + 4) * QP + row];
            qf[im][ks][3] = qsh[(cp + 4) * QP + row + 8];
        }
    }

    float oacc[2][4][4];
#pragma unroll
    for (int im = 0; im < 2; im++)
#pragma unroll
        for (int nt = 0; nt < 4; nt++)
#pragma unroll
            for (int t = 0; t < 4; t++) oacc[im][nt][t] = 0.f;
    float rowm[2][2] = {{-1e30f, -1e30f}, {-1e30f, -1e30f}};
    float rowl[2][2] = {{0.f, 0.f}, {0.f, 0.f}};

    const float SC2 = 0.17677669529663687f * 1.4426950408889634f;

    for (int k0 = 0; k0 < SK; k0 += 64) {
        // ---- stage K/V (pure copies) ----
#pragma unroll
        for (int t2 = 0; t2 < 2; t2++) {
            int idx = tid + t2 * 128;
            int cp = idx >> 4, k4 = (idx & 15) * 4;
            *(uint4*)&ksh[cp * KP + k4] = *(const uint4*)&kp[(size_t)cp * SK + k0 + k4];
            int c = idx >> 3, p4 = (idx & 7) * 4;
            *(uint4*)&vsh[c * VP + p4] = *(const uint4*)&vp[(size_t)c * (SK / 2) + (k0 >> 1) + p4];
        }
        __syncthreads();

        // ---- S = Q K^T (single term) ----
        float sacc[2][8][4];
#pragma unroll
        for (int im = 0; im < 2; im++)
#pragma unroll
            for (int in = 0; in < 8; in++)
#pragma unroll
                for (int t = 0; t < 4; t++) sacc[im][in][t] = 0.f;

#pragma unroll
        for (int ks = 0; ks < 2; ks++) {
            uint32_t bh[8][2];
#pragma unroll
            for (int in = 0; in < 8; in++) {
                int cp = (lane & 3) + ks * 8;
                int ky = in * 8 + (lane >> 2);
                bh[in][0] = ksh[cp * KP + ky];
                bh[in][1] = ksh[(cp + 4) * KP + ky];
            }
#pragma unroll
            for (int im = 0; im < 2; im++)
#pragma unroll
                for (int in = 0; in < 8; in++)
                    mma_f16(sacc[im][in], qf[im][ks], bh[in][0], bh[in][1]);
        }

        // ---- online softmax ----
#pragma unroll
        for (int im = 0; im < 2; im++) {
#pragma unroll
            for (int rs = 0; rs < 2; rs++) {
                float mx = rowm[im][rs];
#pragma unroll
                for (int in = 0; in < 8; in++)
                    mx = fmaxf(mx, fmaxf(sacc[im][in][rs * 2], sacc[im][in][rs * 2 + 1]));
                mx = fmaxf(mx, __shfl_xor_sync(0xffffffffu, mx, 1));
                mx = fmaxf(mx, __shfl_xor_sync(0xffffffffu, mx, 2));
                float corr = ex2f((rowm[im][rs] - mx) * SC2);
                rowm[im][rs] = mx;
                float sum = 0.f;
#pragma unroll
                for (int in = 0; in < 8; in++) {
                    float e0 = ex2f((sacc[im][in][rs * 2] - mx) * SC2);
                    float e1 = ex2f((sacc[im][in][rs * 2 + 1] - mx) * SC2);
                    sacc[im][in][rs * 2] = e0;
                    sacc[im][in][rs * 2 + 1] = e1;
                    sum += e0 + e1;
                }
                rowl[im][rs] = rowl[im][rs] * corr + sum;
#pragma unroll
                for (int nt = 0; nt < 4; nt++) {
                    oacc[im][nt][rs * 2] *= corr;
                    oacc[im][nt][rs * 2 + 1] *= corr;
                }
            }
        }

        // ---- O += P V^T (single term) ----
#pragma unroll
        for (int ks4 = 0; ks4 < 4; ks4++) {
            uint32_t pf[2][4];
#pragma unroll
            for (int im = 0; im < 2; im++) {
                const float* t0 = sacc[im][2 * ks4];
                const float* t1 = sacc[im][2 * ks4 + 1];
                pf[im][0] = pack1(t0[0], t0[1]);
                pf[im][1] = pack1(t0[2], t0[3]);
                pf[im][2] = pack1(t1[0], t1[1]);
                pf[im][3] = pack1(t1[2], t1[3]);
            }
            uint32_t bh[4][2];
#pragma unroll
            for (int nt = 0; nt < 4; nt++) {
                int c  = nt * 8 + (lane >> 2);
                int kq = (lane & 3) + ks4 * 8;
                bh[nt][0] = vsh[c * VP + kq];
                bh[nt][1] = vsh[c * VP + kq + 4];
            }
#pragma unroll
            for (int im = 0; im < 2; im++)
#pragma unroll
                for (int nt = 0; nt < 4; nt++)
                    mma_f16(oacc[im][nt], pf[im], bh[nt][0], bh[nt][1]);
        }
        __syncthreads();
    }

    // ---- finalize: 1/l, pack fp16, store ----
#pragma unroll
    for (int im = 0; im < 2; im++) {
#pragma unroll
        for (int rs = 0; rs < 2; rs++) {
            float l = rowl[im][rs];
            l += __shfl_xor_sync(0xffffffffu, l, 1);
            l += __shfl_xor_sync(0xffffffffu, l, 2);
            float inv = 1.f / l;
#pragma unroll
            for (int nt = 0; nt < 4; nt++) {
                oacc[im][nt][rs * 2] *= inv;
                oacc[im][nt][rs * 2 + 1] *= inv;
            }
        }
    }
    uint32_t* __restrict__ xout = g_x16 + (size_t)n * SQ * 64 + h * 16;
#pragma unroll
    for (int im = 0; im < 2; im++) {
#pragma unroll
        for (int nt = 0; nt < 4; nt++) {
            int row = p0 + w * 32 + im * 16 + (lane >> 2);
            int wc = nt * 4 + (lane & 3);
            xout[(size_t)row * 64 + wc]       = pack1(oacc[im][nt][0], oacc[im][nt][1]);
            xout[(size_t)(row + 8) * 64 + wc] = pack1(oacc[im][nt][2], oacc[im][nt][3]);
        }
    }
}

// ---------------------------------------------------------------------------
extern "C" void kernel_launch(void* const* d_in, const int* in_sizes, int n_in,
                              void* d_out, int out_size) {
    const float* query    = (const float*)d_in[0];
    const float* key_feat = (const float*)d_in[1];
    const float* Wq       = (const float*)d_in[2];
    const float* Wk       = (const float*)d_in[3];
    const float* Wv       = (const float*)d_in[4];
    const float* Wup      = (const float*)d_in[5];
    float* out            = (float*)d_out;

    dim3 g1(SK / 128, NB, 3);
    proj_all<<<g1, 512>>>(query, key_feat, Wq, Wk, Wv);

    dim3 g2(SQ / 128, NH, NB);
    attn_mma<<<g2, 128>>>();

    dim3 g3(DIM / 128, (NB * SQ) / 128);
    up_mma<<<g3, 512>>>(Wup, out);
}

// round 15
// speedup vs baseline: 1.8675x; 1.0630x over previous
#include <cuda_runtime.h>
#include <cuda_fp16.h>
#include <cstdint>

#define SQ 2048
#define SK 2048
#define NB 8
#define DIM 1024
#define INNER 128
#define NH 4
#define HD 32

// Scratch (allocation-free): packed-fp16 projections + packed-fp16 attn output
__device__ uint32_t g_qh[(size_t)NB * 64 * SK];        // q     [n][cpair][s]
__device__ uint32_t g_kk[(size_t)NB * 64 * SK];        // k     [n][cpair][s]
__device__ uint32_t g_vv[(size_t)NB * 128 * (SK / 2)]; // v     [n][c][spair]
__device__ uint32_t g_x16[(size_t)NB * SQ * 64];       // x     [n*SQ+p][epair]

// ============================ warp-MMA helpers =============================
__device__ __forceinline__ uint32_t smem_u32(const void* p) {
    return (uint32_t)__cvta_generic_to_shared(p);
}
__device__ __forceinline__ void ldsm_x4(uint32_t& r0, uint32_t& r1,
                                        uint32_t& r2, uint32_t& r3, uint32_t addr) {
    asm volatile("ldmatrix.sync.aligned.m8n8.x4.shared.b16 {%0,%1,%2,%3}, [%4];"
                 : "=r"(r0), "=r"(r1), "=r"(r2), "=r"(r3) : "r"(addr));
}
__device__ __forceinline__ void mma_f16(float* d, const uint32_t* a,
                                        uint32_t b0, uint32_t b1) {
    asm volatile(
        "mma.sync.aligned.m16n8k16.row.col.f32.f16.f16.f32 "
        "{%0,%1,%2,%3}, {%4,%5,%6,%7}, {%8,%9}, {%0,%1,%2,%3};"
        : "+f"(d[0]), "+f"(d[1]), "+f"(d[2]), "+f"(d[3])
        : "r"(a[0]), "r"(a[1]), "r"(a[2]), "r"(a[3]), "r"(b0), "r"(b1));
}
__device__ __forceinline__ float ex2f(float x) {
    float y;
    asm("ex2.approx.f32 %0, %1;" : "=f"(y) : "f"(x));
    return y;
}

__device__ __forceinline__ void split2(float x, float y, uint32_t& hi, uint32_t& lo) {
    __half hx = __float2half_rn(x);
    __half hy = __float2half_rn(y);
    __half lx = __float2half_rn(x - __half2float(hx));
    __half ly = __float2half_rn(y - __half2float(hy));
    hi = (uint32_t)__half_as_ushort(hx) | ((uint32_t)__half_as_ushort(hy) << 16);
    lo = (uint32_t)__half_as_ushort(lx) | ((uint32_t)__half_as_ushort(ly) << 16);
}
__device__ __forceinline__ uint32_t pack1(float x, float y) {
    return (uint32_t)__half_as_ushort(__float2half_rn(x))
         | ((uint32_t)__half_as_ushort(__float2half_rn(y)) << 16);
}

// ===================== GEMM template (512 threads, 16 warps) ===============
// 2-term: A split (hi/lo), B single-rounded -> AhBh + AlBh.
#define ROWB   80
#define TILE   (128 * ROWB)
#define SM_AH  0
#define SM_AL  TILE
#define SM_BH  (2 * TILE)

__device__ __forceinline__ void cvt_store2(const float4* va, const float4* vb,
                                           char* buf, int rbase, int seg) {
#pragma unroll
    for (int p = 0; p < 2; p++) {
        int off = (rbase + 64 * p) * ROWB + seg * 8;
        uint2 h, l;
        split2(va[p].x, va[p].y, h.x, l.x);
        split2(va[p].z, va[p].w, h.y, l.y);
        *(uint2*)(buf + SM_AH + off) = h;
        *(uint2*)(buf + SM_AL + off) = l;
        h.x = pack1(vb[p].x, vb[p].y);
        h.y = pack1(vb[p].z, vb[p].w);
        *(uint2*)(buf + SM_BH + off) = h;
    }
}

template <int KCHUNKS>
__device__ __forceinline__ void mma_gemm(const float* __restrict__ A, size_t lda,
                                         const float* __restrict__ B, size_t ldb,
                                         float acc[2][4][4], char* sm) {
    const int tid  = threadIdx.x;
    const int lane = tid & 31;
    const int wid  = tid >> 5;
    const int wm   = (wid >> 2) * 32;
    const int wn   = (wid & 3) * 32;
    const int seg  = tid & 7;
    const int rbase = tid >> 3;
    const uint32_t smb = smem_u32(sm);

    float4 va[2], vb[2];
#pragma unroll
    for (int p = 0; p < 2; p++) {
        va[p] = *(const float4*)(A + (size_t)(rbase + 64 * p) * lda + seg * 4);
        vb[p] = *(const float4*)(B + (size_t)(rbase + 64 * p) * ldb + seg * 4);
    }

    for (int c = 0; c < KCHUNKS; c++) {
        cvt_store2(va, vb, sm, rbase, seg);
        __syncthreads();

        if (c + 1 < KCHUNKS) {
            int co = (c + 1) * 32;
#pragma unroll
            for (int p = 0; p < 2; p++) {
                va[p] = *(const float4*)(A + (size_t)(rbase + 64 * p) * lda + co + seg * 4);
                vb[p] = *(const float4*)(B + (size_t)(rbase + 64 * p) * ldb + co + seg * 4);
            }
        }

#pragma unroll
        for (int ks = 0; ks < 2; ks++) {
            const int kb = ks * 32;
            uint32_t ah[2][4], al[2][4];
#pragma unroll
            for (int im = 0; im < 2; im++) {
                uint32_t ra = smb + (wm + im * 16 + (lane & 15)) * ROWB + (lane >> 4) * 16 + kb;
                ldsm_x4(ah[im][0], ah[im][1], ah[im][2], ah[im][3], ra + SM_AH);
                ldsm_x4(al[im][0], al[im][1], al[im][2], al[im][3], ra + SM_AL);
            }
            uint32_t bh[2][4];
#pragma unroll
            for (int i2 = 0; i2 < 2; i2++) {
                uint32_t rb = smb + (wn + i2 * 16 + (lane & 15)) * ROWB + (lane >> 4) * 16 + kb;
                ldsm_x4(bh[i2][0], bh[i2][1], bh[i2][2], bh[i2][3], rb + SM_BH);
            }
#pragma unroll
            for (int im = 0; im < 2; im++) {
#pragma unroll
                for (int in = 0; in < 4; in++) {
                    int i2 = in >> 1, sub = in & 1;
                    mma_f16(acc[im][in], ah[im], bh[i2][sub], bh[i2][sub + 2]);
                    mma_f16(acc[im][in], al[im], bh[i2][sub], bh[i2][sub + 2]);
                }
            }
        }
        __syncthreads();
    }
}

// Merged projection (all 2-term): sel 0 = q, 1 = k, 2 = v.
__global__ __launch_bounds__(512, 1)
void proj_all(const float* __restrict__ query, const float* __restrict__ key_feat,
              const float* __restrict__ Wq, const float* __restrict__ Wk,
              const float* __restrict__ Wv) {
    __shared__ __align__(16) char sm[3 * TILE];
    const int s0  = blockIdx.x * 128;
    const int n   = blockIdx.y;
    const int sel = blockIdx.z;

    const int lane = threadIdx.x & 31, wid = threadIdx.x >> 5;
    const int wm = (wid >> 2) * 32, wn = (wid & 3) * 32;

    const float* __restrict__ X = (sel == 0) ? query : key_feat;
    const float* __restrict__ W = (sel == 0) ? Wq : (sel == 1 ? Wk : Wv);

    float acc[2][4][4];
#pragma unroll
    for (int i = 0; i < 2; i++)
#pragma unroll
        for (int j = 0; j < 4; j++)
#pragma unroll
            for (int t = 0; t < 4; t++) acc[i][j][t] = 0.f;

    mma_gemm<32>(W, DIM, X + (size_t)s0 * (NB * DIM) + (size_t)n * DIM,
                 (size_t)NB * DIM, acc, sm);

    if (sel == 2) {
#pragma unroll
        for (int im = 0; im < 2; im++) {
#pragma unroll
            for (int in = 0; in < 4; in++) {
#pragma unroll
                for (int half = 0; half < 2; half++) {
                    int row = wm + im * 16 + (lane >> 2) + half * 8;
                    int s = s0 + wn + in * 8 + (lane & 3) * 2;
                    g_vv[((size_t)n * 128 + row) * (SK / 2) + (s >> 1)] =
                        pack1(acc[im][in][2 * half], acc[im][in][2 * half + 1]);
                }
            }
        }
    } else {
        uint32_t* __restrict__ dst = (sel == 0) ? g_qh : g_kk;
        const bool even = ((lane >> 2) & 1) == 0;
#pragma unroll
        for (int im = 0; im < 2; im++) {
#pragma unroll
            for (int in = 0; in < 4; in++) {
#pragma unroll
                for (int half = 0; half < 2; half++) {
                    int row = wm + im * 16 + (lane >> 2) + half * 8;
                    int s = s0 + wn + in * 8 + (lane & 3) * 2;
                    int cp = row >> 1;
                    size_t base = ((size_t)n * 64 + cp) * SK + s;
                    uint32_t w = pack1(acc[im][in][2 * half], acc[im][in][2 * half + 1]);
                    uint32_t wp = __shfl_xor_sync(0xffffffffu, w, 4);
                    if (even) {
                        uint2 o;
                        o.x = (w & 0xFFFFu) | (wp << 16);
                        o.y = (w >> 16) | (wp & 0xFFFF0000u);
                        *(uint2*)&dst[base] = o;
                    }
                }
            }
        }
    }
}

// up: 1-term fp16 GEMM. A = g_x16 (pre-packed fp16), B = Wup single-rounded.
#define USM_A 0
#define USM_B TILE

__global__ __launch_bounds__(512, 1)
void up_mma(const float* __restrict__ Wup, float* __restrict__ out) {
    __shared__ __align__(16) char sm[2 * TILE];
    const int d0 = blockIdx.x * 128;
    const int r0 = blockIdx.y * 128;

    const int tid  = threadIdx.x;
    const int lane = tid & 31;
    const int wid  = tid >> 5;
    const int wm   = (wid >> 2) * 32;
    const int wn   = (wid & 3) * 32;
    const uint32_t smb = smem_u32(sm);

    float acc[2][4][4];
#pragma unroll
    for (int i = 0; i < 2; i++)
#pragma unroll
        for (int j = 0; j < 4; j++)
#pragma unroll
            for (int t = 0; t < 4; t++) acc[i][j][t] = 0.f;

    const int arow = tid >> 2, aseg = tid & 3;

    for (int c = 0; c < 4; c++) {
        *(uint4*)(sm + USM_A + arow * ROWB + aseg * 16) =
            *(const uint4*)&g_x16[(size_t)(r0 + arow) * 64 + c * 16 + aseg * 4];
        {
            const float* src = Wup + (size_t)(d0 + arow) * INNER + c * 32 + aseg * 8;
            float4 f0 = *(const float4*)src;
            float4 f1 = *(const float4*)(src + 4);
            uint4 o;
            o.x = pack1(f0.x, f0.y);
            o.y = pack1(f0.z, f0.w);
            o.z = pack1(f1.x, f1.y);
            o.w = pack1(f1.z, f1.w);
            *(uint4*)(sm + USM_B + arow * ROWB + aseg * 16) = o;
        }
        __syncthreads();

#pragma unroll
        for (int ks = 0; ks < 2; ks++) {
            const int kb = ks * 32;
            uint32_t ah[2][4];
#pragma unroll
            for (int im = 0; im < 2; im++) {
                uint32_t ra = smb + USM_A + (wm + im * 16 + (lane & 15)) * ROWB + (lane >> 4) * 16 + kb;
                ldsm_x4(ah[im][0], ah[im][1], ah[im][2], ah[im][3], ra);
            }
            uint32_t bh[2][4];
#pragma unroll
            for (int i2 = 0; i2 < 2; i2++) {
                uint32_t rb = smb + USM_B + (wn + i2 * 16 + (lane & 15)) * ROWB + (lane >> 4) * 16 + kb;
                ldsm_x4(bh[i2][0], bh[i2][1], bh[i2][2], bh[i2][3], rb);
            }
#pragma unroll
            for (int im = 0; im < 2; im++)
#pragma unroll
                for (int in = 0; in < 4; in++) {
                    int i2 = in >> 1, sub = in & 1;
                    mma_f16(acc[im][in], ah[im], bh[i2][sub], bh[i2][sub + 2]);
                }
        }
        __syncthreads();
    }

#pragma unroll
    for (int im = 0; im < 2; im++) {
#pragma unroll
        for (int in = 0; in < 4; in++) {
            int d = d0 + wn + in * 8 + (lane & 3) * 2;
#pragma unroll
            for (int half = 0; half < 2; half++) {
                int r = r0 + wm + im * 16 + (lane >> 2) + half * 8;
                int nn = r >> 11, pp = r & 2047;
                *(float2*)&out[((size_t)pp * NB + nn) * DIM + d] =
                    make_float2(acc[im][in][half * 2], acc[im][in][half * 2 + 1]);
            }
        }
    }
}

// ===================== Flash attention on HMMA =============================
// Query tile 64/CTA (warp tile m16), occupancy 4; Q/K/P/V single fp16.
#define QP2 72
#define KP 72
#define VP 36

__global__ __launch_bounds__(128, 4)
void attn_mma() {
    const int p0 = blockIdx.x * 64;
    const int h  = blockIdx.y;
    const int n  = blockIdx.z;

    const uint32_t* __restrict__ qh = g_qh + ((size_t)n * 64 + h * 16) * SK;
    const uint32_t* __restrict__ kp = g_kk + ((size_t)n * 64 + h * 16) * SK;
    const uint32_t* __restrict__ vp = g_vv + ((size_t)n * 128 + h * 32) * (SK / 2);

    __shared__ uint32_t qsh[16 * QP2];
    __shared__ uint32_t ksh[16 * KP];
    __shared__ uint32_t vsh[32 * VP];

    const int tid  = threadIdx.x;
    const int lane = tid & 31;
    const int w    = tid >> 5;

    // ---- stage Q (pure copy): 16 cpairs x 64 queries ----
#pragma unroll
    for (int t2 = 0; t2 < 2; t2++) {
        int idx = tid + t2 * 128;           // 0..255 uint4 tasks
        int cp = idx >> 4, q4 = (idx & 15) * 4;
        *(uint4*)&qsh[cp * QP2 + q4] = *(const uint4*)&qh[(size_t)cp * SK + p0 + q4];
    }
    __syncthreads();

    uint32_t qf[2][4];
#pragma unroll
    for (int ks = 0; ks < 2; ks++) {
        int row = w * 16 + (lane >> 2);
        int cp = (lane & 3) + ks * 8;
        qf[ks][0] = qsh[cp * QP2 + row];
        qf[ks][1] = qsh[cp * QP2 + row + 8];
        qf[ks][2] = qsh[(cp + 4) * QP2 + row];
        qf[ks][3] = qsh[(cp + 4) * QP2 + row + 8];
    }

    float oacc[4][4];
#pragma unroll
    for (int nt = 0; nt < 4; nt++)
#pragma unroll
        for (int t = 0; t < 4; t++) oacc[nt][t] = 0.f;
    float rowm[2] = {-1e30f, -1e30f};
    float rowl[2] = {0.f, 0.f};

    const float SC2 = 0.17677669529663687f * 1.4426950408889634f;

    for (int k0 = 0; k0 < SK; k0 += 64) {
        // ---- stage K/V (pure copies) ----
#pragma unroll
        for (int t2 = 0; t2 < 2; t2++) {
            int idx = tid + t2 * 128;
            int cp = idx >> 4, k4 = (idx & 15) * 4;
            *(uint4*)&ksh[cp * KP + k4] = *(const uint4*)&kp[(size_t)cp * SK + k0 + k4];
            int c = idx >> 3, p4 = (idx & 7) * 4;
            *(uint4*)&vsh[c * VP + p4] = *(const uint4*)&vp[(size_t)c * (SK / 2) + (k0 >> 1) + p4];
        }
        __syncthreads();

        // ---- S = Q K^T (warp: 16q x 64k) ----
        float sacc[8][4];
#pragma unroll
        for (int in = 0; in < 8; in++)
#pragma unroll
            for (int t = 0; t < 4; t++) sacc[in][t] = 0.f;

#pragma unroll
        for (int ks = 0; ks < 2; ks++) {
            uint32_t bh[8][2];
#pragma unroll
            for (int in = 0; in < 8; in++) {
                int cp = (lane & 3) + ks * 8;
                int ky = in * 8 + (lane >> 2);
                bh[in][0] = ksh[cp * KP + ky];
                bh[in][1] = ksh[(cp + 4) * KP + ky];
            }
#pragma unroll
            for (int in = 0; in < 8; in++)
                mma_f16(sacc[in], qf[ks], bh[in][0], bh[in][1]);
        }

        // ---- online softmax ----
#pragma unroll
        for (int rs = 0; rs < 2; rs++) {
            float mx = rowm[rs];
#pragma unroll
            for (int in = 0; in < 8; in++)
                mx = fmaxf(mx, fmaxf(sacc[in][rs * 2], sacc[in][rs * 2 + 1]));
            mx = fmaxf(mx, __shfl_xor_sync(0xffffffffu, mx, 1));
            mx = fmaxf(mx, __shfl_xor_sync(0xffffffffu, mx, 2));
            float corr = ex2f((rowm[rs] - mx) * SC2);
            rowm[rs] = mx;
            float sum = 0.f;
#pragma unroll
            for (int in = 0; in < 8; in++) {
                float e0 = ex2f((sacc[in][rs * 2] - mx) * SC2);
                float e1 = ex2f((sacc[in][rs * 2 + 1] - mx) * SC2);
                sacc[in][rs * 2] = e0;
                sacc[in][rs * 2 + 1] = e1;
                sum += e0 + e1;
            }
            rowl[rs] = rowl[rs] * corr + sum;
#pragma unroll
            for (int nt = 0; nt < 4; nt++) {
                oacc[nt][rs * 2] *= corr;
                oacc[nt][rs * 2 + 1] *= corr;
            }
        }

        // ---- O += P V^T (single term) ----
#pragma unroll
        for (int ks4 = 0; ks4 < 4; ks4++) {
            uint32_t pf[4];
            {
                const float* t0 = sacc[2 * ks4];
                const float* t1 = sacc[2 * ks4 + 1];
                pf[0] = pack1(t0[0], t0[1]);
                pf[1] = pack1(t0[2], t0[3]);
                pf[2] = pack1(t1[0], t1[1]);
                pf[3] = pack1(t1[2], t1[3]);
            }
            uint32_t bh[4][2];
#pragma unroll
            for (int nt = 0; nt < 4; nt++) {
                int c  = nt * 8 + (lane >> 2);
                int kq = (lane & 3) + ks4 * 8;
                bh[nt][0] = vsh[c * VP + kq];
                bh[nt][1] = vsh[c * VP + kq + 4];
            }
#pragma unroll
            for (int nt = 0; nt < 4; nt++)
                mma_f16(oacc[nt], pf, bh[nt][0], bh[nt][1]);
        }
        __syncthreads();
    }

    // ---- finalize: 1/l, pack fp16, store ----
#pragma unroll
    for (int rs = 0; rs < 2; rs++) {
        float l = rowl[rs];
        l += __shfl_xor_sync(0xffffffffu, l, 1);
        l += __shfl_xor_sync(0xffffffffu, l, 2);
        float inv = 1.f / l;
#pragma unroll
        for (int nt = 0; nt < 4; nt++) {
            oacc[nt][rs * 2] *= inv;
            oacc[nt][rs * 2 + 1] *= inv;
        }
    }
    uint32_t* __restrict__ xout = g_x16 + (size_t)n * SQ * 64 + h * 16;
#pragma unroll
    for (int nt = 0; nt < 4; nt++) {
        int row = p0 + w * 16 + (lane >> 2);
        int wc = nt * 4 + (lane & 3);
        xout[(size_t)row * 64 + wc]       = pack1(oacc[nt][0], oacc[nt][1]);
        xout[(size_t)(row + 8) * 64 + wc] = pack1(oacc[nt][2], oacc[nt][3]);
    }
}

// ---------------------------------------------------------------------------
extern "C" void kernel_launch(void* const* d_in, const int* in_sizes, int n_in,
                              void* d_out, int out_size) {
    const float* query    = (const float*)d_in[0];
    const float* key_feat = (const float*)d_in[1];
    const float* Wq       = (const float*)d_in[2];
    const float* Wk       = (const float*)d_in[3];
    const float* Wv       = (const float*)d_in[4];
    const float* Wup      = (const float*)d_in[5];
    float* out            = (float*)d_out;

    dim3 g1(SK / 128, NB, 3);
    proj_all<<<g1, 512>>>(query, key_feat, Wq, Wk, Wv);

    dim3 g2(SQ / 64, NH, NB);
    attn_mma<<<g2, 128>>>();

    dim3 g3(DIM / 128, (NB * SQ) / 128);
    up_mma<<<g3, 512>>>(Wup, out);
}

// round 16
// speedup vs baseline: 1.9670x; 1.0533x over previous
#include <cuda_runtime.h>
#include <cuda_fp16.h>
#include <cstdint>

#define SQ 2048
#define SK 2048
#define NB 8
#define DIM 1024
#define INNER 128
#define NH 4
#define HD 32

// Scratch (allocation-free): packed-fp16 projections + packed-fp16 attn output
__device__ uint32_t g_qh[(size_t)NB * 64 * SK];        // q     [n][cpair][s]
__device__ uint32_t g_kk[(size_t)NB * 64 * SK];        // k     [n][cpair][s]
__device__ uint32_t g_vv[(size_t)NB * 128 * (SK / 2)]; // v     [n][c][spair]
__device__ uint32_t g_x16[(size_t)NB * SQ * 64];       // x     [n*SQ+p][epair]
__device__ uint32_t g_w16[(size_t)DIM * 64];           // Wup   [d][epair]

// ============================ warp-MMA helpers =============================
__device__ __forceinline__ uint32_t smem_u32(const void* p) {
    return (uint32_t)__cvta_generic_to_shared(p);
}
__device__ __forceinline__ void ldsm_x4(uint32_t& r0, uint32_t& r1,
                                        uint32_t& r2, uint32_t& r3, uint32_t addr) {
    asm volatile("ldmatrix.sync.aligned.m8n8.x4.shared.b16 {%0,%1,%2,%3}, [%4];"
                 : "=r"(r0), "=r"(r1), "=r"(r2), "=r"(r3) : "r"(addr));
}
__device__ __forceinline__ void mma_f16(float* d, const uint32_t* a,
                                        uint32_t b0, uint32_t b1) {
    asm volatile(
        "mma.sync.aligned.m16n8k16.row.col.f32.f16.f16.f32 "
        "{%0,%1,%2,%3}, {%4,%5,%6,%7}, {%8,%9}, {%0,%1,%2,%3};"
        : "+f"(d[0]), "+f"(d[1]), "+f"(d[2]), "+f"(d[3])
        : "r"(a[0]), "r"(a[1]), "r"(a[2]), "r"(a[3]), "r"(b0), "r"(b1));
}
__device__ __forceinline__ float ex2f(float x) {
    float y;
    asm("ex2.approx.f32 %0, %1;" : "=f"(y) : "f"(x));
    return y;
}
// packed fp16x2 exp2 of two fp32 args: returns {lo=exp2(lo), hi=exp2(hi)}
__device__ __forceinline__ uint32_t ex2h2(float lo, float hi) {
    uint32_t h, r;
    asm("cvt.rn.f16x2.f32 %0, %1, %2;" : "=r"(h) : "f"(hi), "f"(lo));
    asm("ex2.approx.f16x2 %0, %1;" : "=r"(r) : "r"(h));
    return r;
}

__device__ __forceinline__ void split2(float x, float y, uint32_t& hi, uint32_t& lo) {
    __half hx = __float2half_rn(x);
    __half hy = __float2half_rn(y);
    __half lx = __float2half_rn(x - __half2float(hx));
    __half ly = __float2half_rn(y - __half2float(hy));
    hi = (uint32_t)__half_as_ushort(hx) | ((uint32_t)__half_as_ushort(hy) << 16);
    lo = (uint32_t)__half_as_ushort(lx) | ((uint32_t)__half_as_ushort(ly) << 16);
}
__device__ __forceinline__ uint32_t pack1(float x, float y) {
    return (uint32_t)__half_as_ushort(__float2half_rn(x))
         | ((uint32_t)__half_as_ushort(__float2half_rn(y)) << 16);
}

// ===================== GEMM template (512 threads, 16 warps) ===============
// 2-term: A split (hi/lo), B single-rounded -> AhBh + AlBh.
#define ROWB   80
#define TILE   (128 * ROWB)
#define SM_AH  0
#define SM_AL  TILE
#define SM_BH  (2 * TILE)

__device__ __forceinline__ void cvt_store2(const float4* va, const float4* vb,
                                           char* buf, int rbase, int seg) {
#pragma unroll
    for (int p = 0; p < 2; p++) {
        int off = (rbase + 64 * p) * ROWB + seg * 8;
        uint2 h, l;
        split2(va[p].x, va[p].y, h.x, l.x);
        split2(va[p].z, va[p].w, h.y, l.y);
        *(uint2*)(buf + SM_AH + off) = h;
        *(uint2*)(buf + SM_AL + off) = l;
        h.x = pack1(vb[p].x, vb[p].y);
        h.y = pack1(vb[p].z, vb[p].w);
        *(uint2*)(buf + SM_BH + off) = h;
    }
}

template <int KCHUNKS>
__device__ __forceinline__ void mma_gemm(const float* __restrict__ A, size_t lda,
                                         const float* __restrict__ B, size_t ldb,
                                         float acc[2][4][4], char* sm) {
    const int tid  = threadIdx.x;
    const int lane = tid & 31;
    const int wid  = tid >> 5;
    const int wm   = (wid >> 2) * 32;
    const int wn   = (wid & 3) * 32;
    const int seg  = tid & 7;
    const int rbase = tid >> 3;
    const uint32_t smb = smem_u32(sm);

    float4 va[2], vb[2];
#pragma unroll
    for (int p = 0; p < 2; p++) {
        va[p] = *(const float4*)(A + (size_t)(rbase + 64 * p) * lda + seg * 4);
        vb[p] = *(const float4*)(B + (size_t)(rbase + 64 * p) * ldb + seg * 4);
    }

    for (int c = 0; c < KCHUNKS; c++) {
        cvt_store2(va, vb, sm, rbase, seg);
        __syncthreads();

        if (c + 1 < KCHUNKS) {
            int co = (c + 1) * 32;
#pragma unroll
            for (int p = 0; p < 2; p++) {
                va[p] = *(const float4*)(A + (size_t)(rbase + 64 * p) * lda + co + seg * 4);
                vb[p] = *(const float4*)(B + (size_t)(rbase + 64 * p) * ldb + co + seg * 4);
            }
        }

#pragma unroll
        for (int ks = 0; ks < 2; ks++) {
            const int kb = ks * 32;
            uint32_t ah[2][4], al[2][4];
#pragma unroll
            for (int im = 0; im < 2; im++) {
                uint32_t ra = smb + (wm + im * 16 + (lane & 15)) * ROWB + (lane >> 4) * 16 + kb;
                ldsm_x4(ah[im][0], ah[im][1], ah[im][2], ah[im][3], ra + SM_AH);
                ldsm_x4(al[im][0], al[im][1], al[im][2], al[im][3], ra + SM_AL);
            }
            uint32_t bh[2][4];
#pragma unroll
            for (int i2 = 0; i2 < 2; i2++) {
                uint32_t rb = smb + (wn + i2 * 16 + (lane & 15)) * ROWB + (lane >> 4) * 16 + kb;
                ldsm_x4(bh[i2][0], bh[i2][1], bh[i2][2], bh[i2][3], rb + SM_BH);
            }
#pragma unroll
            for (int im = 0; im < 2; im++) {
#pragma unroll
                for (int in = 0; in < 4; in++) {
                    int i2 = in >> 1, sub = in & 1;
                    mma_f16(acc[im][in], ah[im], bh[i2][sub], bh[i2][sub + 2]);
                    mma_f16(acc[im][in], al[im], bh[i2][sub], bh[i2][sub + 2]);
                }
            }
        }
        __syncthreads();
    }
}

// Merged projection (all 2-term): sel 0 = q, 1 = k, 2 = v.
__global__ __launch_bounds__(512, 1)
void proj_all(const float* __restrict__ query, const float* __restrict__ key_feat,
              const float* __restrict__ Wq, const float* __restrict__ Wk,
              const float* __restrict__ Wv) {
    __shared__ __align__(16) char sm[3 * TILE];
    const int s0  = blockIdx.x * 128;
    const int n   = blockIdx.y;
    const int sel = blockIdx.z;

    const int lane = threadIdx.x & 31, wid = threadIdx.x >> 5;
    const int wm = (wid >> 2) * 32, wn = (wid & 3) * 32;

    const float* __restrict__ X = (sel == 0) ? query : key_feat;
    const float* __restrict__ W = (sel == 0) ? Wq : (sel == 1 ? Wk : Wv);

    float acc[2][4][4];
#pragma unroll
    for (int i = 0; i < 2; i++)
#pragma unroll
        for (int j = 0; j < 4; j++)
#pragma unroll
            for (int t = 0; t < 4; t++) acc[i][j][t] = 0.f;

    mma_gemm<32>(W, DIM, X + (size_t)s0 * (NB * DIM) + (size_t)n * DIM,
                 (size_t)NB * DIM, acc, sm);

    if (sel == 2) {
#pragma unroll
        for (int im = 0; im < 2; im++) {
#pragma unroll
            for (int in = 0; in < 4; in++) {
#pragma unroll
                for (int half = 0; half < 2; half++) {
                    int row = wm + im * 16 + (lane >> 2) + half * 8;
                    int s = s0 + wn + in * 8 + (lane & 3) * 2;
                    g_vv[((size_t)n * 128 + row) * (SK / 2) + (s >> 1)] =
                        pack1(acc[im][in][2 * half], acc[im][in][2 * half + 1]);
                }
            }
        }
    } else {
        uint32_t* __restrict__ dst = (sel == 0) ? g_qh : g_kk;
        const bool even = ((lane >> 2) & 1) == 0;
#pragma unroll
        for (int im = 0; im < 2; im++) {
#pragma unroll
            for (int in = 0; in < 4; in++) {
#pragma unroll
                for (int half = 0; half < 2; half++) {
                    int row = wm + im * 16 + (lane >> 2) + half * 8;
                    int s = s0 + wn + in * 8 + (lane & 3) * 2;
                    int cp = row >> 1;
                    size_t base = ((size_t)n * 64 + cp) * SK + s;
                    uint32_t w = pack1(acc[im][in][2 * half], acc[im][in][2 * half + 1]);
                    uint32_t wp = __shfl_xor_sync(0xffffffffu, w, 4);
                    if (even) {
                        uint2 o;
                        o.x = (w & 0xFFFFu) | (wp << 16);
                        o.y = (w >> 16) | (wp & 0xFFFF0000u);
                        *(uint2*)&dst[base] = o;
                    }
                }
            }
        }
    }
}

// Wup fp32 -> packed fp16 (one-time, removes 8x redundant conversion in up)
__global__ __launch_bounds__(256, 4)
void cvt_wup(const float* __restrict__ Wup) {
    int idx = blockIdx.x * 256 + threadIdx.x;   // 16384 threads, uint4 each
    const float* src = Wup + (size_t)idx * 8;
    float4 f0 = *(const float4*)src;
    float4 f1 = *(const float4*)(src + 4);
    uint4 o;
    o.x = pack1(f0.x, f0.y);
    o.y = pack1(f0.z, f0.w);
    o.z = pack1(f1.x, f1.y);
    o.w = pack1(f1.z, f1.w);
    *(uint4*)&g_w16[(size_t)idx * 4] = o;
}

// up: 1-term fp16 GEMM. A = g_x16, B = g_w16 (both pre-packed fp16 copies).
#define USM_A 0
#define USM_B TILE

__global__ __launch_bounds__(512, 1)
void up_mma(float* __restrict__ out) {
    __shared__ __align__(16) char sm[2 * TILE];
    const int d0 = blockIdx.x * 128;
    const int r0 = blockIdx.y * 128;

    const int tid  = threadIdx.x;
    const int lane = tid & 31;
    const int wid  = tid >> 5;
    const int wm   = (wid >> 2) * 32;
    const int wn   = (wid & 3) * 32;
    const uint32_t smb = smem_u32(sm);

    float acc[2][4][4];
#pragma unroll
    for (int i = 0; i < 2; i++)
#pragma unroll
        for (int j = 0; j < 4; j++)
#pragma unroll
            for (int t = 0; t < 4; t++) acc[i][j][t] = 0.f;

    const int arow = tid >> 2, aseg = tid & 3;

    for (int c = 0; c < 4; c++) {
        *(uint4*)(sm + USM_A + arow * ROWB + aseg * 16) =
            *(const uint4*)&g_x16[(size_t)(r0 + arow) * 64 + c * 16 + aseg * 4];
        *(uint4*)(sm + USM_B + arow * ROWB + aseg * 16) =
            *(const uint4*)&g_w16[(size_t)(d0 + arow) * 64 + c * 16 + aseg * 4];
        __syncthreads();

#pragma unroll
        for (int ks = 0; ks < 2; ks++) {
            const int kb = ks * 32;
            uint32_t ah[2][4];
#pragma unroll
            for (int im = 0; im < 2; im++) {
                uint32_t ra = smb + USM_A + (wm + im * 16 + (lane & 15)) * ROWB + (lane >> 4) * 16 + kb;
                ldsm_x4(ah[im][0], ah[im][1], ah[im][2], ah[im][3], ra);
            }
            uint32_t bh[2][4];
#pragma unroll
            for (int i2 = 0; i2 < 2; i2++) {
                uint32_t rb = smb + USM_B + (wn + i2 * 16 + (lane & 15)) * ROWB + (lane >> 4) * 16 + kb;
                ldsm_x4(bh[i2][0], bh[i2][1], bh[i2][2], bh[i2][3], rb);
            }
#pragma unroll
            for (int im = 0; im < 2; im++)
#pragma unroll
                for (int in = 0; in < 4; in++) {
                    int i2 = in >> 1, sub = in & 1;
                    mma_f16(acc[im][in], ah[im], bh[i2][sub], bh[i2][sub + 2]);
                }
        }
        __syncthreads();
    }

#pragma unroll
    for (int im = 0; im < 2; im++) {
#pragma unroll
        for (int in = 0; in < 4; in++) {
            int d = d0 + wn + in * 8 + (lane & 3) * 2;
#pragma unroll
            for (int half = 0; half < 2; half++) {
                int r = r0 + wm + im * 16 + (lane >> 2) + half * 8;
                int nn = r >> 11, pp = r & 2047;
                *(float2*)&out[((size_t)pp * NB + nn) * DIM + d] =
                    make_float2(acc[im][in][half * 2], acc[im][in][half * 2 + 1]);
            }
        }
    }
}

// ===================== Flash attention on HMMA =============================
// Query tile 64/CTA (warp tile m16), occupancy 4; fp16x2 softmax exps.
#define QP2 72
#define KP 72
#define VP 36

__global__ __launch_bounds__(128, 4)
void attn_mma() {
    const int p0 = blockIdx.x * 64;
    const int h  = blockIdx.y;
    const int n  = blockIdx.z;

    const uint32_t* __restrict__ qh = g_qh + ((size_t)n * 64 + h * 16) * SK;
    const uint32_t* __restrict__ kp = g_kk + ((size_t)n * 64 + h * 16) * SK;
    const uint32_t* __restrict__ vp = g_vv + ((size_t)n * 128 + h * 32) * (SK / 2);

    __shared__ uint32_t qsh[16 * QP2];
    __shared__ uint32_t ksh[16 * KP];
    __shared__ uint32_t vsh[32 * VP];

    const int tid  = threadIdx.x;
    const int lane = tid & 31;
    const int w    = tid >> 5;

    // ---- stage Q (pure copy): 16 cpairs x 64 queries ----
#pragma unroll
    for (int t2 = 0; t2 < 2; t2++) {
        int idx = tid + t2 * 128;
        int cp = idx >> 4, q4 = (idx & 15) * 4;
        *(uint4*)&qsh[cp * QP2 + q4] = *(const uint4*)&qh[(size_t)cp * SK + p0 + q4];
    }
    __syncthreads();

    uint32_t qf[2][4];
#pragma unroll
    for (int ks = 0; ks < 2; ks++) {
        int row = w * 16 + (lane >> 2);
        int cp = (lane & 3) + ks * 8;
        qf[ks][0] = qsh[cp * QP2 + row];
        qf[ks][1] = qsh[cp * QP2 + row + 8];
        qf[ks][2] = qsh[(cp + 4) * QP2 + row];
        qf[ks][3] = qsh[(cp + 4) * QP2 + row + 8];
    }

    float oacc[4][4];
#pragma unroll
    for (int nt = 0; nt < 4; nt++)
#pragma unroll
        for (int t = 0; t < 4; t++) oacc[nt][t] = 0.f;
    float rowm[2] = {-1e30f, -1e30f};
    float rowl[2] = {0.f, 0.f};

    const float SC2 = 0.17677669529663687f * 1.4426950408889634f;

    for (int k0 = 0; k0 < SK; k0 += 64) {
        // ---- stage K/V (pure copies) ----
#pragma unroll
        for (int t2 = 0; t2 < 2; t2++) {
            int idx = tid + t2 * 128;
            int cp = idx >> 4, k4 = (idx & 15) * 4;
            *(uint4*)&ksh[cp * KP + k4] = *(const uint4*)&kp[(size_t)cp * SK + k0 + k4];
            int c = idx >> 3, p4 = (idx & 7) * 4;
            *(uint4*)&vsh[c * VP + p4] = *(const uint4*)&vp[(size_t)c * (SK / 2) + (k0 >> 1) + p4];
        }
        __syncthreads();

        // ---- S = Q K^T (warp: 16q x 64k) ----
        float sacc[8][4];
#pragma unroll
        for (int in = 0; in < 8; in++)
#pragma unroll
            for (int t = 0; t < 4; t++) sacc[in][t] = 0.f;

#pragma unroll
        for (int ks = 0; ks < 2; ks++) {
            uint32_t bh[8][2];
#pragma unroll
            for (int in = 0; in < 8; in++) {
                int cp = (lane & 3) + ks * 8;
                int ky = in * 8 + (lane >> 2);
                bh[in][0] = ksh[cp * KP + ky];
                bh[in][1] = ksh[(cp + 4) * KP + ky];
            }
#pragma unroll
            for (int in = 0; in < 8; in++)
                mma_f16(sacc[in], qf[ks], bh[in][0], bh[in][1]);
        }

        // ---- online softmax: corr in fp32 MUFU, P exps in fp16x2 MUFU.
        //      packed exp pairs overwrite sacc[in][rs] (dead storage). ----
#pragma unroll
        for (int rs = 0; rs < 2; rs++) {
            float mx = rowm[rs];
#pragma unroll
            for (int in = 0; in < 8; in++)
                mx = fmaxf(mx, fmaxf(sacc[in][rs * 2], sacc[in][rs * 2 + 1]));
            mx = fmaxf(mx, __shfl_xor_sync(0xffffffffu, mx, 1));
            mx = fmaxf(mx, __shfl_xor_sync(0xffffffffu, mx, 2));
            float corr = ex2f((rowm[rs] - mx) * SC2);
            rowm[rs] = mx;
            float sum = 0.f;
#pragma unroll
            for (int in = 0; in < 8; in++) {
                float a0 = (sacc[in][rs * 2] - mx) * SC2;
                float a1 = (sacc[in][rs * 2 + 1] - mx) * SC2;
                uint32_t ph = ex2h2(a0, a1);
                float2 fv = __half22float2(*reinterpret_cast<__half2*>(&ph));
                sum += fv.x + fv.y;
                sacc[in][rs] = __uint_as_float(ph);
            }
            rowl[rs] = rowl[rs] * corr + sum;
#pragma unroll
            for (int nt = 0; nt < 4; nt++) {
                oacc[nt][rs * 2] *= corr;
                oacc[nt][rs * 2 + 1] *= corr;
            }
        }

        // ---- O += P V^T (P fragments read from packed sacc slots) ----
#pragma unroll
        for (int ks4 = 0; ks4 < 4; ks4++) {
            uint32_t pf[4];
            pf[0] = __float_as_uint(sacc[2 * ks4][0]);
            pf[1] = __float_as_uint(sacc[2 * ks4][1]);
            pf[2] = __float_as_uint(sacc[2 * ks4 + 1][0]);
            pf[3] = __float_as_uint(sacc[2 * ks4 + 1][1]);
            uint32_t bh[4][2];
#pragma unroll
            for (int nt = 0; nt < 4; nt++) {
                int c  = nt * 8 + (lane >> 2);
                int kq = (lane & 3) + ks4 * 8;
                bh[nt][0] = vsh[c * VP + kq];
                bh[nt][1] = vsh[c * VP + kq + 4];
            }
#pragma unroll
            for (int nt = 0; nt < 4; nt++)
                mma_f16(oacc[nt], pf, bh[nt][0], bh[nt][1]);
        }
        __syncthreads();
    }

    // ---- finalize: 1/l, pack fp16, store ----
#pragma unroll
    for (int rs = 0; rs < 2; rs++) {
        float l = rowl[rs];
        l += __shfl_xor_sync(0xffffffffu, l, 1);
        l += __shfl_xor_sync(0xffffffffu, l, 2);
        float inv = 1.f / l;
#pragma unroll
        for (int nt = 0; nt < 4; nt++) {
            oacc[nt][rs * 2] *= inv;
            oacc[nt][rs * 2 + 1] *= inv;
        }
    }
    uint32_t* __restrict__ xout = g_x16 + (size_t)n * SQ * 64 + h * 16;
#pragma unroll
    for (int nt = 0; nt < 4; nt++) {
        int row = p0 + w * 16 + (lane >> 2);
        int wc = nt * 4 + (lane & 3);
        xout[(size_t)row * 64 + wc]       = pack1(oacc[nt][0], oacc[nt][1]);
        xout[(size_t)(row + 8) * 64 + wc] = pack1(oacc[nt][2], oacc[nt][3]);
    }
}

// ---------------------------------------------------------------------------
extern "C" void kernel_launch(void* const* d_in, const int* in_sizes, int n_in,
                              void* d_out, int out_size) {
    const float* query    = (const float*)d_in[0];
    const float* key_feat = (const float*)d_in[1];
    const float* Wq       = (const float*)d_in[2];
    const float* Wk       = (const float*)d_in[3];
    const float* Wv       = (const float*)d_in[4];
    const float* Wup      = (const float*)d_in[5];
    float* out            = (float*)d_out;

    cvt_wup<<<64, 256>>>(Wup);

    dim3 g1(SK / 128, NB, 3);
    proj_all<<<g1, 512>>>(query, key_feat, Wq, Wk, Wv);

    dim3 g2(SQ / 64, NH, NB);
    attn_mma<<<g2, 128>>>();

    dim3 g3(DIM / 128, (NB * SQ) / 128);
    up_mma<<<g3, 512>>>(out);
}

// round 17
// speedup vs baseline: 2.0240x; 1.0290x over previous
#include <cuda_runtime.h>
#include <cuda_fp16.h>
#include <cstdint>

#define SQ 2048
#define SK 2048
#define NB 8
#define DIM 1024
#define INNER 128
#define NH 4
#define HD 32

// Scratch (allocation-free): packed-fp16 projections + packed-fp16 attn output
__device__ uint32_t g_qh[(size_t)NB * 64 * SK];        // q     [n][cpair][s]
__device__ uint32_t g_kk[(size_t)NB * 64 * SK];        // k     [n][cpair][s]
__device__ uint32_t g_vv[(size_t)NB * 128 * (SK / 2)]; // v     [n][c][spair]
__device__ uint32_t g_x16[(size_t)NB * SQ * 64];       // x     [n*SQ+p][epair]
__device__ uint32_t g_w16[(size_t)DIM * 64];           // Wup   [d][epair]

// ============================ warp-MMA helpers =============================
__device__ __forceinline__ uint32_t smem_u32(const void* p) {
    return (uint32_t)__cvta_generic_to_shared(p);
}
__device__ __forceinline__ void ldsm_x4(uint32_t& r0, uint32_t& r1,
                                        uint32_t& r2, uint32_t& r3, uint32_t addr) {
    asm volatile("ldmatrix.sync.aligned.m8n8.x4.shared.b16 {%0,%1,%2,%3}, [%4];"
                 : "=r"(r0), "=r"(r1), "=r"(r2), "=r"(r3) : "r"(addr));
}
__device__ __forceinline__ void mma_f16(float* d, const uint32_t* a,
                                        uint32_t b0, uint32_t b1) {
    asm volatile(
        "mma.sync.aligned.m16n8k16.row.col.f32.f16.f16.f32 "
        "{%0,%1,%2,%3}, {%4,%5,%6,%7}, {%8,%9}, {%0,%1,%2,%3};"
        : "+f"(d[0]), "+f"(d[1]), "+f"(d[2]), "+f"(d[3])
        : "r"(a[0]), "r"(a[1]), "r"(a[2]), "r"(a[3]), "r"(b0), "r"(b1));
}
__device__ __forceinline__ float ex2f(float x) {
    float y;
    asm("ex2.approx.f32 %0, %1;" : "=f"(y) : "f"(x));
    return y;
}
// packed fp16x2 exp2 of two fp32 args: returns {lo=exp2(lo), hi=exp2(hi)}
__device__ __forceinline__ uint32_t ex2h2(float lo, float hi) {
    uint32_t h, r;
    asm("cvt.rn.f16x2.f32 %0, %1, %2;" : "=r"(h) : "f"(hi), "f"(lo));
    asm("ex2.approx.f16x2 %0, %1;" : "=r"(r) : "r"(h));
    return r;
}

__device__ __forceinline__ void split2(float x, float y, uint32_t& hi, uint32_t& lo) {
    __half hx = __float2half_rn(x);
    __half hy = __float2half_rn(y);
    __half lx = __float2half_rn(x - __half2float(hx));
    __half ly = __float2half_rn(y - __half2float(hy));
    hi = (uint32_t)__half_as_ushort(hx) | ((uint32_t)__half_as_ushort(hy) << 16);
    lo = (uint32_t)__half_as_ushort(lx) | ((uint32_t)__half_as_ushort(ly) << 16);
}
__device__ __forceinline__ uint32_t pack1(float x, float y) {
    return (uint32_t)__half_as_ushort(__float2half_rn(x))
         | ((uint32_t)__half_as_ushort(__float2half_rn(y)) << 16);
}

// ===================== GEMM template (512 threads, 16 warps) ===============
// 2-term: A split (hi/lo), B single-rounded -> AhBh + AlBh.
#define ROWB   80
#define TILE   (128 * ROWB)
#define SM_AH  0
#define SM_AL  TILE
#define SM_BH  (2 * TILE)

__device__ __forceinline__ void cvt_store2(const float4* va, const float4* vb,
                                           char* buf, int rbase, int seg) {
#pragma unroll
    for (int p = 0; p < 2; p++) {
        int off = (rbase + 64 * p) * ROWB + seg * 8;
        uint2 h, l;
        split2(va[p].x, va[p].y, h.x, l.x);
        split2(va[p].z, va[p].w, h.y, l.y);
        *(uint2*)(buf + SM_AH + off) = h;
        *(uint2*)(buf + SM_AL + off) = l;
        h.x = pack1(vb[p].x, vb[p].y);
        h.y = pack1(vb[p].z, vb[p].w);
        *(uint2*)(buf + SM_BH + off) = h;
    }
}

template <int KCHUNKS>
__device__ __forceinline__ void mma_gemm(const float* __restrict__ A, size_t lda,
                                         const float* __restrict__ B, size_t ldb,
                                         float acc[2][4][4], char* sm) {
    const int tid  = threadIdx.x;
    const int lane = tid & 31;
    const int wid  = tid >> 5;
    const int wm   = (wid >> 2) * 32;
    const int wn   = (wid & 3) * 32;
    const int seg  = tid & 7;
    const int rbase = tid >> 3;
    const uint32_t smb = smem_u32(sm);

    float4 va[2], vb[2];
#pragma unroll
    for (int p = 0; p < 2; p++) {
        va[p] = *(const float4*)(A + (size_t)(rbase + 64 * p) * lda + seg * 4);
        vb[p] = *(const float4*)(B + (size_t)(rbase + 64 * p) * ldb + seg * 4);
    }

    for (int c = 0; c < KCHUNKS; c++) {
        cvt_store2(va, vb, sm, rbase, seg);
        __syncthreads();

        if (c + 1 < KCHUNKS) {
            int co = (c + 1) * 32;
#pragma unroll
            for (int p = 0; p < 2; p++) {
                va[p] = *(const float4*)(A + (size_t)(rbase + 64 * p) * lda + co + seg * 4);
                vb[p] = *(const float4*)(B + (size_t)(rbase + 64 * p) * ldb + co + seg * 4);
            }
        }

#pragma unroll
        for (int ks = 0; ks < 2; ks++) {
            const int kb = ks * 32;
            uint32_t ah[2][4], al[2][4];
#pragma unroll
            for (int im = 0; im < 2; im++) {
                uint32_t ra = smb + (wm + im * 16 + (lane & 15)) * ROWB + (lane >> 4) * 16 + kb;
                ldsm_x4(ah[im][0], ah[im][1], ah[im][2], ah[im][3], ra + SM_AH);
                ldsm_x4(al[im][0], al[im][1], al[im][2], al[im][3], ra + SM_AL);
            }
            uint32_t bh[2][4];
#pragma unroll
            for (int i2 = 0; i2 < 2; i2++) {
                uint32_t rb = smb + (wn + i2 * 16 + (lane & 15)) * ROWB + (lane >> 4) * 16 + kb;
                ldsm_x4(bh[i2][0], bh[i2][1], bh[i2][2], bh[i2][3], rb + SM_BH);
            }
#pragma unroll
            for (int im = 0; im < 2; im++) {
#pragma unroll
                for (int in = 0; in < 4; in++) {
                    int i2 = in >> 1, sub = in & 1;
                    mma_f16(acc[im][in], ah[im], bh[i2][sub], bh[i2][sub + 2]);
                    mma_f16(acc[im][in], al[im], bh[i2][sub], bh[i2][sub + 2]);
                }
            }
        }
        __syncthreads();
    }
}

// Merged projection (all 2-term): sel 0 = q, 1 = k, 2 = v.
__global__ __launch_bounds__(512, 1)
void proj_all(const float* __restrict__ query, const float* __restrict__ key_feat,
              const float* __restrict__ Wq, const float* __restrict__ Wk,
              const float* __restrict__ Wv) {
    __shared__ __align__(16) char sm[3 * TILE];
    const int s0  = blockIdx.x * 128;
    const int n   = blockIdx.y;
    const int sel = blockIdx.z;

    const int lane = threadIdx.x & 31, wid = threadIdx.x >> 5;
    const int wm = (wid >> 2) * 32, wn = (wid & 3) * 32;

    const float* __restrict__ X = (sel == 0) ? query : key_feat;
    const float* __restrict__ W = (sel == 0) ? Wq : (sel == 1 ? Wk : Wv);

    float acc[2][4][4];
#pragma unroll
    for (int i = 0; i < 2; i++)
#pragma unroll
        for (int j = 0; j < 4; j++)
#pragma unroll
            for (int t = 0; t < 4; t++) acc[i][j][t] = 0.f;

    mma_gemm<32>(W, DIM, X + (size_t)s0 * (NB * DIM) + (size_t)n * DIM,
                 (size_t)NB * DIM, acc, sm);

    if (sel == 2) {
#pragma unroll
        for (int im = 0; im < 2; im++) {
#pragma unroll
            for (int in = 0; in < 4; in++) {
#pragma unroll
                for (int half = 0; half < 2; half++) {
                    int row = wm + im * 16 + (lane >> 2) + half * 8;
                    int s = s0 + wn + in * 8 + (lane & 3) * 2;
                    g_vv[((size_t)n * 128 + row) * (SK / 2) + (s >> 1)] =
                        pack1(acc[im][in][2 * half], acc[im][in][2 * half + 1]);
                }
            }
        }
    } else {
        uint32_t* __restrict__ dst = (sel == 0) ? g_qh : g_kk;
        const bool even = ((lane >> 2) & 1) == 0;
#pragma unroll
        for (int im = 0; im < 2; im++) {
#pragma unroll
            for (int in = 0; in < 4; in++) {
#pragma unroll
                for (int half = 0; half < 2; half++) {
                    int row = wm + im * 16 + (lane >> 2) + half * 8;
                    int s = s0 + wn + in * 8 + (lane & 3) * 2;
                    int cp = row >> 1;
                    size_t base = ((size_t)n * 64 + cp) * SK + s;
                    uint32_t w = pack1(acc[im][in][2 * half], acc[im][in][2 * half + 1]);
                    uint32_t wp = __shfl_xor_sync(0xffffffffu, w, 4);
                    if (even) {
                        uint2 o;
                        o.x = (w & 0xFFFFu) | (wp << 16);
                        o.y = (w >> 16) | (wp & 0xFFFF0000u);
                        *(uint2*)&dst[base] = o;
                    }
                }
            }
        }
    }
}

// Wup fp32 -> packed fp16 (one-time, removes 8x redundant conversion in up)
__global__ __launch_bounds__(256, 4)
void cvt_wup(const float* __restrict__ Wup) {
    int idx = blockIdx.x * 256 + threadIdx.x;   // 16384 threads, uint4 each
    const float* src = Wup + (size_t)idx * 8;
    float4 f0 = *(const float4*)src;
    float4 f1 = *(const float4*)(src + 4);
    uint4 o;
    o.x = pack1(f0.x, f0.y);
    o.y = pack1(f0.z, f0.w);
    o.z = pack1(f1.x, f1.y);
    o.w = pack1(f1.z, f1.w);
    *(uint4*)&g_w16[(size_t)idx * 4] = o;
}

// up: 1-term fp16 GEMM. A = g_x16, B = g_w16 (both pre-packed fp16 copies).
// Register-prefetched chunks + occupancy 2 to hide L2 latency.
#define USM_A 0
#define USM_B TILE

__global__ __launch_bounds__(512, 2)
void up_mma(float* __restrict__ out) {
    __shared__ __align__(16) char sm[2 * TILE];
    const int d0 = blockIdx.x * 128;
    const int r0 = blockIdx.y * 128;

    const int tid  = threadIdx.x;
    const int lane = tid & 31;
    const int wid  = tid >> 5;
    const int wm   = (wid >> 2) * 32;
    const int wn   = (wid & 3) * 32;
    const uint32_t smb = smem_u32(sm);

    float acc[2][4][4];
#pragma unroll
    for (int i = 0; i < 2; i++)
#pragma unroll
        for (int j = 0; j < 4; j++)
#pragma unroll
            for (int t = 0; t < 4; t++) acc[i][j][t] = 0.f;

    const int arow = tid >> 2, aseg = tid & 3;
    const uint32_t* __restrict__ asrc = &g_x16[(size_t)(r0 + arow) * 64 + aseg * 4];
    const uint32_t* __restrict__ bsrc = &g_w16[(size_t)(d0 + arow) * 64 + aseg * 4];

    uint4 pa = *(const uint4*)asrc;
    uint4 pb = *(const uint4*)bsrc;

    for (int c = 0; c < 4; c++) {
        *(uint4*)(sm + USM_A + arow * ROWB + aseg * 16) = pa;
        *(uint4*)(sm + USM_B + arow * ROWB + aseg * 16) = pb;
        __syncthreads();

        if (c < 3) {
            pa = *(const uint4*)(asrc + (c + 1) * 16);
            pb = *(const uint4*)(bsrc + (c + 1) * 16);
        }

#pragma unroll
        for (int ks = 0; ks < 2; ks++) {
            const int kb = ks * 32;
            uint32_t ah[2][4];
#pragma unroll
            for (int im = 0; im < 2; im++) {
                uint32_t ra = smb + USM_A + (wm + im * 16 + (lane & 15)) * ROWB + (lane >> 4) * 16 + kb;
                ldsm_x4(ah[im][0], ah[im][1], ah[im][2], ah[im][3], ra);
            }
            uint32_t bh[2][4];
#pragma unroll
            for (int i2 = 0; i2 < 2; i2++) {
                uint32_t rb = smb + USM_B + (wn + i2 * 16 + (lane & 15)) * ROWB + (lane >> 4) * 16 + kb;
                ldsm_x4(bh[i2][0], bh[i2][1], bh[i2][2], bh[i2][3], rb);
            }
#pragma unroll
            for (int im = 0; im < 2; im++)
#pragma unroll
                for (int in = 0; in < 4; in++) {
                    int i2 = in >> 1, sub = in & 1;
                    mma_f16(acc[im][in], ah[im], bh[i2][sub], bh[i2][sub + 2]);
                }
        }
        __syncthreads();
    }

#pragma unroll
    for (int im = 0; im < 2; im++) {
#pragma unroll
        for (int in = 0; in < 4; in++) {
            int d = d0 + wn + in * 8 + (lane & 3) * 2;
#pragma unroll
            for (int half = 0; half < 2; half++) {
                int r = r0 + wm + im * 16 + (lane >> 2) + half * 8;
                int nn = r >> 11, pp = r & 2047;
                *(float2*)&out[((size_t)pp * NB + nn) * DIM + d] =
                    make_float2(acc[im][in][half * 2], acc[im][in][half * 2 + 1]);
            }
        }
    }
}

// ===================== Flash attention on HMMA =============================
// Query tile 64/CTA (warp tile m16), occupancy 4; fp16x2 softmax exps.
#define QP2 72
#define KP 72
#define VP 36

__global__ __launch_bounds__(128, 4)
void attn_mma() {
    const int p0 = blockIdx.x * 64;
    const int h  = blockIdx.y;
    const int n  = blockIdx.z;

    const uint32_t* __restrict__ qh = g_qh + ((size_t)n * 64 + h * 16) * SK;
    const uint32_t* __restrict__ kp = g_kk + ((size_t)n * 64 + h * 16) * SK;
    const uint32_t* __restrict__ vp = g_vv + ((size_t)n * 128 + h * 32) * (SK / 2);

    __shared__ uint32_t qsh[16 * QP2];
    __shared__ uint32_t ksh[16 * KP];
    __shared__ uint32_t vsh[32 * VP];

    const int tid  = threadIdx.x;
    const int lane = tid & 31;
    const int w    = tid >> 5;

    // ---- stage Q (pure copy): 16 cpairs x 64 queries ----
#pragma unroll
    for (int t2 = 0; t2 < 2; t2++) {
        int idx = tid + t2 * 128;
        int cp = idx >> 4, q4 = (idx & 15) * 4;
        *(uint4*)&qsh[cp * QP2 + q4] = *(const uint4*)&qh[(size_t)cp * SK + p0 + q4];
    }
    __syncthreads();

    uint32_t qf[2][4];
#pragma unroll
    for (int ks = 0; ks < 2; ks++) {
        int row = w * 16 + (lane >> 2);
        int cp = (lane & 3) + ks * 8;
        qf[ks][0] = qsh[cp * QP2 + row];
        qf[ks][1] = qsh[cp * QP2 + row + 8];
        qf[ks][2] = qsh[(cp + 4) * QP2 + row];
        qf[ks][3] = qsh[(cp + 4) * QP2 + row + 8];
    }

    float oacc[4][4];
#pragma unroll
    for (int nt = 0; nt < 4; nt++)
#pragma unroll
        for (int t = 0; t < 4; t++) oacc[nt][t] = 0.f;
    float rowm[2] = {-1e30f, -1e30f};
    float rowl[2] = {0.f, 0.f};

    const float SC2 = 0.17677669529663687f * 1.4426950408889634f;

    for (int k0 = 0; k0 < SK; k0 += 64) {
        // ---- stage K/V (pure copies) ----
#pragma unroll
        for (int t2 = 0; t2 < 2; t2++) {
            int idx = tid + t2 * 128;
            int cp = idx >> 4, k4 = (idx & 15) * 4;
            *(uint4*)&ksh[cp * KP + k4] = *(const uint4*)&kp[(size_t)cp * SK + k0 + k4];
            int c = idx >> 3, p4 = (idx & 7) * 4;
            *(uint4*)&vsh[c * VP + p4] = *(const uint4*)&vp[(size_t)c * (SK / 2) + (k0 >> 1) + p4];
        }
        __syncthreads();

        // ---- S = Q K^T (warp: 16q x 64k) ----
        float sacc[8][4];
#pragma unroll
        for (int in = 0; in < 8; in++)
#pragma unroll
            for (int t = 0; t < 4; t++) sacc[in][t] = 0.f;

#pragma unroll
        for (int ks = 0; ks < 2; ks++) {
            uint32_t bh[8][2];
#pragma unroll
            for (int in = 0; in < 8; in++) {
                int cp = (lane & 3) + ks * 8;
                int ky = in * 8 + (lane >> 2);
                bh[in][0] = ksh[cp * KP + ky];
                bh[in][1] = ksh[(cp + 4) * KP + ky];
            }
#pragma unroll
            for (int in = 0; in < 8; in++)
                mma_f16(sacc[in], qf[ks], bh[in][0], bh[in][1]);
        }

        // ---- online softmax: corr in fp32 MUFU, P exps in fp16x2 MUFU ----
#pragma unroll
        for (int rs = 0; rs < 2; rs++) {
            float mx = rowm[rs];
#pragma unroll
            for (int in = 0; in < 8; in++)
                mx = fmaxf(mx, fmaxf(sacc[in][rs * 2], sacc[in][rs * 2 + 1]));
            mx = fmaxf(mx, __shfl_xor_sync(0xffffffffu, mx, 1));
            mx = fmaxf(mx, __shfl_xor_sync(0xffffffffu, mx, 2));
            float corr = ex2f((rowm[rs] - mx) * SC2);
            rowm[rs] = mx;
            float sum = 0.f;
#pragma unroll
            for (int in = 0; in < 8; in++) {
                float a0 = (sacc[in][rs * 2] - mx) * SC2;
                float a1 = (sacc[in][rs * 2 + 1] - mx) * SC2;
                uint32_t ph = ex2h2(a0, a1);
                float2 fv = __half22float2(*reinterpret_cast<__half2*>(&ph));
                sum += fv.x + fv.y;
                sacc[in][rs] = __uint_as_float(ph);
            }
            rowl[rs] = rowl[rs] * corr + sum;
#pragma unroll
            for (int nt = 0; nt < 4; nt++) {
                oacc[nt][rs * 2] *= corr;
                oacc[nt][rs * 2 + 1] *= corr;
            }
        }

        // ---- O += P V^T (P fragments read from packed sacc slots) ----
#pragma unroll
        for (int ks4 = 0; ks4 < 4; ks4++) {
            uint32_t pf[4];
            pf[0] = __float_as_uint(sacc[2 * ks4][0]);
            pf[1] = __float_as_uint(sacc[2 * ks4][1]);
            pf[2] = __float_as_uint(sacc[2 * ks4 + 1][0]);
            pf[3] = __float_as_uint(sacc[2 * ks4 + 1][1]);
            uint32_t bh[4][2];
#pragma unroll
            for (int nt = 0; nt < 4; nt++) {
                int c  = nt * 8 + (lane >> 2);
                int kq = (lane & 3) + ks4 * 8;
                bh[nt][0] = vsh[c * VP + kq];
                bh[nt][1] = vsh[c * VP + kq + 4];
            }
#pragma unroll
            for (int nt = 0; nt < 4; nt++)
                mma_f16(oacc[nt], pf, bh[nt][0], bh[nt][1]);
        }
        __syncthreads();
    }

    // ---- finalize: 1/l, pack fp16, store ----
#pragma unroll
    for (int rs = 0; rs < 2; rs++) {
        float l = rowl[rs];
        l += __shfl_xor_sync(0xffffffffu, l, 1);
        l += __shfl_xor_sync(0xffffffffu, l, 2);
        float inv = 1.f / l;
#pragma unroll
        for (int nt = 0; nt < 4; nt++) {
            oacc[nt][rs * 2] *= inv;
            oacc[nt][rs * 2 + 1] *= inv;
        }
    }
    uint32_t* __restrict__ xout = g_x16 + (size_t)n * SQ * 64 + h * 16;
#pragma unroll
    for (int nt = 0; nt < 4; nt++) {
        int row = p0 + w * 16 + (lane >> 2);
        int wc = nt * 4 + (lane & 3);
        xout[(size_t)row * 64 + wc]       = pack1(oacc[nt][0], oacc[nt][1]);
        xout[(size_t)(row + 8) * 64 + wc] = pack1(oacc[nt][2], oacc[nt][3]);
    }
}

// ---------------------------------------------------------------------------
extern "C" void kernel_launch(void* const* d_in, const int* in_sizes, int n_in,
                              void* d_out, int out_size) {
    const float* query    = (const float*)d_in[0];
    const float* key_feat = (const float*)d_in[1];
    const float* Wq       = (const float*)d_in[2];
    const float* Wk       = (const float*)d_in[3];
    const float* Wv       = (const float*)d_in[4];
    const float* Wup      = (const float*)d_in[5];
    float* out            = (float*)d_out;

    cvt_wup<<<64, 256>>>(Wup);

    dim3 g1(SK / 128, NB, 3);
    proj_all<<<g1, 512>>>(query, key_feat, Wq, Wk, Wv);

    dim3 g2(SQ / 64, NH, NB);
    attn_mma<<<g2, 128>>>();

    dim3 g3(DIM / 128, (NB * SQ) / 128);
    up_mma<<<g3, 512>>>(out);
}